// round 1
// baseline (speedup 1.0000x reference)
#include <cuda_runtime.h>
#include <math.h>

// Problem constants
#define B_  4
#define T_  2048
#define C_  1024
#define H_  16
#define D_  64
#define M_  (B_*T_)   // 8192

// Scratch (allocation-free rule: __device__ globals)
__device__ float g_Q[M_ * C_];
__device__ float g_K[M_ * C_];
__device__ float g_V[M_ * C_];
__device__ float g_O[M_ * C_];

// ---------------------------------------------------------------------------
// Generic C[m,n] = sum_k A[m,k] * W[n,k]   (y = x @ W^T, torch Linear conv.)
// Block tile 64x64, BK=16, 256 threads, 4x4 per-thread microtile.
// ---------------------------------------------------------------------------
__global__ __launch_bounds__(256) void gemm_nt(const float* __restrict__ A,
                                               const float* __restrict__ W,
                                               float* __restrict__ Cc,
                                               int M, int N, int K)
{
    __shared__ float As[16][68];  // [k][m]
    __shared__ float Ws[16][68];  // [k][n]

    const int tid = threadIdx.x;
    const int tx = tid & 15;
    const int ty = tid >> 4;
    const int m0 = blockIdx.y * 64;
    const int n0 = blockIdx.x * 64;

    float acc[4][4];
#pragma unroll
    for (int i = 0; i < 4; i++)
#pragma unroll
        for (int j = 0; j < 4; j++) acc[i][j] = 0.f;

    const int lr = tid >> 2;        // 0..63 row within tile
    const int lk = (tid & 3) * 4;   // 0,4,8,12 col-of-4 within BK
    const float* Ap = A + (size_t)(m0 + lr) * K + lk;
    const float* Wp = W + (size_t)(n0 + lr) * K + lk;

    for (int k0 = 0; k0 < K; k0 += 16) {
        float4 av = *(const float4*)(Ap + k0);
        float4 wv = *(const float4*)(Wp + k0);
        As[lk + 0][lr] = av.x; As[lk + 1][lr] = av.y;
        As[lk + 2][lr] = av.z; As[lk + 3][lr] = av.w;
        Ws[lk + 0][lr] = wv.x; Ws[lk + 1][lr] = wv.y;
        Ws[lk + 2][lr] = wv.z; Ws[lk + 3][lr] = wv.w;
        __syncthreads();

#pragma unroll
        for (int kk = 0; kk < 16; kk++) {
            float a[4], b[4];
#pragma unroll
            for (int i = 0; i < 4; i++) a[i] = As[kk][ty * 4 + i];
#pragma unroll
            for (int j = 0; j < 4; j++) b[j] = Ws[kk][tx * 4 + j];
#pragma unroll
            for (int i = 0; i < 4; i++)
#pragma unroll
                for (int j = 0; j < 4; j++)
                    acc[i][j] += a[i] * b[j];
        }
        __syncthreads();
    }

#pragma unroll
    for (int i = 0; i < 4; i++) {
        int m = m0 + ty * 4 + i;
#pragma unroll
        for (int j = 0; j < 4; j++)
            Cc[(size_t)m * N + n0 + tx * 4 + j] = acc[i][j];
    }
}

// ---------------------------------------------------------------------------
// Flash attention (fp32). One CTA = one (b,h) x 64-row q-tile.
// K/V tiles of 32 rows. Online softmax with shared-memory row reductions.
// Q,K,V,O layout: [b, t, h*64 + d]  (row stride C_ = 1024).
// ---------------------------------------------------------------------------
__global__ __launch_bounds__(256) void attn_kernel(const float* __restrict__ Q,
                                                   const float* __restrict__ K,
                                                   const float* __restrict__ V,
                                                   const int*   __restrict__ mask,
                                                   float* __restrict__ O)
{
    __shared__ float Qs[64][68];
    __shared__ float Ks[32][68];
    __shared__ float Vs[32][68];
    __shared__ float Ps[64][36];
    __shared__ float red[64][16];
    __shared__ float m_s[64], l_s[64], a_s[64];

    const int tid = threadIdx.x;
    const int tx = tid & 15;
    const int ty = tid >> 4;
    const int bh = blockIdx.y;          // b*H + h
    const int b  = bh >> 4;
    const int h  = bh & 15;
    const int q0 = blockIdx.x * 64;

    const float scale = 0.125f;         // 1/sqrt(64)

    // Load Q tile (64 rows x 64 d), 4 float4 per thread
    {
        const int lr = tid >> 2;
        const int lc = (tid & 3) * 16;
        const float4* src = (const float4*)(Q + (size_t)(b * T_ + q0 + lr) * C_ + h * D_ + lc);
        float4 v0 = src[0], v1 = src[1], v2 = src[2], v3 = src[3];
        *(float4*)&Qs[lr][lc + 0]  = v0;
        *(float4*)&Qs[lr][lc + 4]  = v1;
        *(float4*)&Qs[lr][lc + 8]  = v2;
        *(float4*)&Qs[lr][lc + 12] = v3;
    }
    if (tid < 64) { m_s[tid] = -1e30f; l_s[tid] = 0.f; }

    float o[4][4];
#pragma unroll
    for (int i = 0; i < 4; i++)
#pragma unroll
        for (int j = 0; j < 4; j++) o[i][j] = 0.f;

    const size_t mbase = (size_t)b * T_ * T_;

    for (int kt = 0; kt < T_ / 32; kt++) {
        const int kt0 = kt * 32;
        __syncthreads();   // protects Ks/Vs/Ps reuse + init/l_s visibility

        // Load K,V tiles (32 x 64), 2 float4 each per thread
#pragma unroll
        for (int q = 0; q < 2; q++) {
            int fl  = tid * 2 + q;      // 0..511
            int row = fl >> 4;          // 0..31
            int c4  = (fl & 15) * 4;
            size_t gofs = (size_t)(b * T_ + kt0 + row) * C_ + h * D_ + c4;
            *(float4*)&Ks[row][c4] = *(const float4*)(K + gofs);
            *(float4*)&Vs[row][c4] = *(const float4*)(V + gofs);
        }
        __syncthreads();

        // S = Q K^T (per-thread 4 rows x 2 cols)
        float s[4][2];
#pragma unroll
        for (int i = 0; i < 4; i++) { s[i][0] = 0.f; s[i][1] = 0.f; }
#pragma unroll 8
        for (int d = 0; d < 64; d++) {
            float a0 = Qs[ty * 4 + 0][d];
            float a1 = Qs[ty * 4 + 1][d];
            float a2 = Qs[ty * 4 + 2][d];
            float a3 = Qs[ty * 4 + 3][d];
            float b0 = Ks[tx * 2 + 0][d];
            float b1 = Ks[tx * 2 + 1][d];
            s[0][0] += a0 * b0; s[0][1] += a0 * b1;
            s[1][0] += a1 * b0; s[1][1] += a1 * b1;
            s[2][0] += a2 * b0; s[2][1] += a2 * b1;
            s[3][0] += a3 * b0; s[3][1] += a3 * b1;
        }

        // scale + mask, per-thread row max
#pragma unroll
        for (int i = 0; i < 4; i++) {
            int qg = q0 + ty * 4 + i;
            float lm = -1e30f;
#pragma unroll
            for (int j = 0; j < 2; j++) {
                float sv = s[i][j] * scale;
                int mv = __ldg(&mask[mbase + (size_t)qg * T_ + kt0 + tx * 2 + j]);
                if (mv == 0) sv = -1e9f;
                s[i][j] = sv;
                lm = fmaxf(lm, sv);
            }
            red[ty * 4 + i][tx] = lm;
        }
        __syncthreads();

        if (tid < 64) {
            float rm = red[tid][0];
#pragma unroll
            for (int t = 1; t < 16; t++) rm = fmaxf(rm, red[tid][t]);
            float m_new = fmaxf(m_s[tid], rm);
            float alpha = __expf(m_s[tid] - m_new);
            a_s[tid] = alpha;
            m_s[tid] = m_new;
            l_s[tid] *= alpha;
        }
        __syncthreads();

        // P = exp(S - m), stash to shared, per-thread row sums
#pragma unroll
        for (int i = 0; i < 4; i++) {
            int r = ty * 4 + i;
            float mrow = m_s[r];
            float ls = 0.f;
#pragma unroll
            for (int j = 0; j < 2; j++) {
                float p = __expf(s[i][j] - mrow);
                Ps[r][tx * 2 + j] = p;
                ls += p;
            }
            red[r][tx] = ls;
        }
        __syncthreads();

        if (tid < 64) {
            float rs = 0.f;
#pragma unroll
            for (int t = 0; t < 16; t++) rs += red[tid][t];
            l_s[tid] += rs;
        }

        // Rescale accumulators and O += P V  (per-thread 4 rows x 4 d-cols)
        float alpha[4];
#pragma unroll
        for (int i = 0; i < 4; i++) alpha[i] = a_s[ty * 4 + i];
#pragma unroll
        for (int i = 0; i < 4; i++)
#pragma unroll
            for (int j = 0; j < 4; j++) o[i][j] *= alpha[i];

#pragma unroll 8
        for (int k = 0; k < 32; k++) {
            float p0 = Ps[ty * 4 + 0][k];
            float p1 = Ps[ty * 4 + 1][k];
            float p2 = Ps[ty * 4 + 2][k];
            float p3 = Ps[ty * 4 + 3][k];
            float v0 = Vs[k][tx * 4 + 0];
            float v1 = Vs[k][tx * 4 + 1];
            float v2 = Vs[k][tx * 4 + 2];
            float v3 = Vs[k][tx * 4 + 3];
            o[0][0] += p0 * v0; o[0][1] += p0 * v1; o[0][2] += p0 * v2; o[0][3] += p0 * v3;
            o[1][0] += p1 * v0; o[1][1] += p1 * v1; o[1][2] += p1 * v2; o[1][3] += p1 * v3;
            o[2][0] += p2 * v0; o[2][1] += p2 * v1; o[2][2] += p2 * v2; o[2][3] += p2 * v3;
            o[3][0] += p3 * v0; o[3][1] += p3 * v1; o[3][2] += p3 * v2; o[3][3] += p3 * v3;
        }
    }

    __syncthreads();   // l_s final values visible

    float inv_l[4];
#pragma unroll
    for (int i = 0; i < 4; i++) inv_l[i] = 1.f / l_s[ty * 4 + i];

#pragma unroll
    for (int i = 0; i < 4; i++) {
        int qg = q0 + ty * 4 + i;
        float* dst = O + (size_t)(b * T_ + qg) * C_ + h * D_ + tx * 4;
#pragma unroll
        for (int j = 0; j < 4; j++) dst[j] = o[i][j] * inv_l[i];
    }
}

// ---------------------------------------------------------------------------
extern "C" void kernel_launch(void* const* d_in, const int* in_sizes, int n_in,
                              void* d_out, int out_size)
{
    const float* x    = (const float*)d_in[0];
    const int*   mask = (const int*)  d_in[1];
    const float* Wq   = (const float*)d_in[2];
    const float* Wk   = (const float*)d_in[3];
    const float* Wv   = (const float*)d_in[4];
    const float* Wo   = (const float*)d_in[5];
    float* out = (float*)d_out;

    float *Qp, *Kp, *Vp, *Op;
    cudaGetSymbolAddress((void**)&Qp, g_Q);
    cudaGetSymbolAddress((void**)&Kp, g_K);
    cudaGetSymbolAddress((void**)&Vp, g_V);
    cudaGetSymbolAddress((void**)&Op, g_O);

    dim3 gb(C_ / 64, M_ / 64);   // (16, 128)
    gemm_nt<<<gb, 256>>>(x, Wq, Qp, M_, C_, C_);
    gemm_nt<<<gb, 256>>>(x, Wk, Kp, M_, C_, C_);
    gemm_nt<<<gb, 256>>>(x, Wv, Vp, M_, C_, C_);

    dim3 ga(T_ / 64, B_ * H_);   // (32, 64)
    attn_kernel<<<ga, 256>>>(Qp, Kp, Vp, mask, Op);

    gemm_nt<<<gb, 256>>>(Op, Wo, out, M_, C_, C_);
}

// round 3
// speedup vs baseline: 2.5694x; 2.5694x over previous
#include <cuda_runtime.h>
#include <cuda_bf16.h>
#include <cuda_fp16.h>
#include <mma.h>
#include <cstdint>
#include <math.h>

using namespace nvcuda;

// Problem constants
#define B_  4
#define T_  2048
#define C_  1024
#define H_  16
#define D_  64
#define M_  (B_*T_)   // 8192

// Scratch (allocation-free rule: __device__ globals)
__device__ __half g_Qh[M_ * C_];
__device__ __half g_Kh[M_ * C_];
__device__ __half g_Vh[M_ * C_];
__device__ float  g_O [M_ * C_];

// ===========================================================================
// GEMM: C[m,n] = sum_k A[m,k] * W[n,k]  (y = x @ W^T), bf16 3-pass split MMA.
// CTA tile 128x128, BK=32, 256 threads (8 warps: 4 m x 2 n, warp = 32x64).
// ===========================================================================
#define GBM 128
#define GBN 128
#define GBK 32
#define LDA 40                       // padded halves per smem row
#define GT  (128*LDA)                // halves per tile buffer

template<bool HALF_OUT>
__global__ __launch_bounds__(256, 1) void gemm_mma(const float* __restrict__ A,
                                                   const float* __restrict__ W,
                                                   void* __restrict__ Cout,
                                                   int M, int N, int K)
{
    extern __shared__ char smem_raw[];
    __nv_bfloat16* sm = (__nv_bfloat16*)smem_raw;
    // stage s: [Ahi | Alo | Bhi | Blo], each 128 x LDA halves
    const int tid = threadIdx.x;
    const int wid = tid >> 5;
    const int wm  = wid >> 1;         // 0..3
    const int wn  = wid & 1;          // 0..1
    const int m0  = blockIdx.y * GBM;
    const int n0  = blockIdx.x * GBN;

    wmma::fragment<wmma::accumulator, 16, 16, 16, float> acc[2][4];
#pragma unroll
    for (int i = 0; i < 2; i++)
#pragma unroll
        for (int j = 0; j < 4; j++) wmma::fill_fragment(acc[i][j], 0.f);

    // loader mapping: per matrix, 1024 float4 per chunk; 4 per thread
    const int lr0[4] = { (0*256+tid) >> 3, (1*256+tid) >> 3, (2*256+tid) >> 3, (3*256+tid) >> 3 };
    const int lg    = tid & 7;        // float4 group within 32-col row

    float4 ra[4], rb[4];

    auto g_load = [&](int k0) {
#pragma unroll
        for (int i = 0; i < 4; i++) {
            ra[i] = *(const float4*)(A + (size_t)(m0 + lr0[i]) * K + k0 + lg * 4);
            rb[i] = *(const float4*)(W + (size_t)(n0 + lr0[i]) * K + k0 + lg * 4);
        }
    };
    auto s_store = [&](int s) {
        __nv_bfloat16* Ahi = sm + (size_t)s * 4 * GT;
        __nv_bfloat16* Alo = Ahi + GT;
        __nv_bfloat16* Bhi = Alo + GT;
        __nv_bfloat16* Blo = Bhi + GT;
#pragma unroll
        for (int i = 0; i < 4; i++) {
            int idx = lr0[i] * LDA + lg * 4;
            float4 v = ra[i];
            __nv_bfloat16 hx = __float2bfloat16(v.x), hy = __float2bfloat16(v.y);
            __nv_bfloat16 hz = __float2bfloat16(v.z), hw = __float2bfloat16(v.w);
            ((__nv_bfloat162*)(Ahi + idx))[0] = __nv_bfloat162(hx, hy);
            ((__nv_bfloat162*)(Ahi + idx))[1] = __nv_bfloat162(hz, hw);
            ((__nv_bfloat162*)(Alo + idx))[0] = __nv_bfloat162(
                __float2bfloat16(v.x - __bfloat162float(hx)),
                __float2bfloat16(v.y - __bfloat162float(hy)));
            ((__nv_bfloat162*)(Alo + idx))[1] = __nv_bfloat162(
                __float2bfloat16(v.z - __bfloat162float(hz)),
                __float2bfloat16(v.w - __bfloat162float(hw)));
            v = rb[i];
            hx = __float2bfloat16(v.x); hy = __float2bfloat16(v.y);
            hz = __float2bfloat16(v.z); hw = __float2bfloat16(v.w);
            ((__nv_bfloat162*)(Bhi + idx))[0] = __nv_bfloat162(hx, hy);
            ((__nv_bfloat162*)(Bhi + idx))[1] = __nv_bfloat162(hz, hw);
            ((__nv_bfloat162*)(Blo + idx))[0] = __nv_bfloat162(
                __float2bfloat16(v.x - __bfloat162float(hx)),
                __float2bfloat16(v.y - __bfloat162float(hy)));
            ((__nv_bfloat162*)(Blo + idx))[1] = __nv_bfloat162(
                __float2bfloat16(v.z - __bfloat162float(hz)),
                __float2bfloat16(v.w - __bfloat162float(hw)));
        }
    };

    g_load(0);
    s_store(0);
    __syncthreads();

    const int NC = K / GBK;
    for (int c = 0; c < NC; c++) {
        int s = c & 1;
        if (c + 1 < NC) g_load((c + 1) * GBK);

        const __nv_bfloat16* Ahi = sm + (size_t)s * 4 * GT;
        const __nv_bfloat16* Alo = Ahi + GT;
        const __nv_bfloat16* Bhi = Alo + GT;
        const __nv_bfloat16* Blo = Bhi + GT;
#pragma unroll
        for (int kk = 0; kk < 2; kk++) {
            wmma::fragment<wmma::matrix_a, 16, 16, 16, __nv_bfloat16, wmma::row_major> ah[2], al[2];
#pragma unroll
            for (int mi = 0; mi < 2; mi++) {
                int r = wm * 32 + mi * 16;
                wmma::load_matrix_sync(ah[mi], Ahi + r * LDA + kk * 16, LDA);
                wmma::load_matrix_sync(al[mi], Alo + r * LDA + kk * 16, LDA);
            }
#pragma unroll
            for (int nj = 0; nj < 4; nj++) {
                int n = wn * 64 + nj * 16;
                wmma::fragment<wmma::matrix_b, 16, 16, 16, __nv_bfloat16, wmma::col_major> bh, bl;
                wmma::load_matrix_sync(bh, Bhi + n * LDA + kk * 16, LDA);
                wmma::load_matrix_sync(bl, Blo + n * LDA + kk * 16, LDA);
#pragma unroll
                for (int mi = 0; mi < 2; mi++) {
                    wmma::mma_sync(acc[mi][nj], ah[mi], bh, acc[mi][nj]);
                    wmma::mma_sync(acc[mi][nj], ah[mi], bl, acc[mi][nj]);
                    wmma::mma_sync(acc[mi][nj], al[mi], bh, acc[mi][nj]);
                }
            }
        }
        __syncthreads();
        if (c + 1 < NC) s_store(s ^ 1);
        __syncthreads();
    }

    if (!HALF_OUT) {
        float* Cf = (float*)Cout;
#pragma unroll
        for (int mi = 0; mi < 2; mi++)
#pragma unroll
            for (int nj = 0; nj < 4; nj++)
                wmma::store_matrix_sync(Cf + (size_t)(m0 + wm * 32 + mi * 16) * N
                                           + n0 + wn * 64 + nj * 16,
                                        acc[mi][nj], N, wmma::mem_row_major);
    } else {
        float* Cs = (float*)smem_raw;          // 128 x 132 staging
#pragma unroll
        for (int mi = 0; mi < 2; mi++)
#pragma unroll
            for (int nj = 0; nj < 4; nj++)
                wmma::store_matrix_sync(Cs + (wm * 32 + mi * 16) * 132 + wn * 64 + nj * 16,
                                        acc[mi][nj], 132, wmma::mem_row_major);
        __syncthreads();
        __half* Ch = (__half*)Cout;
        for (int idx = tid; idx < 128 * 64; idx += 256) {
            int r = idx >> 6;
            int c2 = (idx & 63) * 2;
            __half2 hv = __floats2half2_rn(Cs[r * 132 + c2], Cs[r * 132 + c2 + 1]);
            *(__half2*)(Ch + (size_t)(m0 + r) * N + n0 + c2) = hv;
        }
    }
}
#define GEMM_SMEM (2 * 4 * GT * 2)   // 81920 bytes

// ===========================================================================
// Flash attention, fp16 wmma, unnormalized softmax (exact up to fp rounding).
// CTA = (b,h) x 64 q-rows, 4 warps (warp = 16-row strip), kv tiles of 64.
// ===========================================================================
#define AQ_LD 72     // half ldm
#define AS_LD 68     // float ldm
// smem byte offsets
#define OFF_QS 0
#define OFF_KS (OFF_QS + 64*AQ_LD*2)
#define OFF_VS (OFF_KS + 64*AQ_LD*2)
#define OFF_PS (OFF_VS + 64*AQ_LD*2)
#define OFF_SS (OFF_PS + 64*AQ_LD*2)
#define OFF_LS (OFF_SS + 64*AS_LD*4)
#define ATT_SMEM (OFF_LS + 64*4)

__global__ __launch_bounds__(128, 1) void attn_mma(const __half* __restrict__ Q,
                                                   const __half* __restrict__ K,
                                                   const __half* __restrict__ V,
                                                   const int*    __restrict__ mask,
                                                   float* __restrict__ O)
{
    extern __shared__ char smem_raw[];
    __half* Qs = (__half*)(smem_raw + OFF_QS);
    __half* Ks = (__half*)(smem_raw + OFF_KS);
    __half* Vs = (__half*)(smem_raw + OFF_VS);
    __half* Ps = (__half*)(smem_raw + OFF_PS);
    float*  Ss = (float*) (smem_raw + OFF_SS);
    float*  ls = (float*) (smem_raw + OFF_LS);

    const int tid  = threadIdx.x;
    const int w    = tid >> 5;
    const int lane = tid & 31;
    const int bh   = blockIdx.y;
    const int b    = bh >> 4;
    const int h    = bh & 15;
    const int q0   = blockIdx.x * 64;

    // Load Q tile (64 x 64 halves)
#pragma unroll
    for (int i = 0; i < 4; i++) {
        int f = i * 128 + tid;
        int r = f >> 3, g = f & 7;
        *(uint4*)(Qs + r * AQ_LD + g * 8) =
            *(const uint4*)(Q + (size_t)(b * T_ + q0 + r) * C_ + h * D_ + g * 8);
    }

    wmma::fragment<wmma::accumulator, 16, 16, 16, float> oacc[4];
#pragma unroll
    for (int j = 0; j < 4; j++) wmma::fill_fragment(oacc[j], 0.f);
    float lpart = 0.f;

    const int lrow  = lane >> 1;           // strip-local row 0..15
    const int chalf = (lane & 1) * 32;     // col half 0 / 32
    const int srow  = w * 16 + lrow;

    for (int kt = 0; kt < T_ / 64; kt++) {
        const int kt0 = kt * 64;
        __syncthreads();   // everyone done with previous Ks/Vs
#pragma unroll
        for (int i = 0; i < 4; i++) {
            int f = i * 128 + tid;
            int r = f >> 3, g = f & 7;
            size_t go = (size_t)(b * T_ + kt0 + r) * C_ + h * D_ + g * 8;
            *(uint4*)(Ks + r * AQ_LD + g * 8) = *(const uint4*)(K + go);
            *(uint4*)(Vs + r * AQ_LD + g * 8) = *(const uint4*)(V + go);
        }
        __syncthreads();

        // S strip (16 x 64) = Q_strip (16x64) . K^T
        wmma::fragment<wmma::accumulator, 16, 16, 16, float> sacc[4];
#pragma unroll
        for (int j = 0; j < 4; j++) wmma::fill_fragment(sacc[j], 0.f);
#pragma unroll
        for (int kd = 0; kd < 4; kd++) {
            wmma::fragment<wmma::matrix_a, 16, 16, 16, __half, wmma::row_major> af;
            wmma::load_matrix_sync(af, Qs + (w * 16) * AQ_LD + kd * 16, AQ_LD);
#pragma unroll
            for (int nj = 0; nj < 4; nj++) {
                wmma::fragment<wmma::matrix_b, 16, 16, 16, __half, wmma::col_major> bf;
                wmma::load_matrix_sync(bf, Ks + (nj * 16) * AQ_LD + kd * 16, AQ_LD);
                wmma::mma_sync(sacc[nj], af, bf, sacc[nj]);
            }
        }
#pragma unroll
        for (int nj = 0; nj < 4; nj++)
            wmma::store_matrix_sync(Ss + (w * 16) * AS_LD + nj * 16, sacc[nj],
                                    AS_LD, wmma::mem_row_major);
        __syncwarp();

        // exp(scale*S with mask), accumulate row-sum, write P (fp16)
        {
            const int4* mp = (const int4*)(mask + ((size_t)b * T_ + q0 + srow) * T_ + kt0 + chalf);
            const float* Srow = Ss + srow * AS_LD + chalf;
            __half2*    Prow = (__half2*)(Ps + srow * AQ_LD + chalf);
#pragma unroll
            for (int jj = 0; jj < 8; jj++) {
                int4 mv = __ldg(mp + jj);
                float s0 = Srow[jj * 4 + 0] * 0.125f; if (mv.x == 0) s0 = -1e9f;
                float s1 = Srow[jj * 4 + 1] * 0.125f; if (mv.y == 0) s1 = -1e9f;
                float s2 = Srow[jj * 4 + 2] * 0.125f; if (mv.z == 0) s2 = -1e9f;
                float s3 = Srow[jj * 4 + 3] * 0.125f; if (mv.w == 0) s3 = -1e9f;
                float e0 = __expf(s0), e1 = __expf(s1), e2 = __expf(s2), e3 = __expf(s3);
                lpart += (e0 + e1) + (e2 + e3);
                Prow[jj * 2 + 0] = __floats2half2_rn(e0, e1);
                Prow[jj * 2 + 1] = __floats2half2_rn(e2, e3);
            }
        }
        __syncwarp();

        // O_strip += P_strip (16x64) . V (64x64)
#pragma unroll
        for (int kd = 0; kd < 4; kd++) {
            wmma::fragment<wmma::matrix_a, 16, 16, 16, __half, wmma::row_major> af;
            wmma::load_matrix_sync(af, Ps + (w * 16) * AQ_LD + kd * 16, AQ_LD);
#pragma unroll
            for (int nj = 0; nj < 4; nj++) {
                wmma::fragment<wmma::matrix_b, 16, 16, 16, __half, wmma::row_major> bf;
                wmma::load_matrix_sync(bf, Vs + (kd * 16) * AQ_LD + nj * 16, AQ_LD);
                wmma::mma_sync(oacc[nj], af, bf, oacc[nj]);
            }
        }
    }

    // row sums (2 lanes per row)
    float lsum = lpart + __shfl_xor_sync(0xFFFFFFFFu, lpart, 1);
    if ((lane & 1) == 0) ls[srow] = lsum;

    // stage O strip to smem (reuse Ss) and write normalized fp32 output
#pragma unroll
    for (int nj = 0; nj < 4; nj++)
        wmma::store_matrix_sync(Ss + (w * 16) * AS_LD + nj * 16, oacc[nj],
                                AS_LD, wmma::mem_row_major);
    __syncwarp();
#pragma unroll
    for (int r = 0; r < 16; r++) {
        int row = w * 16 + r;
        float inv = 1.f / ls[row];
        float* dst = O + (size_t)(b * T_ + q0 + row) * C_ + h * D_;
        dst[lane]      = Ss[row * AS_LD + lane]      * inv;
        dst[lane + 32] = Ss[row * AS_LD + lane + 32] * inv;
    }
}

// ===========================================================================
extern "C" void kernel_launch(void* const* d_in, const int* in_sizes, int n_in,
                              void* d_out, int out_size)
{
    const float* x    = (const float*)d_in[0];
    const int*   mask = (const int*)  d_in[1];
    const float* Wq   = (const float*)d_in[2];
    const float* Wk   = (const float*)d_in[3];
    const float* Wv   = (const float*)d_in[4];
    const float* Wo   = (const float*)d_in[5];
    float* out = (float*)d_out;

    __half *Qh, *Kh, *Vh; float *Op;
    cudaGetSymbolAddress((void**)&Qh, g_Qh);
    cudaGetSymbolAddress((void**)&Kh, g_Kh);
    cudaGetSymbolAddress((void**)&Vh, g_Vh);
    cudaGetSymbolAddress((void**)&Op, g_O);

    cudaFuncSetAttribute(gemm_mma<true>,  cudaFuncAttributeMaxDynamicSharedMemorySize, GEMM_SMEM);
    cudaFuncSetAttribute(gemm_mma<false>, cudaFuncAttributeMaxDynamicSharedMemorySize, GEMM_SMEM);
    cudaFuncSetAttribute(attn_mma,        cudaFuncAttributeMaxDynamicSharedMemorySize, ATT_SMEM);

    dim3 gg(C_ / GBN, M_ / GBM);   // (8, 64)
    gemm_mma<true><<<gg, 256, GEMM_SMEM>>>(x, Wq, Qh, M_, C_, C_);
    gemm_mma<true><<<gg, 256, GEMM_SMEM>>>(x, Wk, Kh, M_, C_, C_);
    gemm_mma<true><<<gg, 256, GEMM_SMEM>>>(x, Wv, Vh, M_, C_, C_);

    dim3 ga(T_ / 64, B_ * H_);     // (32, 64)
    attn_mma<<<ga, 128, ATT_SMEM>>>(Qh, Kh, Vh, mask, Op);

    gemm_mma<false><<<gg, 256, GEMM_SMEM>>>(Op, Wo, out, M_, C_, C_);
}

// round 4
// speedup vs baseline: 3.5652x; 1.3876x over previous
#include <cuda_runtime.h>
#include <cuda_bf16.h>
#include <cuda_fp16.h>
#include <mma.h>
#include <cstdint>
#include <math.h>

using namespace nvcuda;

// Problem constants
#define B_  4
#define T_  2048
#define C_  1024
#define H_  16
#define D_  64
#define M_  (B_*T_)   // 8192

// Scratch (allocation-free rule: __device__ globals)
__device__ __half g_Qh[M_ * C_];
__device__ __half g_Kh[M_ * C_];
__device__ __half g_Vh[M_ * C_];
__device__ float  g_O [M_ * C_];
__device__ int    g_mflag[B_ * 16 * 32];   // per (b, 128-q-block, 64-k-block): 1 = all mask!=0

// ===========================================================================
// GEMM: C[m,n] = sum_k A[m,k] * W[n,k]  (y = x @ W^T), bf16 3-pass split MMA.
// CTA tile 128x128, BK=32, 256 threads (8 warps: 4 m x 2 n, warp = 32x64).
// blockIdx.z selects (W, Cout) so QKV runs as one launch.
// ===========================================================================
#define GBM 128
#define GBN 128
#define GBK 32
#define LDA 40                       // padded halves per smem row
#define GT  (128*LDA)                // halves per tile buffer

template<bool HALF_OUT>
__global__ __launch_bounds__(256, 1) void gemm_mma(const float* __restrict__ A,
                                                   const float* __restrict__ W0,
                                                   const float* __restrict__ W1,
                                                   const float* __restrict__ W2,
                                                   void* __restrict__ C0,
                                                   void* __restrict__ C1,
                                                   void* __restrict__ C2,
                                                   int M, int N, int K)
{
    const float* W   = blockIdx.z == 0 ? W0 : (blockIdx.z == 1 ? W1 : W2);
    void*        Cout = blockIdx.z == 0 ? C0 : (blockIdx.z == 1 ? C1 : C2);

    extern __shared__ char smem_raw[];
    __nv_bfloat16* sm = (__nv_bfloat16*)smem_raw;
    const int tid = threadIdx.x;
    const int wid = tid >> 5;
    const int wm  = wid >> 1;         // 0..3
    const int wn  = wid & 1;          // 0..1
    const int m0  = blockIdx.y * GBM;
    const int n0  = blockIdx.x * GBN;

    wmma::fragment<wmma::accumulator, 16, 16, 16, float> acc[2][4];
#pragma unroll
    for (int i = 0; i < 2; i++)
#pragma unroll
        for (int j = 0; j < 4; j++) wmma::fill_fragment(acc[i][j], 0.f);

    const int lr0[4] = { (0*256+tid) >> 3, (1*256+tid) >> 3, (2*256+tid) >> 3, (3*256+tid) >> 3 };
    const int lg    = tid & 7;

    float4 ra[4], rb[4];

    auto g_load = [&](int k0) {
#pragma unroll
        for (int i = 0; i < 4; i++) {
            ra[i] = *(const float4*)(A + (size_t)(m0 + lr0[i]) * K + k0 + lg * 4);
            rb[i] = *(const float4*)(W + (size_t)(n0 + lr0[i]) * K + k0 + lg * 4);
        }
    };
    auto s_store = [&](int s) {
        __nv_bfloat16* Ahi = sm + (size_t)s * 4 * GT;
        __nv_bfloat16* Alo = Ahi + GT;
        __nv_bfloat16* Bhi = Alo + GT;
        __nv_bfloat16* Blo = Bhi + GT;
#pragma unroll
        for (int i = 0; i < 4; i++) {
            int idx = lr0[i] * LDA + lg * 4;
            float4 v = ra[i];
            __nv_bfloat16 hx = __float2bfloat16(v.x), hy = __float2bfloat16(v.y);
            __nv_bfloat16 hz = __float2bfloat16(v.z), hw = __float2bfloat16(v.w);
            ((__nv_bfloat162*)(Ahi + idx))[0] = __nv_bfloat162(hx, hy);
            ((__nv_bfloat162*)(Ahi + idx))[1] = __nv_bfloat162(hz, hw);
            ((__nv_bfloat162*)(Alo + idx))[0] = __nv_bfloat162(
                __float2bfloat16(v.x - __bfloat162float(hx)),
                __float2bfloat16(v.y - __bfloat162float(hy)));
            ((__nv_bfloat162*)(Alo + idx))[1] = __nv_bfloat162(
                __float2bfloat16(v.z - __bfloat162float(hz)),
                __float2bfloat16(v.w - __bfloat162float(hw)));
            v = rb[i];
            hx = __float2bfloat16(v.x); hy = __float2bfloat16(v.y);
            hz = __float2bfloat16(v.z); hw = __float2bfloat16(v.w);
            ((__nv_bfloat162*)(Bhi + idx))[0] = __nv_bfloat162(hx, hy);
            ((__nv_bfloat162*)(Bhi + idx))[1] = __nv_bfloat162(hz, hw);
            ((__nv_bfloat162*)(Blo + idx))[0] = __nv_bfloat162(
                __float2bfloat16(v.x - __bfloat162float(hx)),
                __float2bfloat16(v.y - __bfloat162float(hy)));
            ((__nv_bfloat162*)(Blo + idx))[1] = __nv_bfloat162(
                __float2bfloat16(v.z - __bfloat162float(hz)),
                __float2bfloat16(v.w - __bfloat162float(hw)));
        }
    };

    g_load(0);
    s_store(0);
    __syncthreads();

    const int NC = K / GBK;
    for (int c = 0; c < NC; c++) {
        int s = c & 1;
        if (c + 1 < NC) g_load((c + 1) * GBK);

        const __nv_bfloat16* Ahi = sm + (size_t)s * 4 * GT;
        const __nv_bfloat16* Alo = Ahi + GT;
        const __nv_bfloat16* Bhi = Alo + GT;
        const __nv_bfloat16* Blo = Bhi + GT;
#pragma unroll
        for (int kk = 0; kk < 2; kk++) {
            wmma::fragment<wmma::matrix_a, 16, 16, 16, __nv_bfloat16, wmma::row_major> ah[2], al[2];
#pragma unroll
            for (int mi = 0; mi < 2; mi++) {
                int r = wm * 32 + mi * 16;
                wmma::load_matrix_sync(ah[mi], Ahi + r * LDA + kk * 16, LDA);
                wmma::load_matrix_sync(al[mi], Alo + r * LDA + kk * 16, LDA);
            }
#pragma unroll
            for (int nj = 0; nj < 4; nj++) {
                int n = wn * 64 + nj * 16;
                wmma::fragment<wmma::matrix_b, 16, 16, 16, __nv_bfloat16, wmma::col_major> bh, bl;
                wmma::load_matrix_sync(bh, Bhi + n * LDA + kk * 16, LDA);
                wmma::load_matrix_sync(bl, Blo + n * LDA + kk * 16, LDA);
#pragma unroll
                for (int mi = 0; mi < 2; mi++) {
                    wmma::mma_sync(acc[mi][nj], ah[mi], bh, acc[mi][nj]);
                    wmma::mma_sync(acc[mi][nj], ah[mi], bl, acc[mi][nj]);
                    wmma::mma_sync(acc[mi][nj], al[mi], bh, acc[mi][nj]);
                }
            }
        }
        __syncthreads();
        if (c + 1 < NC) s_store(s ^ 1);
        __syncthreads();
    }

    if (!HALF_OUT) {
        float* Cf = (float*)Cout;
#pragma unroll
        for (int mi = 0; mi < 2; mi++)
#pragma unroll
            for (int nj = 0; nj < 4; nj++)
                wmma::store_matrix_sync(Cf + (size_t)(m0 + wm * 32 + mi * 16) * N
                                           + n0 + wn * 64 + nj * 16,
                                        acc[mi][nj], N, wmma::mem_row_major);
    } else {
        float* Cs = (float*)smem_raw;
#pragma unroll
        for (int mi = 0; mi < 2; mi++)
#pragma unroll
            for (int nj = 0; nj < 4; nj++)
                wmma::store_matrix_sync(Cs + (wm * 32 + mi * 16) * 132 + wn * 64 + nj * 16,
                                        acc[mi][nj], 132, wmma::mem_row_major);
        __syncthreads();
        __half* Ch = (__half*)Cout;
        for (int idx = tid; idx < 128 * 64; idx += 256) {
            int r = idx >> 6;
            int c2 = (idx & 63) * 2;
            __half2 hv = __floats2half2_rn(Cs[r * 132 + c2], Cs[r * 132 + c2 + 1]);
            *(__half2*)(Ch + (size_t)(m0 + r) * N + n0 + c2) = hv;
        }
    }
}
#define GEMM_SMEM (2 * 4 * GT * 2)   // 81920 bytes

// ===========================================================================
// Mask pre-scan: flag[b][qb][kb] = 1 iff mask[b, qb*128:+128, kb*64:+64] all != 0
// ===========================================================================
__global__ __launch_bounds__(256) void mask_flags(const int* __restrict__ mask)
{
    __shared__ int s_zero;
    const int t = threadIdx.x;
    if (t == 0) s_zero = 0;
    __syncthreads();
    const int fid = blockIdx.x;
    const int b  = fid >> 9;
    const int qb = (fid >> 5) & 15;
    const int kb = fid & 31;
    const int* base = mask + ((size_t)b * T_ + qb * 128) * T_ + kb * 64;
    const int r = t >> 1, hh = t & 1;
    const int4* p = (const int4*)(base + (size_t)r * T_ + hh * 32);
    bool ok = true;
#pragma unroll
    for (int i = 0; i < 8; i++) {
        int4 v = p[i];
        ok = ok && (v.x != 0) && (v.y != 0) && (v.z != 0) && (v.w != 0);
    }
    if (!ok) s_zero = 1;
    __syncthreads();
    if (t == 0) g_mflag[fid] = s_zero ? 0 : 1;
}

// ===========================================================================
// Register-resident flash attention (raw mma.sync m16n8k16, fp16).
// CTA = (b,h) x 128 q-rows, 8 warps (16 rows each). KV tiles of 64,
// cp.async double-buffered. Unnormalized softmax (exact: masked -> e=0).
// ===========================================================================
#define AT_LD   72                    // halves per smem row
#define AT_ROWB (AT_LD*2)             // 144 bytes
#define OFF_Q   0
#define Q_BYTES (128*AT_ROWB)         // 18432
#define OFF_KV  Q_BYTES
#define KV_STG  (64*AT_ROWB*2)        // K+V one stage = 18432
#define ATT2_SMEM (OFF_KV + 2*KV_STG) // 55296

__device__ __forceinline__ uint32_t smem_u32a(const void* p){
    uint32_t a;
    asm("{ .reg .u64 t; cvta.to.shared.u64 t, %1; cvt.u32.u64 %0, t; }" : "=r"(a) : "l"(p));
    return a;
}
__device__ __forceinline__ void mma16816(float* d, const uint32_t* a, const uint32_t* b){
    asm volatile("mma.sync.aligned.m16n8k16.row.col.f32.f16.f16.f32 "
        "{%0,%1,%2,%3}, {%4,%5,%6,%7}, {%8,%9}, {%0,%1,%2,%3};"
        : "+f"(d[0]), "+f"(d[1]), "+f"(d[2]), "+f"(d[3])
        : "r"(a[0]), "r"(a[1]), "r"(a[2]), "r"(a[3]), "r"(b[0]), "r"(b[1]));
}
__device__ __forceinline__ void ldsm4(uint32_t* r, uint32_t addr){
    asm volatile("ldmatrix.sync.aligned.m8n8.x4.shared.b16 {%0,%1,%2,%3}, [%4];"
        : "=r"(r[0]), "=r"(r[1]), "=r"(r[2]), "=r"(r[3]) : "r"(addr));
}
__device__ __forceinline__ void ldsm4t(uint32_t* r, uint32_t addr){
    asm volatile("ldmatrix.sync.aligned.m8n8.x4.trans.shared.b16 {%0,%1,%2,%3}, [%4];"
        : "=r"(r[0]), "=r"(r[1]), "=r"(r[2]), "=r"(r[3]) : "r"(addr));
}
__device__ __forceinline__ uint32_t packe(float a, float b){
    __half2 h = __floats2half2_rn(a, b);
    return *(uint32_t*)&h;
}
#define CP16(dst, src) asm volatile("cp.async.ca.shared.global [%0], [%1], 16;" :: "r"(dst), "l"(src))
#define CP_COMMIT()    asm volatile("cp.async.commit_group;")
#define CP_WAIT1()     asm volatile("cp.async.wait_group 1;")
#define CP_WAIT0()     asm volatile("cp.async.wait_group 0;")

__global__ __launch_bounds__(256, 1) void attn_reg(const __half* __restrict__ Q,
                                                   const __half* __restrict__ K,
                                                   const __half* __restrict__ V,
                                                   const int*    __restrict__ mask,
                                                   float* __restrict__ O)
{
    extern __shared__ char smem_raw[];
    const uint32_t sb = smem_u32a(smem_raw);

    const int tid  = threadIdx.x;
    const int w    = tid >> 5;
    const int lane = tid & 31;
    const int b    = blockIdx.y >> 4;
    const int h    = blockIdx.y & 15;
    const int q0   = blockIdx.x * 128;

    // --- cp.async prefetch of KV tile kt into stage s ---
    auto prefetch = [&](int kt, int s){
        uint32_t kbase = sb + OFF_KV + s * KV_STG;
        uint32_t vbase = kbase + 64 * AT_ROWB;
        const __half* Kg = K + (size_t)(b * T_ + kt * 64) * C_ + h * D_;
        const __half* Vg = V + (size_t)(b * T_ + kt * 64) * C_ + h * D_;
#pragma unroll
        for (int i = 0; i < 2; i++) {
            int cid = i * 256 + tid;      // 0..511
            int r = cid >> 3, c = cid & 7;
            CP16(kbase + r * AT_ROWB + c * 16, Kg + (size_t)r * C_ + c * 8);
            CP16(vbase + r * AT_ROWB + c * 16, Vg + (size_t)r * C_ + c * 8);
        }
    };

    prefetch(0, 0); CP_COMMIT();
    prefetch(1, 1); CP_COMMIT();

    // --- stage Q, build persistent A-fragments ---
#pragma unroll
    for (int i = 0; i < 4; i++) {
        int cid = i * 256 + tid;          // 0..1023
        int r = cid >> 3, c = cid & 7;
        *(uint4*)(smem_raw + OFF_Q + r * AT_ROWB + c * 16) =
            *(const uint4*)(Q + (size_t)(b * T_ + q0 + r) * C_ + h * D_ + c * 8);
    }
    __syncthreads();
    uint32_t qf[4][4];
#pragma unroll
    for (int kd = 0; kd < 4; kd++) {
        uint32_t aq = sb + OFF_Q + (w * 16 + (lane & 15)) * AT_ROWB
                    + (kd * 16 + (lane >> 4) * 8) * 2;
        ldsm4(qf[kd], aq);
    }

    float oacc[8][4];
#pragma unroll
    for (int i = 0; i < 8; i++)
#pragma unroll
        for (int j = 0; j < 4; j++) oacc[i][j] = 0.f;
    float lsum0 = 0.f, lsum1 = 0.f;

    const int NT = T_ / 64;  // 32
    for (int kt = 0; kt < NT; kt++) {
        const int s = kt & 1;
        if (kt + 1 < NT) { CP_WAIT1(); } else { CP_WAIT0(); }
        __syncthreads();

        const uint32_t kS = sb + OFF_KV + s * KV_STG;
        const uint32_t vS = kS + 64 * AT_ROWB;
        const int flag = g_mflag[(b * 16 + blockIdx.x) * 32 + kt];

        uint32_t pf[4][4];
        // ---- S = Q K^T, softmax, pack P fragments (all registers) ----
#pragma unroll
        for (int j = 0; j < 8; j++) {
            float sj[4] = {0.f, 0.f, 0.f, 0.f};
            uint32_t kb0[4], kb1[4];
            uint32_t a0 = kS + (j * 8 + (lane & 7)) * AT_ROWB + (lane >> 3) * 16;
            ldsm4(kb0, a0);          // kd0: b0,b1 ; kd1: b0,b1
            ldsm4(kb1, a0 + 64);     // kd2, kd3
            mma16816(sj, qf[0], kb0 + 0);
            mma16816(sj, qf[1], kb0 + 2);
            mma16816(sj, qf[2], kb1 + 0);
            mma16816(sj, qf[3], kb1 + 2);

            float e0 = __expf(sj[0] * 0.125f);
            float e1 = __expf(sj[1] * 0.125f);
            float e2 = __expf(sj[2] * 0.125f);
            float e3 = __expf(sj[3] * 0.125f);
            if (!flag) {
                const int* mp = mask + ((size_t)b * T_ + q0 + w * 16 + (lane >> 2)) * T_
                              + kt * 64 + j * 8 + 2 * (lane & 3);
                int2 m0 = *(const int2*)mp;
                int2 m1 = *(const int2*)(mp + 8 * T_);
                if (m0.x == 0) e0 = 0.f;
                if (m0.y == 0) e1 = 0.f;
                if (m1.x == 0) e2 = 0.f;
                if (m1.y == 0) e3 = 0.f;
            }
            lsum0 += e0 + e1;
            lsum1 += e2 + e3;
            pf[j >> 1][(j & 1) * 2 + 0] = packe(e0, e1);
            pf[j >> 1][(j & 1) * 2 + 1] = packe(e2, e3);
        }

        // ---- O += P V ----
#pragma unroll
        for (int kk = 0; kk < 4; kk++) {
#pragma unroll
            for (int np = 0; np < 4; np++) {
                uint32_t vb[4];
                uint32_t ad = vS + (kk * 16 + ((lane >> 3) & 1) * 8 + (lane & 7)) * AT_ROWB
                            + (np * 16 + (lane >> 4) * 8) * 2;
                ldsm4t(vb, ad);
                mma16816(oacc[np * 2 + 0], pf[kk], vb + 0);
                mma16816(oacc[np * 2 + 1], pf[kk], vb + 2);
            }
        }

        __syncthreads();
        if (kt + 2 < NT) { prefetch(kt + 2, s); CP_COMMIT(); }
    }

    // ---- normalize and write ----
    lsum0 += __shfl_xor_sync(0xFFFFFFFFu, lsum0, 1);
    lsum0 += __shfl_xor_sync(0xFFFFFFFFu, lsum0, 2);
    lsum1 += __shfl_xor_sync(0xFFFFFFFFu, lsum1, 1);
    lsum1 += __shfl_xor_sync(0xFFFFFFFFu, lsum1, 2);
    const float inv0 = 1.f / lsum0;
    const float inv1 = 1.f / lsum1;

    float* d0 = O + (size_t)(b * T_ + q0 + w * 16 + (lane >> 2)) * C_ + h * D_ + 2 * (lane & 3);
    float* d1 = d0 + 8 * C_;
#pragma unroll
    for (int nd = 0; nd < 8; nd++) {
        *(float2*)(d0 + nd * 8) = make_float2(oacc[nd][0] * inv0, oacc[nd][1] * inv0);
        *(float2*)(d1 + nd * 8) = make_float2(oacc[nd][2] * inv1, oacc[nd][3] * inv1);
    }
}

// ===========================================================================
extern "C" void kernel_launch(void* const* d_in, const int* in_sizes, int n_in,
                              void* d_out, int out_size)
{
    const float* x    = (const float*)d_in[0];
    const int*   mask = (const int*)  d_in[1];
    const float* Wq   = (const float*)d_in[2];
    const float* Wk   = (const float*)d_in[3];
    const float* Wv   = (const float*)d_in[4];
    const float* Wo   = (const float*)d_in[5];
    float* out = (float*)d_out;

    __half *Qh, *Kh, *Vh; float *Op;
    cudaGetSymbolAddress((void**)&Qh, g_Qh);
    cudaGetSymbolAddress((void**)&Kh, g_Kh);
    cudaGetSymbolAddress((void**)&Vh, g_Vh);
    cudaGetSymbolAddress((void**)&Op, g_O);

    cudaFuncSetAttribute(gemm_mma<true>,  cudaFuncAttributeMaxDynamicSharedMemorySize, GEMM_SMEM);
    cudaFuncSetAttribute(gemm_mma<false>, cudaFuncAttributeMaxDynamicSharedMemorySize, GEMM_SMEM);
    cudaFuncSetAttribute(attn_reg,        cudaFuncAttributeMaxDynamicSharedMemorySize, ATT2_SMEM);

    mask_flags<<<B_ * 16 * 32, 256>>>(mask);

    dim3 gg(C_ / GBN, M_ / GBM, 3);   // (8, 64, 3) — fused QKV
    gemm_mma<true><<<gg, 256, GEMM_SMEM>>>(x, Wq, Wk, Wv, Qh, Kh, Vh, M_, C_, C_);

    dim3 ga(T_ / 128, B_ * H_);       // (16, 64)
    attn_reg<<<ga, 256, ATT2_SMEM>>>(Qh, Kh, Vh, mask, Op);

    dim3 go(C_ / GBN, M_ / GBM, 1);
    gemm_mma<false><<<go, 256, GEMM_SMEM>>>(Op, Wo, Wo, Wo, out, out, out, M_, C_, C_);
}

// round 5
// speedup vs baseline: 5.1894x; 1.4556x over previous
#include <cuda_runtime.h>
#include <cuda_bf16.h>
#include <cuda_fp16.h>
#include <cstdint>
#include <math.h>

// Problem constants
#define B_  4
#define T_  2048
#define C_  1024
#define H_  16
#define D_  64
#define M_  (B_*T_)   // 8192

// Scratch (allocation-free rule: __device__ globals)
__device__ __half         g_Qh[M_ * C_];
__device__ __half         g_Kh[M_ * C_];
__device__ __half         g_Vh[M_ * C_];
__device__ __nv_bfloat16  g_xhi[M_ * C_];
__device__ __nv_bfloat16  g_xlo[M_ * C_];
__device__ __nv_bfloat16  g_whi[4 * C_ * C_];
__device__ __nv_bfloat16  g_wlo[4 * C_ * C_];
__device__ __nv_bfloat16  g_Ohi[M_ * C_];
__device__ __nv_bfloat16  g_Olo[M_ * C_];
__device__ int            g_mflag[B_ * 16 * 32];

// ---------------------------------------------------------------------------
// Common PTX helpers
// ---------------------------------------------------------------------------
__device__ __forceinline__ uint32_t smem_u32a(const void* p){
    uint32_t a;
    asm("{ .reg .u64 t; cvta.to.shared.u64 t, %1; cvt.u32.u64 %0, t; }" : "=r"(a) : "l"(p));
    return a;
}
__device__ __forceinline__ void mma16816(float* d, const uint32_t* a, const uint32_t* b){
    asm volatile("mma.sync.aligned.m16n8k16.row.col.f32.f16.f16.f32 "
        "{%0,%1,%2,%3}, {%4,%5,%6,%7}, {%8,%9}, {%0,%1,%2,%3};"
        : "+f"(d[0]), "+f"(d[1]), "+f"(d[2]), "+f"(d[3])
        : "r"(a[0]), "r"(a[1]), "r"(a[2]), "r"(a[3]), "r"(b[0]), "r"(b[1]));
}
__device__ __forceinline__ void mma16816bf(float* d, const uint32_t* a, const uint32_t* b){
    asm volatile("mma.sync.aligned.m16n8k16.row.col.f32.bf16.bf16.f32 "
        "{%0,%1,%2,%3}, {%4,%5,%6,%7}, {%8,%9}, {%0,%1,%2,%3};"
        : "+f"(d[0]), "+f"(d[1]), "+f"(d[2]), "+f"(d[3])
        : "r"(a[0]), "r"(a[1]), "r"(a[2]), "r"(a[3]), "r"(b[0]), "r"(b[1]));
}
__device__ __forceinline__ void ldsm4(uint32_t* r, uint32_t addr){
    asm volatile("ldmatrix.sync.aligned.m8n8.x4.shared.b16 {%0,%1,%2,%3}, [%4];"
        : "=r"(r[0]), "=r"(r[1]), "=r"(r[2]), "=r"(r[3]) : "r"(addr));
}
__device__ __forceinline__ void ldsm4t(uint32_t* r, uint32_t addr){
    asm volatile("ldmatrix.sync.aligned.m8n8.x4.trans.shared.b16 {%0,%1,%2,%3}, [%4];"
        : "=r"(r[0]), "=r"(r[1]), "=r"(r[2]), "=r"(r[3]) : "r"(addr));
}
__device__ __forceinline__ uint32_t packe(float a, float b){
    __half2 h = __floats2half2_rn(a, b);
    return *(uint32_t*)&h;
}
#define CP16(dst, src) asm volatile("cp.async.cg.shared.global [%0], [%1], 16;" :: "r"(dst), "l"(src))
#define CP_COMMIT()    asm volatile("cp.async.commit_group;")
#define CP_WAIT1()     asm volatile("cp.async.wait_group 1;")
#define CP_WAIT0()     asm volatile("cp.async.wait_group 0;")

// ---------------------------------------------------------------------------
// Split fp32 -> bf16 hi/lo
// ---------------------------------------------------------------------------
__global__ __launch_bounds__(256) void split_bf16(const float* __restrict__ src,
                                                  __nv_bfloat16* __restrict__ hi,
                                                  __nv_bfloat16* __restrict__ lo,
                                                  int n)
{
    int i = (blockIdx.x * 256 + threadIdx.x) * 4;
    if (i >= n) return;
    float4 v = *(const float4*)(src + i);
    __nv_bfloat16 hx = __float2bfloat16(v.x), hy = __float2bfloat16(v.y);
    __nv_bfloat16 hz = __float2bfloat16(v.z), hw = __float2bfloat16(v.w);
    ((__nv_bfloat162*)(hi + i))[0] = __nv_bfloat162(hx, hy);
    ((__nv_bfloat162*)(hi + i))[1] = __nv_bfloat162(hz, hw);
    ((__nv_bfloat162*)(lo + i))[0] = __nv_bfloat162(
        __float2bfloat16(v.x - __bfloat162float(hx)),
        __float2bfloat16(v.y - __bfloat162float(hy)));
    ((__nv_bfloat162*)(lo + i))[1] = __nv_bfloat162(
        __float2bfloat16(v.z - __bfloat162float(hz)),
        __float2bfloat16(v.w - __bfloat162float(hw)));
}

// ---------------------------------------------------------------------------
// Mask pre-scan: flag[b][qb][kb] = 1 iff mask[b, qb*128:+128, kb*64:+64] all != 0
// ---------------------------------------------------------------------------
__global__ __launch_bounds__(256) void mask_flags(const int* __restrict__ mask)
{
    __shared__ int s_zero;
    const int t = threadIdx.x;
    if (t == 0) s_zero = 0;
    __syncthreads();
    const int fid = blockIdx.x;
    const int b  = fid >> 9;
    const int qb = (fid >> 5) & 15;
    const int kb = fid & 31;
    const int* base = mask + ((size_t)b * T_ + qb * 128) * T_ + kb * 64;
    const int r = t >> 1, hh = t & 1;
    const int4* p = (const int4*)(base + (size_t)r * T_ + hh * 32);
    bool ok = true;
#pragma unroll
    for (int i = 0; i < 8; i++) {
        int4 v = p[i];
        ok = ok && (v.x != 0) && (v.y != 0) && (v.z != 0) && (v.w != 0);
    }
    if (!ok) s_zero = 1;
    __syncthreads();
    if (t == 0) g_mflag[fid] = s_zero ? 0 : 1;
}

// ===========================================================================
// GEMM v2: C[m,n] = sum_k A[m,k]*W[n,k], pre-split bf16 hi/lo inputs, bf16x3.
// CTA 128x128, BK=64, cp.async double-buffered, XOR-swizzled smem, raw mma.
// 8 warps: wm in {0,1} (64 m-rows), wn in {0..3} (32 n-cols).
// blockIdx.z selects weight slice + output (fused QKV).
// ===========================================================================
#define TILE_B  16384                 // 128 rows x 128 bytes
#define STAGE_B (4*TILE_B)            // Ahi|Alo|Bhi|Blo
#define G2_SMEM (2*STAGE_B)           // 131072

template<bool HALF_OUT>
__global__ __launch_bounds__(256, 1) void gemm_bf16x3(
    const __nv_bfloat16* __restrict__ Ahi_g,
    const __nv_bfloat16* __restrict__ Alo_g,
    const __nv_bfloat16* __restrict__ Bhi_g,
    const __nv_bfloat16* __restrict__ Blo_g,
    void* __restrict__ C0, void* __restrict__ C1, void* __restrict__ C2,
    int M, int N, int K)
{
    extern __shared__ char smem_raw[];
    const uint32_t sb = smem_u32a(smem_raw);

    const int z = blockIdx.z;
    const __nv_bfloat16* Bh = Bhi_g + (size_t)z * N * K;
    const __nv_bfloat16* Bl = Blo_g + (size_t)z * N * K;
    void* Cout = z == 0 ? C0 : (z == 1 ? C1 : C2);

    const int tid  = threadIdx.x;
    const int w    = tid >> 5;
    const int lane = tid & 31;
    const int wm   = w >> 2;          // 0..1
    const int wn   = w & 3;           // 0..3
    const int m0   = blockIdx.y * 128;
    const int n0   = blockIdx.x * 128;

    auto prefetch = [&](int t, int s){
        uint32_t st = sb + s * STAGE_B;
        int k0 = t * 64;
#pragma unroll
        for (int i = 0; i < 4; i++) {
            int id = i * 256 + tid;          // 0..1023
            int r = id >> 3, c = id & 7;
            uint32_t dsw = (uint32_t)(r * 128 + ((c ^ (r & 7)) << 4));
            size_t ga = (size_t)(m0 + r) * K + k0 + c * 8;
            size_t gb = (size_t)(n0 + r) * K + k0 + c * 8;
            CP16(st + dsw,              Ahi_g + ga);
            CP16(st + TILE_B + dsw,     Alo_g + ga);
            CP16(st + 2 * TILE_B + dsw, Bh + gb);
            CP16(st + 3 * TILE_B + dsw, Bl + gb);
        }
    };

    prefetch(0, 0); CP_COMMIT();
    prefetch(1, 1); CP_COMMIT();

    float acc[4][4][4];
#pragma unroll
    for (int mi = 0; mi < 4; mi++)
#pragma unroll
        for (int nb = 0; nb < 4; nb++)
#pragma unroll
            for (int j = 0; j < 4; j++) acc[mi][nb][j] = 0.f;

    const int NT = K / 64;            // 16
    for (int t = 0; t < NT; t++) {
        const int s = t & 1;
        if (t + 1 < NT) { CP_WAIT1(); } else { CP_WAIT0(); }
        __syncthreads();

        const uint32_t aH = sb + s * STAGE_B;
        const uint32_t aL = aH + TILE_B;
        const uint32_t bH = aL + TILE_B;
        const uint32_t bL = bH + TILE_B;

#pragma unroll
        for (int kp = 0; kp < 2; kp++) {
            uint32_t bhf[4][4], blf[4][4];
#pragma unroll
            for (int nb = 0; nb < 4; nb++) {
                int r = wn * 32 + nb * 8 + (lane & 7);
                int c = kp * 4 + (lane >> 3);
                uint32_t off = (uint32_t)(r * 128 + ((c ^ (r & 7)) << 4));
                ldsm4(bhf[nb], bH + off);
                ldsm4(blf[nb], bL + off);
            }
#pragma unroll
            for (int k2 = 0; k2 < 2; k2++) {
                const int kk = kp * 2 + k2;
                uint32_t ahf[4][4], alf[4][4];
#pragma unroll
                for (int mi = 0; mi < 4; mi++) {
                    int r = wm * 64 + mi * 16 + (lane & 15);
                    int c = kk * 2 + (lane >> 4);
                    uint32_t off = (uint32_t)(r * 128 + ((c ^ (r & 7)) << 4));
                    ldsm4(ahf[mi], aH + off);
                    ldsm4(alf[mi], aL + off);
                }
#pragma unroll
                for (int mi = 0; mi < 4; mi++)
#pragma unroll
                    for (int nb = 0; nb < 4; nb++) {
                        mma16816bf(acc[mi][nb], ahf[mi], bhf[nb] + k2 * 2);
                        mma16816bf(acc[mi][nb], ahf[mi], blf[nb] + k2 * 2);
                        mma16816bf(acc[mi][nb], alf[mi], bhf[nb] + k2 * 2);
                    }
            }
        }
        __syncthreads();
        if (t + 2 < NT) { prefetch(t + 2, s); CP_COMMIT(); }
    }

    // Epilogue: direct register -> global
#pragma unroll
    for (int mi = 0; mi < 4; mi++) {
        int r0 = m0 + wm * 64 + mi * 16 + (lane >> 2);
#pragma unroll
        for (int nb = 0; nb < 4; nb++) {
            int col = n0 + wn * 32 + nb * 8 + (lane & 3) * 2;
            if (HALF_OUT) {
                __half* Ch = (__half*)Cout;
                *(__half2*)(Ch + (size_t)r0 * N + col) =
                    __floats2half2_rn(acc[mi][nb][0], acc[mi][nb][1]);
                *(__half2*)(Ch + (size_t)(r0 + 8) * N + col) =
                    __floats2half2_rn(acc[mi][nb][2], acc[mi][nb][3]);
            } else {
                float* Cf = (float*)Cout;
                *(float2*)(Cf + (size_t)r0 * N + col) =
                    make_float2(acc[mi][nb][0], acc[mi][nb][1]);
                *(float2*)(Cf + (size_t)(r0 + 8) * N + col) =
                    make_float2(acc[mi][nb][2], acc[mi][nb][3]);
            }
        }
    }
}

// ===========================================================================
// Register-resident flash attention (raw mma, fp16), epilogue emits bf16 hi/lo.
// ===========================================================================
#define AT_LD   72
#define AT_ROWB (AT_LD*2)
#define OFF_Q   0
#define Q_BYTES (128*AT_ROWB)
#define OFF_KV  Q_BYTES
#define KV_STG  (64*AT_ROWB*2)
#define ATT2_SMEM (OFF_KV + 2*KV_STG)

__global__ __launch_bounds__(256, 1) void attn_reg(const __half* __restrict__ Q,
                                                   const __half* __restrict__ K,
                                                   const __half* __restrict__ V,
                                                   const int*    __restrict__ mask,
                                                   __nv_bfloat16* __restrict__ Ohi,
                                                   __nv_bfloat16* __restrict__ Olo)
{
    extern __shared__ char smem_raw[];
    const uint32_t sb = smem_u32a(smem_raw);

    const int tid  = threadIdx.x;
    const int w    = tid >> 5;
    const int lane = tid & 31;
    const int b    = blockIdx.y >> 4;
    const int h    = blockIdx.y & 15;
    const int q0   = blockIdx.x * 128;

    auto prefetch = [&](int kt, int s){
        uint32_t kbase = sb + OFF_KV + s * KV_STG;
        uint32_t vbase = kbase + 64 * AT_ROWB;
        const __half* Kg = K + (size_t)(b * T_ + kt * 64) * C_ + h * D_;
        const __half* Vg = V + (size_t)(b * T_ + kt * 64) * C_ + h * D_;
#pragma unroll
        for (int i = 0; i < 2; i++) {
            int cid = i * 256 + tid;
            int r = cid >> 3, c = cid & 7;
            CP16(kbase + r * AT_ROWB + c * 16, Kg + (size_t)r * C_ + c * 8);
            CP16(vbase + r * AT_ROWB + c * 16, Vg + (size_t)r * C_ + c * 8);
        }
    };

    prefetch(0, 0); CP_COMMIT();
    prefetch(1, 1); CP_COMMIT();

#pragma unroll
    for (int i = 0; i < 4; i++) {
        int cid = i * 256 + tid;
        int r = cid >> 3, c = cid & 7;
        *(uint4*)(smem_raw + OFF_Q + r * AT_ROWB + c * 16) =
            *(const uint4*)(Q + (size_t)(b * T_ + q0 + r) * C_ + h * D_ + c * 8);
    }
    __syncthreads();
    uint32_t qf[4][4];
#pragma unroll
    for (int kd = 0; kd < 4; kd++) {
        uint32_t aq = sb + OFF_Q + (w * 16 + (lane & 15)) * AT_ROWB
                    + (kd * 16 + (lane >> 4) * 8) * 2;
        ldsm4(qf[kd], aq);
    }

    float oacc[8][4];
#pragma unroll
    for (int i = 0; i < 8; i++)
#pragma unroll
        for (int j = 0; j < 4; j++) oacc[i][j] = 0.f;
    float lsum0 = 0.f, lsum1 = 0.f;

    const int NT = T_ / 64;
    for (int kt = 0; kt < NT; kt++) {
        const int s = kt & 1;
        if (kt + 1 < NT) { CP_WAIT1(); } else { CP_WAIT0(); }
        __syncthreads();

        const uint32_t kS = sb + OFF_KV + s * KV_STG;
        const uint32_t vS = kS + 64 * AT_ROWB;
        const int flag = g_mflag[(b * 16 + blockIdx.x) * 32 + kt];

        uint32_t pf[4][4];
#pragma unroll
        for (int j = 0; j < 8; j++) {
            float sj[4] = {0.f, 0.f, 0.f, 0.f};
            uint32_t kb0[4], kb1[4];
            uint32_t a0 = kS + (j * 8 + (lane & 7)) * AT_ROWB + (lane >> 3) * 16;
            ldsm4(kb0, a0);
            ldsm4(kb1, a0 + 64);
            mma16816(sj, qf[0], kb0 + 0);
            mma16816(sj, qf[1], kb0 + 2);
            mma16816(sj, qf[2], kb1 + 0);
            mma16816(sj, qf[3], kb1 + 2);

            float e0 = __expf(sj[0] * 0.125f);
            float e1 = __expf(sj[1] * 0.125f);
            float e2 = __expf(sj[2] * 0.125f);
            float e3 = __expf(sj[3] * 0.125f);
            if (!flag) {
                const int* mp = mask + ((size_t)b * T_ + q0 + w * 16 + (lane >> 2)) * T_
                              + kt * 64 + j * 8 + 2 * (lane & 3);
                int2 m0v = *(const int2*)mp;
                int2 m1v = *(const int2*)(mp + 8 * T_);
                if (m0v.x == 0) e0 = 0.f;
                if (m0v.y == 0) e1 = 0.f;
                if (m1v.x == 0) e2 = 0.f;
                if (m1v.y == 0) e3 = 0.f;
            }
            lsum0 += e0 + e1;
            lsum1 += e2 + e3;
            pf[j >> 1][(j & 1) * 2 + 0] = packe(e0, e1);
            pf[j >> 1][(j & 1) * 2 + 1] = packe(e2, e3);
        }

#pragma unroll
        for (int kk = 0; kk < 4; kk++) {
#pragma unroll
            for (int np = 0; np < 4; np++) {
                uint32_t vb[4];
                uint32_t ad = vS + (kk * 16 + ((lane >> 3) & 1) * 8 + (lane & 7)) * AT_ROWB
                            + (np * 16 + (lane >> 4) * 8) * 2;
                ldsm4t(vb, ad);
                mma16816(oacc[np * 2 + 0], pf[kk], vb + 0);
                mma16816(oacc[np * 2 + 1], pf[kk], vb + 2);
            }
        }

        __syncthreads();
        if (kt + 2 < NT) { prefetch(kt + 2, s); CP_COMMIT(); }
    }

    lsum0 += __shfl_xor_sync(0xFFFFFFFFu, lsum0, 1);
    lsum0 += __shfl_xor_sync(0xFFFFFFFFu, lsum0, 2);
    lsum1 += __shfl_xor_sync(0xFFFFFFFFu, lsum1, 1);
    lsum1 += __shfl_xor_sync(0xFFFFFFFFu, lsum1, 2);
    const float inv0 = 1.f / lsum0;
    const float inv1 = 1.f / lsum1;

    size_t o0 = (size_t)(b * T_ + q0 + w * 16 + (lane >> 2)) * C_ + h * D_ + 2 * (lane & 3);
    size_t o1 = o0 + 8 * C_;
#pragma unroll
    for (int nd = 0; nd < 8; nd++) {
        float v0 = oacc[nd][0] * inv0, v1 = oacc[nd][1] * inv0;
        float v2 = oacc[nd][2] * inv1, v3 = oacc[nd][3] * inv1;
        __nv_bfloat16 h0 = __float2bfloat16(v0), h1 = __float2bfloat16(v1);
        __nv_bfloat16 h2 = __float2bfloat16(v2), h3 = __float2bfloat16(v3);
        *(__nv_bfloat162*)(Ohi + o0 + nd * 8) = __nv_bfloat162(h0, h1);
        *(__nv_bfloat162*)(Ohi + o1 + nd * 8) = __nv_bfloat162(h2, h3);
        *(__nv_bfloat162*)(Olo + o0 + nd * 8) = __nv_bfloat162(
            __float2bfloat16(v0 - __bfloat162float(h0)),
            __float2bfloat16(v1 - __bfloat162float(h1)));
        *(__nv_bfloat162*)(Olo + o1 + nd * 8) = __nv_bfloat162(
            __float2bfloat16(v2 - __bfloat162float(h2)),
            __float2bfloat16(v3 - __bfloat162float(h3)));
    }
}

// ===========================================================================
extern "C" void kernel_launch(void* const* d_in, const int* in_sizes, int n_in,
                              void* d_out, int out_size)
{
    const float* x    = (const float*)d_in[0];
    const int*   mask = (const int*)  d_in[1];
    const float* Wq   = (const float*)d_in[2];
    const float* Wk   = (const float*)d_in[3];
    const float* Wv   = (const float*)d_in[4];
    const float* Wo   = (const float*)d_in[5];
    float* out = (float*)d_out;

    __half *Qh, *Kh, *Vh;
    __nv_bfloat16 *xhi, *xlo, *whi, *wlo, *Ohi, *Olo;
    cudaGetSymbolAddress((void**)&Qh,  g_Qh);
    cudaGetSymbolAddress((void**)&Kh,  g_Kh);
    cudaGetSymbolAddress((void**)&Vh,  g_Vh);
    cudaGetSymbolAddress((void**)&xhi, g_xhi);
    cudaGetSymbolAddress((void**)&xlo, g_xlo);
    cudaGetSymbolAddress((void**)&whi, g_whi);
    cudaGetSymbolAddress((void**)&wlo, g_wlo);
    cudaGetSymbolAddress((void**)&Ohi, g_Ohi);
    cudaGetSymbolAddress((void**)&Olo, g_Olo);

    cudaFuncSetAttribute(gemm_bf16x3<true>,  cudaFuncAttributeMaxDynamicSharedMemorySize, G2_SMEM);
    cudaFuncSetAttribute(gemm_bf16x3<false>, cudaFuncAttributeMaxDynamicSharedMemorySize, G2_SMEM);
    cudaFuncSetAttribute(attn_reg,           cudaFuncAttributeMaxDynamicSharedMemorySize, ATT2_SMEM);

    const int WN = C_ * C_;          // 1048576
    split_bf16<<<M_ * C_ / 1024, 256>>>(x,  xhi, xlo, M_ * C_);
    split_bf16<<<WN / 1024, 256>>>(Wq, whi + 0 * (size_t)WN, wlo + 0 * (size_t)WN, WN);
    split_bf16<<<WN / 1024, 256>>>(Wk, whi + 1 * (size_t)WN, wlo + 1 * (size_t)WN, WN);
    split_bf16<<<WN / 1024, 256>>>(Wv, whi + 2 * (size_t)WN, wlo + 2 * (size_t)WN, WN);
    split_bf16<<<WN / 1024, 256>>>(Wo, whi + 3 * (size_t)WN, wlo + 3 * (size_t)WN, WN);

    mask_flags<<<B_ * 16 * 32, 256>>>(mask);

    dim3 gq(C_ / 128, M_ / 128, 3);   // fused QKV
    gemm_bf16x3<true><<<gq, 256, G2_SMEM>>>(xhi, xlo, whi, wlo,
                                            Qh, Kh, Vh, M_, C_, C_);

    dim3 ga(T_ / 128, B_ * H_);
    attn_reg<<<ga, 256, ATT2_SMEM>>>(Qh, Kh, Vh, mask, Ohi, Olo);

    dim3 go(C_ / 128, M_ / 128, 1);
    gemm_bf16x3<false><<<go, 256, G2_SMEM>>>(Ohi, Olo, whi + 3 * (size_t)WN, wlo + 3 * (size_t)WN,
                                             out, out, out, M_, C_, C_);
}

// round 6
// speedup vs baseline: 7.6153x; 1.4675x over previous
#include <cuda_runtime.h>
#include <cuda_fp16.h>
#include <cstdint>
#include <math.h>

// Problem constants
#define B_  4
#define T_  2048
#define C_  1024
#define H_  16
#define D_  64
#define M_  (B_*T_)   // 8192

// Scratch (allocation-free rule: __device__ globals)
__device__ __half g_Qh [M_ * C_];
__device__ __half g_Kh [M_ * C_];
__device__ __half g_Vh [M_ * C_];
__device__ __half g_xh [M_ * C_];
__device__ __half g_wh [4 * C_ * C_];
__device__ __half g_Ohi[M_ * C_];
__device__ __half g_Olo[M_ * C_];
__device__ int    g_mflag[B_ * 16 * 32];

// ---------------------------------------------------------------------------
// Common PTX helpers
// ---------------------------------------------------------------------------
__device__ __forceinline__ uint32_t smem_u32a(const void* p){
    uint32_t a;
    asm("{ .reg .u64 t; cvta.to.shared.u64 t, %1; cvt.u32.u64 %0, t; }" : "=r"(a) : "l"(p));
    return a;
}
__device__ __forceinline__ void mma16816(float* d, const uint32_t* a, const uint32_t* b){
    asm volatile("mma.sync.aligned.m16n8k16.row.col.f32.f16.f16.f32 "
        "{%0,%1,%2,%3}, {%4,%5,%6,%7}, {%8,%9}, {%0,%1,%2,%3};"
        : "+f"(d[0]), "+f"(d[1]), "+f"(d[2]), "+f"(d[3])
        : "r"(a[0]), "r"(a[1]), "r"(a[2]), "r"(a[3]), "r"(b[0]), "r"(b[1]));
}
__device__ __forceinline__ void ldsm4(uint32_t* r, uint32_t addr){
    asm volatile("ldmatrix.sync.aligned.m8n8.x4.shared.b16 {%0,%1,%2,%3}, [%4];"
        : "=r"(r[0]), "=r"(r[1]), "=r"(r[2]), "=r"(r[3]) : "r"(addr));
}
__device__ __forceinline__ void ldsm4t(uint32_t* r, uint32_t addr){
    asm volatile("ldmatrix.sync.aligned.m8n8.x4.trans.shared.b16 {%0,%1,%2,%3}, [%4];"
        : "=r"(r[0]), "=r"(r[1]), "=r"(r[2]), "=r"(r[3]) : "r"(addr));
}
__device__ __forceinline__ uint32_t packe(float a, float b){
    __half2 h = __floats2half2_rn(a, b);
    return *(uint32_t*)&h;
}
#define CP16(dst, src) asm volatile("cp.async.cg.shared.global [%0], [%1], 16;" :: "r"(dst), "l"(src))
#define CP_COMMIT()    asm volatile("cp.async.commit_group;")
#define CP_WAIT2()     asm volatile("cp.async.wait_group 2;")
#define CP_WAIT1()     asm volatile("cp.async.wait_group 1;")
#define CP_WAIT0()     asm volatile("cp.async.wait_group 0;")

// ---------------------------------------------------------------------------
// fp32 -> fp16 convert
// ---------------------------------------------------------------------------
__global__ __launch_bounds__(256) void tofp16(const float* __restrict__ src,
                                              __half* __restrict__ dst, int n)
{
    int i = (blockIdx.x * 256 + threadIdx.x) * 4;
    if (i >= n) return;
    float4 v = *(const float4*)(src + i);
    ((__half2*)(dst + i))[0] = __floats2half2_rn(v.x, v.y);
    ((__half2*)(dst + i))[1] = __floats2half2_rn(v.z, v.w);
}

// ---------------------------------------------------------------------------
// Mask pre-scan: flag[b][qb][kb] = 1 iff mask[b, qb*128:+128, kb*64:+64] all != 0
// ---------------------------------------------------------------------------
__global__ __launch_bounds__(256) void mask_flags(const int* __restrict__ mask)
{
    __shared__ int s_zero;
    const int t = threadIdx.x;
    if (t == 0) s_zero = 0;
    __syncthreads();
    const int fid = blockIdx.x;
    const int b  = fid >> 9;
    const int qb = (fid >> 5) & 15;
    const int kb = fid & 31;
    const int* base = mask + ((size_t)b * T_ + qb * 128) * T_ + kb * 64;
    const int r = t >> 1, hh = t & 1;
    const int4* p = (const int4*)(base + (size_t)r * T_ + hh * 32);
    bool ok = true;
#pragma unroll
    for (int i = 0; i < 8; i++) {
        int4 v = p[i];
        ok = ok && (v.x != 0) && (v.y != 0) && (v.z != 0) && (v.w != 0);
    }
    if (!ok) s_zero = 1;
    __syncthreads();
    if (t == 0) g_mflag[fid] = s_zero ? 0 : 1;
}

// ===========================================================================
// GEMM v3: C[m,n] = sum_k A[m,k]*W[n,k], fp16 operands, NPASS splits on A.
// CTA 128x128, BK=64, 4-stage cp.async, XOR-swizzled smem, raw mma.
// 8 warps: wm in {0,1} (64 m-rows), wn in {0..3} (32 n-cols).
// blockIdx.z selects weight slice + output (fused QKV).
// ===========================================================================
#define TILE16 16384                  // 128 rows x 128 bytes (64 fp16 cols)
#define NSTG   4

template<int NPASS, bool HALF_OUT>
__global__ __launch_bounds__(256, 1) void gemm_fp16(
    const __half* __restrict__ Ahi_g,
    const __half* __restrict__ Alo_g,
    const __half* __restrict__ Bg,
    void* __restrict__ C0, void* __restrict__ C1, void* __restrict__ C2,
    int M, int N, int K)
{
    constexpr int STAGE_B = (NPASS + 1) * TILE16;
    extern __shared__ char smem_raw[];
    const uint32_t sb = smem_u32a(smem_raw);

    const int z = blockIdx.z;
    const __half* Bz = Bg + (size_t)z * N * K;
    void* Cout = z == 0 ? C0 : (z == 1 ? C1 : C2);

    const int tid  = threadIdx.x;
    const int w    = tid >> 5;
    const int lane = tid & 31;
    const int wm   = w >> 2;          // 0..1
    const int wn   = w & 3;           // 0..3
    const int m0   = blockIdx.y * 128;
    const int n0   = blockIdx.x * 128;

    auto prefetch = [&](int t, int s){
        uint32_t st = sb + s * STAGE_B;
        int k0 = t * 64;
#pragma unroll
        for (int i = 0; i < 4; i++) {
            int id = i * 256 + tid;          // 0..1023
            int r = id >> 3, c = id & 7;
            uint32_t dsw = (uint32_t)(r * 128 + ((c ^ (r & 7)) << 4));
            size_t ga = (size_t)(m0 + r) * K + k0 + c * 8;
            CP16(st + dsw, Ahi_g + ga);
            if (NPASS == 2) CP16(st + TILE16 + dsw, Alo_g + ga);
            CP16(st + NPASS * TILE16 + dsw, Bz + (size_t)(n0 + r) * K + k0 + c * 8);
        }
    };

    prefetch(0, 0); CP_COMMIT();
    prefetch(1, 1); CP_COMMIT();
    prefetch(2, 2); CP_COMMIT();

    float acc[4][4][4];
#pragma unroll
    for (int mi = 0; mi < 4; mi++)
#pragma unroll
        for (int nb = 0; nb < 4; nb++)
#pragma unroll
            for (int j = 0; j < 4; j++) acc[mi][nb][j] = 0.f;

    const int NT = K / 64;            // 16
    for (int t = 0; t < NT; t++) {
        CP_WAIT2();
        __syncthreads();
        if (t + NSTG - 1 < NT) prefetch(t + NSTG - 1, (t + NSTG - 1) & (NSTG - 1));
        CP_COMMIT();                  // empty commit keeps group accounting uniform

        const uint32_t aH = sb + (t & (NSTG - 1)) * STAGE_B;
        const uint32_t aL = aH + TILE16;
        const uint32_t bB = aH + NPASS * TILE16;

#pragma unroll
        for (int kp = 0; kp < 2; kp++) {
            uint32_t bhf[4][4];
#pragma unroll
            for (int nb = 0; nb < 4; nb++) {
                int r = wn * 32 + nb * 8 + (lane & 7);
                int c = kp * 4 + (lane >> 3);
                ldsm4(bhf[nb], bB + (uint32_t)(r * 128 + ((c ^ (r & 7)) << 4)));
            }
#pragma unroll
            for (int k2 = 0; k2 < 2; k2++) {
                const int kk = kp * 2 + k2;
                uint32_t ahf[4][4], alf[4][4];
#pragma unroll
                for (int mi = 0; mi < 4; mi++) {
                    int r = wm * 64 + mi * 16 + (lane & 15);
                    int c = kk * 2 + (lane >> 4);
                    uint32_t off = (uint32_t)(r * 128 + ((c ^ (r & 7)) << 4));
                    ldsm4(ahf[mi], aH + off);
                    if (NPASS == 2) ldsm4(alf[mi], aL + off);
                }
#pragma unroll
                for (int mi = 0; mi < 4; mi++)
#pragma unroll
                    for (int nb = 0; nb < 4; nb++) {
                        mma16816(acc[mi][nb], ahf[mi], bhf[nb] + k2 * 2);
                        if (NPASS == 2) mma16816(acc[mi][nb], alf[mi], bhf[nb] + k2 * 2);
                    }
            }
        }
    }

    // Epilogue: direct register -> global
#pragma unroll
    for (int mi = 0; mi < 4; mi++) {
        int r0 = m0 + wm * 64 + mi * 16 + (lane >> 2);
#pragma unroll
        for (int nb = 0; nb < 4; nb++) {
            int col = n0 + wn * 32 + nb * 8 + (lane & 3) * 2;
            if (HALF_OUT) {
                __half* Ch = (__half*)Cout;
                *(__half2*)(Ch + (size_t)r0 * N + col) =
                    __floats2half2_rn(acc[mi][nb][0], acc[mi][nb][1]);
                *(__half2*)(Ch + (size_t)(r0 + 8) * N + col) =
                    __floats2half2_rn(acc[mi][nb][2], acc[mi][nb][3]);
            } else {
                float* Cf = (float*)Cout;
                *(float2*)(Cf + (size_t)r0 * N + col) =
                    make_float2(acc[mi][nb][0], acc[mi][nb][1]);
                *(float2*)(Cf + (size_t)(r0 + 8) * N + col) =
                    make_float2(acc[mi][nb][2], acc[mi][nb][3]);
            }
        }
    }
}
#define G1_SMEM (NSTG * 2 * TILE16)   // 131072
#define G2_SMEM (NSTG * 3 * TILE16)   // 196608

// ===========================================================================
// Register-resident flash attention (raw mma, fp16), epilogue emits fp16 hi/lo.
// ===========================================================================
#define AT_LD   72
#define AT_ROWB (AT_LD*2)
#define OFF_Q   0
#define Q_BYTES (128*AT_ROWB)
#define OFF_KV  Q_BYTES
#define KV_STG  (64*AT_ROWB*2)
#define ATT2_SMEM (OFF_KV + 2*KV_STG)

__global__ __launch_bounds__(256, 1) void attn_reg(const __half* __restrict__ Q,
                                                   const __half* __restrict__ K,
                                                   const __half* __restrict__ V,
                                                   const int*    __restrict__ mask,
                                                   __half* __restrict__ Ohi,
                                                   __half* __restrict__ Olo)
{
    extern __shared__ char smem_raw[];
    const uint32_t sb = smem_u32a(smem_raw);

    const int tid  = threadIdx.x;
    const int w    = tid >> 5;
    const int lane = tid & 31;
    const int b    = blockIdx.y >> 4;
    const int h    = blockIdx.y & 15;
    const int q0   = blockIdx.x * 128;

    auto prefetch = [&](int kt, int s){
        uint32_t kbase = sb + OFF_KV + s * KV_STG;
        uint32_t vbase = kbase + 64 * AT_ROWB;
        const __half* Kg = K + (size_t)(b * T_ + kt * 64) * C_ + h * D_;
        const __half* Vg = V + (size_t)(b * T_ + kt * 64) * C_ + h * D_;
#pragma unroll
        for (int i = 0; i < 2; i++) {
            int cid = i * 256 + tid;
            int r = cid >> 3, c = cid & 7;
            CP16(kbase + r * AT_ROWB + c * 16, Kg + (size_t)r * C_ + c * 8);
            CP16(vbase + r * AT_ROWB + c * 16, Vg + (size_t)r * C_ + c * 8);
        }
    };

    prefetch(0, 0); CP_COMMIT();
    prefetch(1, 1); CP_COMMIT();

#pragma unroll
    for (int i = 0; i < 4; i++) {
        int cid = i * 256 + tid;
        int r = cid >> 3, c = cid & 7;
        *(uint4*)(smem_raw + OFF_Q + r * AT_ROWB + c * 16) =
            *(const uint4*)(Q + (size_t)(b * T_ + q0 + r) * C_ + h * D_ + c * 8);
    }
    __syncthreads();
    uint32_t qf[4][4];
#pragma unroll
    for (int kd = 0; kd < 4; kd++) {
        uint32_t aq = sb + OFF_Q + (w * 16 + (lane & 15)) * AT_ROWB
                    + (kd * 16 + (lane >> 4) * 8) * 2;
        ldsm4(qf[kd], aq);
    }

    float oacc[8][4];
#pragma unroll
    for (int i = 0; i < 8; i++)
#pragma unroll
        for (int j = 0; j < 4; j++) oacc[i][j] = 0.f;
    float lsum0 = 0.f, lsum1 = 0.f;

    const int NT = T_ / 64;
    for (int kt = 0; kt < NT; kt++) {
        const int s = kt & 1;
        if (kt + 1 < NT) { CP_WAIT1(); } else { CP_WAIT0(); }
        __syncthreads();

        const uint32_t kS = sb + OFF_KV + s * KV_STG;
        const uint32_t vS = kS + 64 * AT_ROWB;
        const int flag = g_mflag[(b * 16 + blockIdx.x) * 32 + kt];

        uint32_t pf[4][4];
#pragma unroll
        for (int j = 0; j < 8; j++) {
            float sj[4] = {0.f, 0.f, 0.f, 0.f};
            uint32_t kb0[4], kb1[4];
            uint32_t a0 = kS + (j * 8 + (lane & 7)) * AT_ROWB + (lane >> 3) * 16;
            ldsm4(kb0, a0);
            ldsm4(kb1, a0 + 64);
            mma16816(sj, qf[0], kb0 + 0);
            mma16816(sj, qf[1], kb0 + 2);
            mma16816(sj, qf[2], kb1 + 0);
            mma16816(sj, qf[3], kb1 + 2);

            float e0 = __expf(sj[0] * 0.125f);
            float e1 = __expf(sj[1] * 0.125f);
            float e2 = __expf(sj[2] * 0.125f);
            float e3 = __expf(sj[3] * 0.125f);
            if (!flag) {
                const int* mp = mask + ((size_t)b * T_ + q0 + w * 16 + (lane >> 2)) * T_
                              + kt * 64 + j * 8 + 2 * (lane & 3);
                int2 m0v = *(const int2*)mp;
                int2 m1v = *(const int2*)(mp + 8 * T_);
                if (m0v.x == 0) e0 = 0.f;
                if (m0v.y == 0) e1 = 0.f;
                if (m1v.x == 0) e2 = 0.f;
                if (m1v.y == 0) e3 = 0.f;
            }
            lsum0 += e0 + e1;
            lsum1 += e2 + e3;
            pf[j >> 1][(j & 1) * 2 + 0] = packe(e0, e1);
            pf[j >> 1][(j & 1) * 2 + 1] = packe(e2, e3);
        }

#pragma unroll
        for (int kk = 0; kk < 4; kk++) {
#pragma unroll
            for (int np = 0; np < 4; np++) {
                uint32_t vb[4];
                uint32_t ad = vS + (kk * 16 + ((lane >> 3) & 1) * 8 + (lane & 7)) * AT_ROWB
                            + (np * 16 + (lane >> 4) * 8) * 2;
                ldsm4t(vb, ad);
                mma16816(oacc[np * 2 + 0], pf[kk], vb + 0);
                mma16816(oacc[np * 2 + 1], pf[kk], vb + 2);
            }
        }

        __syncthreads();
        if (kt + 2 < NT) { prefetch(kt + 2, s); CP_COMMIT(); }
    }

    lsum0 += __shfl_xor_sync(0xFFFFFFFFu, lsum0, 1);
    lsum0 += __shfl_xor_sync(0xFFFFFFFFu, lsum0, 2);
    lsum1 += __shfl_xor_sync(0xFFFFFFFFu, lsum1, 1);
    lsum1 += __shfl_xor_sync(0xFFFFFFFFu, lsum1, 2);
    const float inv0 = 1.f / lsum0;
    const float inv1 = 1.f / lsum1;

    size_t o0 = (size_t)(b * T_ + q0 + w * 16 + (lane >> 2)) * C_ + h * D_ + 2 * (lane & 3);
    size_t o1 = o0 + 8 * C_;
#pragma unroll
    for (int nd = 0; nd < 8; nd++) {
        float v0 = oacc[nd][0] * inv0, v1 = oacc[nd][1] * inv0;
        float v2 = oacc[nd][2] * inv1, v3 = oacc[nd][3] * inv1;
        __half h0 = __float2half_rn(v0), h1 = __float2half_rn(v1);
        __half h2 = __float2half_rn(v2), h3 = __float2half_rn(v3);
        *(__half2*)(Ohi + o0 + nd * 8) = __half2(h0, h1);
        *(__half2*)(Ohi + o1 + nd * 8) = __half2(h2, h3);
        *(__half2*)(Olo + o0 + nd * 8) =
            __floats2half2_rn(v0 - __half2float(h0), v1 - __half2float(h1));
        *(__half2*)(Olo + o1 + nd * 8) =
            __floats2half2_rn(v2 - __half2float(h2), v3 - __half2float(h3));
    }
}

// ===========================================================================
extern "C" void kernel_launch(void* const* d_in, const int* in_sizes, int n_in,
                              void* d_out, int out_size)
{
    const float* x    = (const float*)d_in[0];
    const int*   mask = (const int*)  d_in[1];
    const float* Wq   = (const float*)d_in[2];
    const float* Wk   = (const float*)d_in[3];
    const float* Wv   = (const float*)d_in[4];
    const float* Wo   = (const float*)d_in[5];
    float* out = (float*)d_out;

    __half *Qh, *Kh, *Vh, *xh, *wh, *Ohi, *Olo;
    cudaGetSymbolAddress((void**)&Qh,  g_Qh);
    cudaGetSymbolAddress((void**)&Kh,  g_Kh);
    cudaGetSymbolAddress((void**)&Vh,  g_Vh);
    cudaGetSymbolAddress((void**)&xh,  g_xh);
    cudaGetSymbolAddress((void**)&wh,  g_wh);
    cudaGetSymbolAddress((void**)&Ohi, g_Ohi);
    cudaGetSymbolAddress((void**)&Olo, g_Olo);

    cudaFuncSetAttribute((const void*)gemm_fp16<1, true>,
                         cudaFuncAttributeMaxDynamicSharedMemorySize, G1_SMEM);
    cudaFuncSetAttribute((const void*)gemm_fp16<2, false>,
                         cudaFuncAttributeMaxDynamicSharedMemorySize, G2_SMEM);
    cudaFuncSetAttribute(attn_reg, cudaFuncAttributeMaxDynamicSharedMemorySize, ATT2_SMEM);

    const int WN = C_ * C_;          // 1048576
    tofp16<<<M_ * C_ / 1024, 256>>>(x,  xh, M_ * C_);
    tofp16<<<WN / 1024, 256>>>(Wq, wh + 0 * (size_t)WN, WN);
    tofp16<<<WN / 1024, 256>>>(Wk, wh + 1 * (size_t)WN, WN);
    tofp16<<<WN / 1024, 256>>>(Wv, wh + 2 * (size_t)WN, WN);
    tofp16<<<WN / 1024, 256>>>(Wo, wh + 3 * (size_t)WN, WN);

    mask_flags<<<B_ * 16 * 32, 256>>>(mask);

    dim3 gq(C_ / 128, M_ / 128, 3);   // fused QKV, single-pass fp16
    gemm_fp16<1, true><<<gq, 256, G1_SMEM>>>(xh, xh, wh, Qh, Kh, Vh, M_, C_, C_);

    dim3 ga(T_ / 128, B_ * H_);
    attn_reg<<<ga, 256, ATT2_SMEM>>>(Qh, Kh, Vh, mask, Ohi, Olo);

    dim3 go(C_ / 128, M_ / 128, 1);   // out-proj, 2-pass (A exact, Wo fp16)
    gemm_fp16<2, false><<<go, 256, G2_SMEM>>>(Ohi, Olo, wh + 3 * (size_t)WN,
                                              out, out, out, M_, C_, C_);
}

// round 7
// speedup vs baseline: 8.6383x; 1.1343x over previous
#include <cuda_runtime.h>
#include <cuda_fp16.h>
#include <cstdint>
#include <math.h>

// Problem constants
#define B_  4
#define T_  2048
#define C_  1024
#define H_  16
#define D_  64
#define M_  (B_*T_)   // 8192

// Scratch (allocation-free rule: __device__ globals)
__device__ __half g_Qh[M_ * C_];
__device__ __half g_Kh[M_ * C_];
__device__ __half g_Vh[M_ * C_];
__device__ __half g_xh[M_ * C_];
__device__ __half g_wh[4 * C_ * C_];
__device__ __half g_Oh[M_ * C_];
__device__ int    g_mflag[B_ * 16 * 32];

// ---------------------------------------------------------------------------
// Common PTX helpers
// ---------------------------------------------------------------------------
__device__ __forceinline__ uint32_t smem_u32a(const void* p){
    uint32_t a;
    asm("{ .reg .u64 t; cvta.to.shared.u64 t, %1; cvt.u32.u64 %0, t; }" : "=r"(a) : "l"(p));
    return a;
}
__device__ __forceinline__ void mma16816(float* d, const uint32_t* a, const uint32_t* b){
    asm volatile("mma.sync.aligned.m16n8k16.row.col.f32.f16.f16.f32 "
        "{%0,%1,%2,%3}, {%4,%5,%6,%7}, {%8,%9}, {%0,%1,%2,%3};"
        : "+f"(d[0]), "+f"(d[1]), "+f"(d[2]), "+f"(d[3])
        : "r"(a[0]), "r"(a[1]), "r"(a[2]), "r"(a[3]), "r"(b[0]), "r"(b[1]));
}
__device__ __forceinline__ void ldsm4(uint32_t* r, uint32_t addr){
    asm volatile("ldmatrix.sync.aligned.m8n8.x4.shared.b16 {%0,%1,%2,%3}, [%4];"
        : "=r"(r[0]), "=r"(r[1]), "=r"(r[2]), "=r"(r[3]) : "r"(addr));
}
__device__ __forceinline__ void ldsm4t(uint32_t* r, uint32_t addr){
    asm volatile("ldmatrix.sync.aligned.m8n8.x4.trans.shared.b16 {%0,%1,%2,%3}, [%4];"
        : "=r"(r[0]), "=r"(r[1]), "=r"(r[2]), "=r"(r[3]) : "r"(addr));
}
__device__ __forceinline__ uint32_t packe(float a, float b){
    __half2 h = __floats2half2_rn(a, b);
    return *(uint32_t*)&h;
}
#define CP16(dst, src) asm volatile("cp.async.cg.shared.global [%0], [%1], 16;" :: "r"(dst), "l"(src))
#define CP_COMMIT()    asm volatile("cp.async.commit_group;")
#define CP_WAIT1()     asm volatile("cp.async.wait_group 1;")
#define CP_WAIT0()     asm volatile("cp.async.wait_group 0;")

// ---------------------------------------------------------------------------
// fp32 -> fp16 converts
// ---------------------------------------------------------------------------
__global__ __launch_bounds__(256) void tofp16(const float* __restrict__ src,
                                              __half* __restrict__ dst, int n)
{
    int i = (blockIdx.x * 256 + threadIdx.x) * 4;
    if (i >= n) return;
    float4 v = *(const float4*)(src + i);
    ((__half2*)(dst + i))[0] = __floats2half2_rn(v.x, v.y);
    ((__half2*)(dst + i))[1] = __floats2half2_rn(v.z, v.w);
}
__global__ __launch_bounds__(256) void tofp16_w(const float* __restrict__ w0,
                                                const float* __restrict__ w1,
                                                const float* __restrict__ w2,
                                                const float* __restrict__ w3,
                                                __half* __restrict__ dst)
{
    const int z = blockIdx.y;
    const float* src = z == 0 ? w0 : (z == 1 ? w1 : (z == 2 ? w2 : w3));
    int i = (blockIdx.x * 256 + threadIdx.x) * 4;
    float4 v = *(const float4*)(src + i);
    __half* d = dst + (size_t)z * C_ * C_ + i;
    ((__half2*)d)[0] = __floats2half2_rn(v.x, v.y);
    ((__half2*)d)[1] = __floats2half2_rn(v.z, v.w);
}

// ---------------------------------------------------------------------------
// Mask pre-scan: flag[b][qb][kb] = 1 iff mask[b, qb*128:+128, kb*64:+64] all != 0
// ---------------------------------------------------------------------------
__global__ __launch_bounds__(256) void mask_flags(const int* __restrict__ mask)
{
    __shared__ int s_zero;
    const int t = threadIdx.x;
    if (t == 0) s_zero = 0;
    __syncthreads();
    const int fid = blockIdx.x;
    const int b  = fid >> 9;
    const int qb = (fid >> 5) & 15;
    const int kb = fid & 31;
    const int* base = mask + ((size_t)b * T_ + qb * 128) * T_ + kb * 64;
    const int r = t >> 1, hh = t & 1;
    const int4* p = (const int4*)(base + (size_t)r * T_ + hh * 32);
    bool ok = true;
#pragma unroll
    for (int i = 0; i < 8; i++) {
        int4 v = p[i];
        ok = ok && (v.x != 0) && (v.y != 0) && (v.z != 0) && (v.w != 0);
    }
    if (!ok) s_zero = 1;
    __syncthreads();
    if (t == 0) g_mflag[fid] = s_zero ? 0 : 1;
}

// ===========================================================================
// GEMM v4: C[m,n] = sum_k A[m,k]*W[n,k], single-pass fp16 mma.
// CTA 128x128, BK=64, 3-stage cp.async (96KB smem -> 2 CTAs/SM),
// XOR-swizzled smem, 8 warps: wm in {0,1}, wn in {0..3}.
// blockIdx.z selects weight slice + output (fused QKV).
// ===========================================================================
#define TILE16 16384                  // 128 rows x 128 bytes (64 fp16 cols)
#define NSTG   3
#define STAGE_B (2*TILE16)            // A | B
#define G_SMEM (NSTG*STAGE_B)         // 98304

template<bool HALF_OUT>
__global__ __launch_bounds__(256, 2) void gemm_fp16(
    const __half* __restrict__ Ag,
    const __half* __restrict__ Bg,
    void* __restrict__ C0, void* __restrict__ C1, void* __restrict__ C2,
    int M, int N, int K)
{
    extern __shared__ char smem_raw[];
    const uint32_t sb = smem_u32a(smem_raw);

    const int z = blockIdx.z;
    const __half* Bz = Bg + (size_t)z * N * K;
    void* Cout = z == 0 ? C0 : (z == 1 ? C1 : C2);

    const int tid  = threadIdx.x;
    const int w    = tid >> 5;
    const int lane = tid & 31;
    const int wm   = w >> 2;          // 0..1
    const int wn   = w & 3;           // 0..3
    const int m0   = blockIdx.y * 128;
    const int n0   = blockIdx.x * 128;

    auto prefetch = [&](int t, int s){
        uint32_t st = sb + s * STAGE_B;
        int k0 = t * 64;
#pragma unroll
        for (int i = 0; i < 4; i++) {
            int id = i * 256 + tid;          // 0..1023
            int r = id >> 3, c = id & 7;
            uint32_t dsw = (uint32_t)(r * 128 + ((c ^ (r & 7)) << 4));
            CP16(st + dsw,          Ag + (size_t)(m0 + r) * K + k0 + c * 8);
            CP16(st + TILE16 + dsw, Bz + (size_t)(n0 + r) * K + k0 + c * 8);
        }
    };

    prefetch(0, 0); CP_COMMIT();
    prefetch(1, 1); CP_COMMIT();

    float acc[4][4][4];
#pragma unroll
    for (int mi = 0; mi < 4; mi++)
#pragma unroll
        for (int nb = 0; nb < 4; nb++)
#pragma unroll
            for (int j = 0; j < 4; j++) acc[mi][nb][j] = 0.f;

    const int NT = K / 64;            // 16
    for (int t = 0; t < NT; t++) {
        CP_WAIT1();
        __syncthreads();
        if (t + 2 < NT) prefetch(t + 2, (t + 2) % NSTG);
        CP_COMMIT();                  // uniform group accounting

        const uint32_t aB = sb + (t % NSTG) * STAGE_B;
        const uint32_t bB = aB + TILE16;

#pragma unroll
        for (int kp = 0; kp < 2; kp++) {
            uint32_t bhf[4][4];
#pragma unroll
            for (int nb = 0; nb < 4; nb++) {
                int r = wn * 32 + nb * 8 + (lane & 7);
                int c = kp * 4 + (lane >> 3);
                ldsm4(bhf[nb], bB + (uint32_t)(r * 128 + ((c ^ (r & 7)) << 4)));
            }
#pragma unroll
            for (int k2 = 0; k2 < 2; k2++) {
                const int kk = kp * 2 + k2;
                uint32_t ahf[4][4];
#pragma unroll
                for (int mi = 0; mi < 4; mi++) {
                    int r = wm * 64 + mi * 16 + (lane & 15);
                    int c = kk * 2 + (lane >> 4);
                    ldsm4(ahf[mi], aB + (uint32_t)(r * 128 + ((c ^ (r & 7)) << 4)));
                }
#pragma unroll
                for (int mi = 0; mi < 4; mi++)
#pragma unroll
                    for (int nb = 0; nb < 4; nb++)
                        mma16816(acc[mi][nb], ahf[mi], bhf[nb] + k2 * 2);
            }
        }
    }

    // Epilogue: direct register -> global
#pragma unroll
    for (int mi = 0; mi < 4; mi++) {
        int r0 = m0 + wm * 64 + mi * 16 + (lane >> 2);
#pragma unroll
        for (int nb = 0; nb < 4; nb++) {
            int col = n0 + wn * 32 + nb * 8 + (lane & 3) * 2;
            if (HALF_OUT) {
                __half* Ch = (__half*)Cout;
                *(__half2*)(Ch + (size_t)r0 * N + col) =
                    __floats2half2_rn(acc[mi][nb][0], acc[mi][nb][1]);
                *(__half2*)(Ch + (size_t)(r0 + 8) * N + col) =
                    __floats2half2_rn(acc[mi][nb][2], acc[mi][nb][3]);
            } else {
                float* Cf = (float*)Cout;
                *(float2*)(Cf + (size_t)r0 * N + col) =
                    make_float2(acc[mi][nb][0], acc[mi][nb][1]);
                *(float2*)(Cf + (size_t)(r0 + 8) * N + col) =
                    make_float2(acc[mi][nb][2], acc[mi][nb][3]);
            }
        }
    }
}

// ===========================================================================
// Register-resident flash attention (raw mma, fp16), fp16 output.
// ===========================================================================
#define AT_LD   72
#define AT_ROWB (AT_LD*2)
#define OFF_Q   0
#define Q_BYTES (128*AT_ROWB)
#define OFF_KV  Q_BYTES
#define KV_STG  (64*AT_ROWB*2)
#define ATT2_SMEM (OFF_KV + 2*KV_STG)

__global__ __launch_bounds__(256, 1) void attn_reg(const __half* __restrict__ Q,
                                                   const __half* __restrict__ K,
                                                   const __half* __restrict__ V,
                                                   const int*    __restrict__ mask,
                                                   __half* __restrict__ Oh)
{
    extern __shared__ char smem_raw[];
    const uint32_t sb = smem_u32a(smem_raw);

    const int tid  = threadIdx.x;
    const int w    = tid >> 5;
    const int lane = tid & 31;
    const int b    = blockIdx.y >> 4;
    const int h    = blockIdx.y & 15;
    const int q0   = blockIdx.x * 128;

    auto prefetch = [&](int kt, int s){
        uint32_t kbase = sb + OFF_KV + s * KV_STG;
        uint32_t vbase = kbase + 64 * AT_ROWB;
        const __half* Kg = K + (size_t)(b * T_ + kt * 64) * C_ + h * D_;
        const __half* Vg = V + (size_t)(b * T_ + kt * 64) * C_ + h * D_;
#pragma unroll
        for (int i = 0; i < 2; i++) {
            int cid = i * 256 + tid;
            int r = cid >> 3, c = cid & 7;
            CP16(kbase + r * AT_ROWB + c * 16, Kg + (size_t)r * C_ + c * 8);
            CP16(vbase + r * AT_ROWB + c * 16, Vg + (size_t)r * C_ + c * 8);
        }
    };

    prefetch(0, 0); CP_COMMIT();
    prefetch(1, 1); CP_COMMIT();

#pragma unroll
    for (int i = 0; i < 4; i++) {
        int cid = i * 256 + tid;
        int r = cid >> 3, c = cid & 7;
        *(uint4*)(smem_raw + OFF_Q + r * AT_ROWB + c * 16) =
            *(const uint4*)(Q + (size_t)(b * T_ + q0 + r) * C_ + h * D_ + c * 8);
    }
    __syncthreads();
    uint32_t qf[4][4];
#pragma unroll
    for (int kd = 0; kd < 4; kd++) {
        uint32_t aq = sb + OFF_Q + (w * 16 + (lane & 15)) * AT_ROWB
                    + (kd * 16 + (lane >> 4) * 8) * 2;
        ldsm4(qf[kd], aq);
    }

    float oacc[8][4];
#pragma unroll
    for (int i = 0; i < 8; i++)
#pragma unroll
        for (int j = 0; j < 4; j++) oacc[i][j] = 0.f;
    float lsum0 = 0.f, lsum1 = 0.f;

    const int NT = T_ / 64;
    for (int kt = 0; kt < NT; kt++) {
        const int s = kt & 1;
        if (kt + 1 < NT) { CP_WAIT1(); } else { CP_WAIT0(); }
        __syncthreads();

        const uint32_t kS = sb + OFF_KV + s * KV_STG;
        const uint32_t vS = kS + 64 * AT_ROWB;
        const int flag = g_mflag[(b * 16 + blockIdx.x) * 32 + kt];

        uint32_t pf[4][4];
#pragma unroll
        for (int j = 0; j < 8; j++) {
            float sj[4] = {0.f, 0.f, 0.f, 0.f};
            uint32_t kb0[4], kb1[4];
            uint32_t a0 = kS + (j * 8 + (lane & 7)) * AT_ROWB + (lane >> 3) * 16;
            ldsm4(kb0, a0);
            ldsm4(kb1, a0 + 64);
            mma16816(sj, qf[0], kb0 + 0);
            mma16816(sj, qf[1], kb0 + 2);
            mma16816(sj, qf[2], kb1 + 0);
            mma16816(sj, qf[3], kb1 + 2);

            float e0 = __expf(sj[0] * 0.125f);
            float e1 = __expf(sj[1] * 0.125f);
            float e2 = __expf(sj[2] * 0.125f);
            float e3 = __expf(sj[3] * 0.125f);
            if (!flag) {
                const int* mp = mask + ((size_t)b * T_ + q0 + w * 16 + (lane >> 2)) * T_
                              + kt * 64 + j * 8 + 2 * (lane & 3);
                int2 m0v = *(const int2*)mp;
                int2 m1v = *(const int2*)(mp + 8 * T_);
                if (m0v.x == 0) e0 = 0.f;
                if (m0v.y == 0) e1 = 0.f;
                if (m1v.x == 0) e2 = 0.f;
                if (m1v.y == 0) e3 = 0.f;
            }
            lsum0 += e0 + e1;
            lsum1 += e2 + e3;
            pf[j >> 1][(j & 1) * 2 + 0] = packe(e0, e1);
            pf[j >> 1][(j & 1) * 2 + 1] = packe(e2, e3);
        }

#pragma unroll
        for (int kk = 0; kk < 4; kk++) {
#pragma unroll
            for (int np = 0; np < 4; np++) {
                uint32_t vb[4];
                uint32_t ad = vS + (kk * 16 + ((lane >> 3) & 1) * 8 + (lane & 7)) * AT_ROWB
                            + (np * 16 + (lane >> 4) * 8) * 2;
                ldsm4t(vb, ad);
                mma16816(oacc[np * 2 + 0], pf[kk], vb + 0);
                mma16816(oacc[np * 2 + 1], pf[kk], vb + 2);
            }
        }

        __syncthreads();
        if (kt + 2 < NT) { prefetch(kt + 2, s); CP_COMMIT(); }
    }

    lsum0 += __shfl_xor_sync(0xFFFFFFFFu, lsum0, 1);
    lsum0 += __shfl_xor_sync(0xFFFFFFFFu, lsum0, 2);
    lsum1 += __shfl_xor_sync(0xFFFFFFFFu, lsum1, 1);
    lsum1 += __shfl_xor_sync(0xFFFFFFFFu, lsum1, 2);
    const float inv0 = 1.f / lsum0;
    const float inv1 = 1.f / lsum1;

    size_t o0 = (size_t)(b * T_ + q0 + w * 16 + (lane >> 2)) * C_ + h * D_ + 2 * (lane & 3);
    size_t o1 = o0 + 8 * C_;
#pragma unroll
    for (int nd = 0; nd < 8; nd++) {
        *(__half2*)(Oh + o0 + nd * 8) =
            __floats2half2_rn(oacc[nd][0] * inv0, oacc[nd][1] * inv0);
        *(__half2*)(Oh + o1 + nd * 8) =
            __floats2half2_rn(oacc[nd][2] * inv1, oacc[nd][3] * inv1);
    }
}

// ===========================================================================
extern "C" void kernel_launch(void* const* d_in, const int* in_sizes, int n_in,
                              void* d_out, int out_size)
{
    const float* x    = (const float*)d_in[0];
    const int*   mask = (const int*)  d_in[1];
    const float* Wq   = (const float*)d_in[2];
    const float* Wk   = (const float*)d_in[3];
    const float* Wv   = (const float*)d_in[4];
    const float* Wo   = (const float*)d_in[5];
    float* out = (float*)d_out;

    __half *Qh, *Kh, *Vh, *xh, *wh, *Oh;
    cudaGetSymbolAddress((void**)&Qh, g_Qh);
    cudaGetSymbolAddress((void**)&Kh, g_Kh);
    cudaGetSymbolAddress((void**)&Vh, g_Vh);
    cudaGetSymbolAddress((void**)&xh, g_xh);
    cudaGetSymbolAddress((void**)&wh, g_wh);
    cudaGetSymbolAddress((void**)&Oh, g_Oh);

    cudaFuncSetAttribute((const void*)gemm_fp16<true>,
                         cudaFuncAttributeMaxDynamicSharedMemorySize, G_SMEM);
    cudaFuncSetAttribute((const void*)gemm_fp16<false>,
                         cudaFuncAttributeMaxDynamicSharedMemorySize, G_SMEM);
    cudaFuncSetAttribute(attn_reg, cudaFuncAttributeMaxDynamicSharedMemorySize, ATT2_SMEM);

    const int WN = C_ * C_;          // 1048576
    tofp16<<<M_ * C_ / 1024, 256>>>(x, xh, M_ * C_);
    dim3 gw(WN / 1024, 4);
    tofp16_w<<<gw, 256>>>(Wq, Wk, Wv, Wo, wh);

    mask_flags<<<B_ * 16 * 32, 256>>>(mask);

    dim3 gq(C_ / 128, M_ / 128, 3);   // fused QKV, single-pass fp16
    gemm_fp16<true><<<gq, 256, G_SMEM>>>(xh, wh, Qh, Kh, Vh, M_, C_, C_);

    dim3 ga(T_ / 128, B_ * H_);
    attn_reg<<<ga, 256, ATT2_SMEM>>>(Qh, Kh, Vh, mask, Oh);

    dim3 go(C_ / 128, M_ / 128, 1);   // out-proj, single-pass fp16
    gemm_fp16<false><<<go, 256, G_SMEM>>>(Oh, wh + 3 * (size_t)WN,
                                          out, out, out, M_, C_, C_);
}

// round 8
// speedup vs baseline: 9.5708x; 1.1079x over previous
#include <cuda_runtime.h>
#include <cuda_fp16.h>
#include <cstdint>
#include <math.h>

// Problem constants
#define B_  4
#define T_  2048
#define C_  1024
#define H_  16
#define D_  64
#define M_  (B_*T_)   // 8192

// Scratch (allocation-free rule: __device__ globals)
__device__ __half g_Qh[M_ * C_];
__device__ __half g_Kh[M_ * C_];
__device__ __half g_Vh[M_ * C_];
__device__ __half g_xh[M_ * C_];
__device__ __half g_wh[4 * C_ * C_];
__device__ __half g_Oh[M_ * C_];
__device__ int    g_mflag[B_ * 16 * 32];

// ---------------------------------------------------------------------------
// Common PTX helpers
// ---------------------------------------------------------------------------
__device__ __forceinline__ uint32_t smem_u32a(const void* p){
    uint32_t a;
    asm("{ .reg .u64 t; cvta.to.shared.u64 t, %1; cvt.u32.u64 %0, t; }" : "=r"(a) : "l"(p));
    return a;
}
__device__ __forceinline__ void mma16816(float* d, const uint32_t* a, const uint32_t* b){
    asm volatile("mma.sync.aligned.m16n8k16.row.col.f32.f16.f16.f32 "
        "{%0,%1,%2,%3}, {%4,%5,%6,%7}, {%8,%9}, {%0,%1,%2,%3};"
        : "+f"(d[0]), "+f"(d[1]), "+f"(d[2]), "+f"(d[3])
        : "r"(a[0]), "r"(a[1]), "r"(a[2]), "r"(a[3]), "r"(b[0]), "r"(b[1]));
}
__device__ __forceinline__ void ldsm4(uint32_t* r, uint32_t addr){
    asm volatile("ldmatrix.sync.aligned.m8n8.x4.shared.b16 {%0,%1,%2,%3}, [%4];"
        : "=r"(r[0]), "=r"(r[1]), "=r"(r[2]), "=r"(r[3]) : "r"(addr));
}
__device__ __forceinline__ void ldsm4t(uint32_t* r, uint32_t addr){
    asm volatile("ldmatrix.sync.aligned.m8n8.x4.trans.shared.b16 {%0,%1,%2,%3}, [%4];"
        : "=r"(r[0]), "=r"(r[1]), "=r"(r[2]), "=r"(r[3]) : "r"(addr));
}
__device__ __forceinline__ uint32_t packe(float a, float b){
    __half2 h = __floats2half2_rn(a, b);
    return *(uint32_t*)&h;
}
#define CP16(dst, src) asm volatile("cp.async.cg.shared.global [%0], [%1], 16;" :: "r"(dst), "l"(src))
#define CP_COMMIT()    asm volatile("cp.async.commit_group;")
#define CP_WAIT1()     asm volatile("cp.async.wait_group 1;")
#define CP_WAIT0()     asm volatile("cp.async.wait_group 0;")

// ---------------------------------------------------------------------------
// fp32 -> fp16 converts
// ---------------------------------------------------------------------------
__global__ __launch_bounds__(256) void tofp16(const float* __restrict__ src,
                                              __half* __restrict__ dst, int n)
{
    int i = (blockIdx.x * 256 + threadIdx.x) * 4;
    if (i >= n) return;
    float4 v = *(const float4*)(src + i);
    ((__half2*)(dst + i))[0] = __floats2half2_rn(v.x, v.y);
    ((__half2*)(dst + i))[1] = __floats2half2_rn(v.z, v.w);
}
__global__ __launch_bounds__(256) void tofp16_w(const float* __restrict__ w0,
                                                const float* __restrict__ w1,
                                                const float* __restrict__ w2,
                                                const float* __restrict__ w3,
                                                __half* __restrict__ dst)
{
    const int z = blockIdx.y;
    const float* src = z == 0 ? w0 : (z == 1 ? w1 : (z == 2 ? w2 : w3));
    int i = (blockIdx.x * 256 + threadIdx.x) * 4;
    float4 v = *(const float4*)(src + i);
    __half* d = dst + (size_t)z * C_ * C_ + i;
    ((__half2*)d)[0] = __floats2half2_rn(v.x, v.y);
    ((__half2*)d)[1] = __floats2half2_rn(v.z, v.w);
}

// ---------------------------------------------------------------------------
// Mask pre-scan: flag[b][qb][kb] = 1 iff mask[b, qb*128:+128, kb*64:+64] all != 0
// ---------------------------------------------------------------------------
__global__ __launch_bounds__(256) void mask_flags(const int* __restrict__ mask)
{
    __shared__ int s_zero;
    const int t = threadIdx.x;
    if (t == 0) s_zero = 0;
    __syncthreads();
    const int fid = blockIdx.x;
    const int b  = fid >> 9;
    const int qb = (fid >> 5) & 15;
    const int kb = fid & 31;
    const int* base = mask + ((size_t)b * T_ + qb * 128) * T_ + kb * 64;
    const int r = t >> 1, hh = t & 1;
    const int4* p = (const int4*)(base + (size_t)r * T_ + hh * 32);
    bool ok = true;
#pragma unroll
    for (int i = 0; i < 8; i++) {
        int4 v = p[i];
        ok = ok && (v.x != 0) && (v.y != 0) && (v.z != 0) && (v.w != 0);
    }
    if (!ok) s_zero = 1;
    __syncthreads();
    if (t == 0) g_mflag[fid] = s_zero ? 0 : 1;
}

// ===========================================================================
// GEMM v5: C[m,n] = sum_k A[m,k]*W[n,k], single-pass fp16 mma.
// CTA 128x128, BK=64, 3-stage cp.async (96KB -> 2 CTAs/SM), 128 threads,
// 4 warps with 64x64 tiles (wm in {0,1}, wn in {0,1}); 128 mma / 32 ldsm / ktile.
// blockIdx.z selects weight slice + output (fused QKV).
// ===========================================================================
#define TILE16 16384                  // 128 rows x 128 bytes (64 fp16 cols)
#define NSTG   3
#define STAGE_B (2*TILE16)            // A | B
#define G_SMEM (NSTG*STAGE_B)         // 98304

template<bool HALF_OUT>
__global__ __launch_bounds__(128, 2) void gemm_fp16(
    const __half* __restrict__ Ag,
    const __half* __restrict__ Bg,
    void* __restrict__ C0, void* __restrict__ C1, void* __restrict__ C2,
    int M, int N, int K)
{
    extern __shared__ char smem_raw[];
    const uint32_t sb = smem_u32a(smem_raw);

    const int z = blockIdx.z;
    const __half* Bz = Bg + (size_t)z * N * K;
    void* Cout = z == 0 ? C0 : (z == 1 ? C1 : C2);

    const int tid  = threadIdx.x;
    const int w    = tid >> 5;
    const int lane = tid & 31;
    const int wm   = w >> 1;          // 0..1
    const int wn   = w & 1;           // 0..1
    const int m0   = blockIdx.y * 128;
    const int n0   = blockIdx.x * 128;

    auto prefetch = [&](int t, int s){
        uint32_t st = sb + s * STAGE_B;
        int k0 = t * 64;
#pragma unroll
        for (int i = 0; i < 8; i++) {
            int id = i * 128 + tid;          // 0..1023
            int r = id >> 3, c = id & 7;
            uint32_t dsw = (uint32_t)(r * 128 + ((c ^ (r & 7)) << 4));
            CP16(st + dsw,          Ag + (size_t)(m0 + r) * K + k0 + c * 8);
            CP16(st + TILE16 + dsw, Bz + (size_t)(n0 + r) * K + k0 + c * 8);
        }
    };

    prefetch(0, 0); CP_COMMIT();
    prefetch(1, 1); CP_COMMIT();

    float acc[4][8][4];
#pragma unroll
    for (int mi = 0; mi < 4; mi++)
#pragma unroll
        for (int nb = 0; nb < 8; nb++)
#pragma unroll
            for (int j = 0; j < 4; j++) acc[mi][nb][j] = 0.f;

    const int NT = K / 64;            // 16
    for (int t = 0; t < NT; t++) {
        CP_WAIT1();
        __syncthreads();
        if (t + 2 < NT) prefetch(t + 2, (t + 2) % NSTG);
        CP_COMMIT();                  // uniform group accounting

        const uint32_t aB = sb + (t % NSTG) * STAGE_B;
        const uint32_t bB = aB + TILE16;

#pragma unroll
        for (int kp = 0; kp < 2; kp++) {
            uint32_t bhf[8][4];
#pragma unroll
            for (int nb = 0; nb < 8; nb++) {
                int r = wn * 64 + nb * 8 + (lane & 7);
                int c = kp * 4 + (lane >> 3);
                ldsm4(bhf[nb], bB + (uint32_t)(r * 128 + ((c ^ (r & 7)) << 4)));
            }
#pragma unroll
            for (int k2 = 0; k2 < 2; k2++) {
                const int kk = kp * 2 + k2;
                uint32_t ahf[4][4];
#pragma unroll
                for (int mi = 0; mi < 4; mi++) {
                    int r = wm * 64 + mi * 16 + (lane & 15);
                    int c = kk * 2 + (lane >> 4);
                    ldsm4(ahf[mi], aB + (uint32_t)(r * 128 + ((c ^ (r & 7)) << 4)));
                }
#pragma unroll
                for (int mi = 0; mi < 4; mi++)
#pragma unroll
                    for (int nb = 0; nb < 8; nb++)
                        mma16816(acc[mi][nb], ahf[mi], bhf[nb] + k2 * 2);
            }
        }
    }

    // Epilogue: direct register -> global
#pragma unroll
    for (int mi = 0; mi < 4; mi++) {
        int r0 = m0 + wm * 64 + mi * 16 + (lane >> 2);
#pragma unroll
        for (int nb = 0; nb < 8; nb++) {
            int col = n0 + wn * 64 + nb * 8 + (lane & 3) * 2;
            if (HALF_OUT) {
                __half* Ch = (__half*)Cout;
                *(__half2*)(Ch + (size_t)r0 * N + col) =
                    __floats2half2_rn(acc[mi][nb][0], acc[mi][nb][1]);
                *(__half2*)(Ch + (size_t)(r0 + 8) * N + col) =
                    __floats2half2_rn(acc[mi][nb][2], acc[mi][nb][3]);
            } else {
                float* Cf = (float*)Cout;
                *(float2*)(Cf + (size_t)r0 * N + col) =
                    make_float2(acc[mi][nb][0], acc[mi][nb][1]);
                *(float2*)(Cf + (size_t)(r0 + 8) * N + col) =
                    make_float2(acc[mi][nb][2], acc[mi][nb][3]);
            }
        }
    }
}

// ===========================================================================
// Register-resident flash attention (raw mma, fp16), fp16 output.
// CTA = (b,h) x 64 q-rows, 128 threads (4 warps), 3 CTAs/SM.
// ===========================================================================
#define AT_LD   72
#define AT_ROWB (AT_LD*2)
#define OFF_Q   0
#define Q_BYTES (64*AT_ROWB)          // 9216
#define OFF_KV  Q_BYTES
#define KV_STG  (64*AT_ROWB*2)        // 18432
#define ATT2_SMEM (OFF_KV + 2*KV_STG) // 46080

__global__ __launch_bounds__(128, 3) void attn_reg(const __half* __restrict__ Q,
                                                   const __half* __restrict__ K,
                                                   const __half* __restrict__ V,
                                                   const int*    __restrict__ mask,
                                                   __half* __restrict__ Oh)
{
    extern __shared__ char smem_raw[];
    const uint32_t sb = smem_u32a(smem_raw);

    const int tid  = threadIdx.x;
    const int w    = tid >> 5;
    const int lane = tid & 31;
    const int b    = blockIdx.y >> 4;
    const int h    = blockIdx.y & 15;
    const int q0   = blockIdx.x * 64;

    auto prefetch = [&](int kt, int s){
        uint32_t kbase = sb + OFF_KV + s * KV_STG;
        uint32_t vbase = kbase + 64 * AT_ROWB;
        const __half* Kg = K + (size_t)(b * T_ + kt * 64) * C_ + h * D_;
        const __half* Vg = V + (size_t)(b * T_ + kt * 64) * C_ + h * D_;
#pragma unroll
        for (int i = 0; i < 4; i++) {
            int cid = i * 128 + tid;         // 0..511
            int r = cid >> 3, c = cid & 7;
            CP16(kbase + r * AT_ROWB + c * 16, Kg + (size_t)r * C_ + c * 8);
            CP16(vbase + r * AT_ROWB + c * 16, Vg + (size_t)r * C_ + c * 8);
        }
    };

    prefetch(0, 0); CP_COMMIT();
    prefetch(1, 1); CP_COMMIT();

#pragma unroll
    for (int i = 0; i < 4; i++) {
        int cid = i * 128 + tid;             // 0..511
        int r = cid >> 3, c = cid & 7;
        *(uint4*)(smem_raw + OFF_Q + r * AT_ROWB + c * 16) =
            *(const uint4*)(Q + (size_t)(b * T_ + q0 + r) * C_ + h * D_ + c * 8);
    }
    __syncthreads();
    uint32_t qf[4][4];
#pragma unroll
    for (int kd = 0; kd < 4; kd++) {
        uint32_t aq = sb + OFF_Q + (w * 16 + (lane & 15)) * AT_ROWB
                    + (kd * 16 + (lane >> 4) * 8) * 2;
        ldsm4(qf[kd], aq);
    }

    float oacc[8][4];
#pragma unroll
    for (int i = 0; i < 8; i++)
#pragma unroll
        for (int j = 0; j < 4; j++) oacc[i][j] = 0.f;
    float lsum0 = 0.f, lsum1 = 0.f;

    const int NT = T_ / 64;
    for (int kt = 0; kt < NT; kt++) {
        const int s = kt & 1;
        if (kt + 1 < NT) { CP_WAIT1(); } else { CP_WAIT0(); }
        __syncthreads();

        const uint32_t kS = sb + OFF_KV + s * KV_STG;
        const uint32_t vS = kS + 64 * AT_ROWB;
        const int flag = g_mflag[(b * 16 + (blockIdx.x >> 1)) * 32 + kt];

        uint32_t pf[4][4];
#pragma unroll
        for (int j = 0; j < 8; j++) {
            float sj[4] = {0.f, 0.f, 0.f, 0.f};
            uint32_t kb0[4], kb1[4];
            uint32_t a0 = kS + (j * 8 + (lane & 7)) * AT_ROWB + (lane >> 3) * 16;
            ldsm4(kb0, a0);
            ldsm4(kb1, a0 + 64);
            mma16816(sj, qf[0], kb0 + 0);
            mma16816(sj, qf[1], kb0 + 2);
            mma16816(sj, qf[2], kb1 + 0);
            mma16816(sj, qf[3], kb1 + 2);

            float e0 = __expf(sj[0] * 0.125f);
            float e1 = __expf(sj[1] * 0.125f);
            float e2 = __expf(sj[2] * 0.125f);
            float e3 = __expf(sj[3] * 0.125f);
            if (!flag) {
                const int* mp = mask + ((size_t)b * T_ + q0 + w * 16 + (lane >> 2)) * T_
                              + kt * 64 + j * 8 + 2 * (lane & 3);
                int2 m0v = *(const int2*)mp;
                int2 m1v = *(const int2*)(mp + 8 * T_);
                if (m0v.x == 0) e0 = 0.f;
                if (m0v.y == 0) e1 = 0.f;
                if (m1v.x == 0) e2 = 0.f;
                if (m1v.y == 0) e3 = 0.f;
            }
            lsum0 += e0 + e1;
            lsum1 += e2 + e3;
            pf[j >> 1][(j & 1) * 2 + 0] = packe(e0, e1);
            pf[j >> 1][(j & 1) * 2 + 1] = packe(e2, e3);
        }

#pragma unroll
        for (int kk = 0; kk < 4; kk++) {
#pragma unroll
            for (int np = 0; np < 4; np++) {
                uint32_t vb[4];
                uint32_t ad = vS + (kk * 16 + ((lane >> 3) & 1) * 8 + (lane & 7)) * AT_ROWB
                            + (np * 16 + (lane >> 4) * 8) * 2;
                ldsm4t(vb, ad);
                mma16816(oacc[np * 2 + 0], pf[kk], vb + 0);
                mma16816(oacc[np * 2 + 1], pf[kk], vb + 2);
            }
        }

        __syncthreads();
        if (kt + 2 < NT) { prefetch(kt + 2, s); CP_COMMIT(); }
    }

    lsum0 += __shfl_xor_sync(0xFFFFFFFFu, lsum0, 1);
    lsum0 += __shfl_xor_sync(0xFFFFFFFFu, lsum0, 2);
    lsum1 += __shfl_xor_sync(0xFFFFFFFFu, lsum1, 1);
    lsum1 += __shfl_xor_sync(0xFFFFFFFFu, lsum1, 2);
    const float inv0 = 1.f / lsum0;
    const float inv1 = 1.f / lsum1;

    size_t o0 = (size_t)(b * T_ + q0 + w * 16 + (lane >> 2)) * C_ + h * D_ + 2 * (lane & 3);
    size_t o1 = o0 + 8 * C_;
#pragma unroll
    for (int nd = 0; nd < 8; nd++) {
        *(__half2*)(Oh + o0 + nd * 8) =
            __floats2half2_rn(oacc[nd][0] * inv0, oacc[nd][1] * inv0);
        *(__half2*)(Oh + o1 + nd * 8) =
            __floats2half2_rn(oacc[nd][2] * inv1, oacc[nd][3] * inv1);
    }
}

// ===========================================================================
extern "C" void kernel_launch(void* const* d_in, const int* in_sizes, int n_in,
                              void* d_out, int out_size)
{
    const float* x    = (const float*)d_in[0];
    const int*   mask = (const int*)  d_in[1];
    const float* Wq   = (const float*)d_in[2];
    const float* Wk   = (const float*)d_in[3];
    const float* Wv   = (const float*)d_in[4];
    const float* Wo   = (const float*)d_in[5];
    float* out = (float*)d_out;

    __half *Qh, *Kh, *Vh, *xh, *wh, *Oh;
    cudaGetSymbolAddress((void**)&Qh, g_Qh);
    cudaGetSymbolAddress((void**)&Kh, g_Kh);
    cudaGetSymbolAddress((void**)&Vh, g_Vh);
    cudaGetSymbolAddress((void**)&xh, g_xh);
    cudaGetSymbolAddress((void**)&wh, g_wh);
    cudaGetSymbolAddress((void**)&Oh, g_Oh);

    cudaFuncSetAttribute((const void*)gemm_fp16<true>,
                         cudaFuncAttributeMaxDynamicSharedMemorySize, G_SMEM);
    cudaFuncSetAttribute((const void*)gemm_fp16<false>,
                         cudaFuncAttributeMaxDynamicSharedMemorySize, G_SMEM);
    cudaFuncSetAttribute(attn_reg, cudaFuncAttributeMaxDynamicSharedMemorySize, ATT2_SMEM);

    const int WN = C_ * C_;          // 1048576
    tofp16<<<M_ * C_ / 1024, 256>>>(x, xh, M_ * C_);
    dim3 gw(WN / 1024, 4);
    tofp16_w<<<gw, 256>>>(Wq, Wk, Wv, Wo, wh);

    mask_flags<<<B_ * 16 * 32, 256>>>(mask);

    dim3 gq(C_ / 128, M_ / 128, 3);   // fused QKV, single-pass fp16
    gemm_fp16<true><<<gq, 128, G_SMEM>>>(xh, wh, Qh, Kh, Vh, M_, C_, C_);

    dim3 ga(T_ / 64, B_ * H_);        // (32, 64)
    attn_reg<<<ga, 128, ATT2_SMEM>>>(Qh, Kh, Vh, mask, Oh);

    dim3 go(C_ / 128, M_ / 128, 1);   // out-proj, single-pass fp16
    gemm_fp16<false><<<go, 128, G_SMEM>>>(Oh, wh + 3 * (size_t)WN,
                                          out, out, out, M_, C_, C_);
}

// round 9
// speedup vs baseline: 9.8065x; 1.0246x over previous
#include <cuda_runtime.h>
#include <cuda_fp16.h>
#include <cstdint>
#include <math.h>

// Problem constants
#define B_  4
#define T_  2048
#define C_  1024
#define H_  16
#define D_  64
#define M_  (B_*T_)   // 8192

// Scratch (allocation-free rule: __device__ globals)
__device__ __half g_Qh[M_ * C_];
__device__ __half g_Kh[M_ * C_];
__device__ __half g_Vh[M_ * C_];
__device__ __half g_xh[M_ * C_];
__device__ __half g_wh[4 * C_ * C_];
__device__ __half g_Oh[M_ * C_];
__device__ int    g_mflag[B_ * 16 * 32];

// ---------------------------------------------------------------------------
// Common PTX helpers
// ---------------------------------------------------------------------------
__device__ __forceinline__ uint32_t smem_u32a(const void* p){
    uint32_t a;
    asm("{ .reg .u64 t; cvta.to.shared.u64 t, %1; cvt.u32.u64 %0, t; }" : "=r"(a) : "l"(p));
    return a;
}
__device__ __forceinline__ void mma16816(float* d, const uint32_t* a, const uint32_t* b){
    asm volatile("mma.sync.aligned.m16n8k16.row.col.f32.f16.f16.f32 "
        "{%0,%1,%2,%3}, {%4,%5,%6,%7}, {%8,%9}, {%0,%1,%2,%3};"
        : "+f"(d[0]), "+f"(d[1]), "+f"(d[2]), "+f"(d[3])
        : "r"(a[0]), "r"(a[1]), "r"(a[2]), "r"(a[3]), "r"(b[0]), "r"(b[1]));
}
__device__ __forceinline__ void ldsm4(uint32_t* r, uint32_t addr){
    asm volatile("ldmatrix.sync.aligned.m8n8.x4.shared.b16 {%0,%1,%2,%3}, [%4];"
        : "=r"(r[0]), "=r"(r[1]), "=r"(r[2]), "=r"(r[3]) : "r"(addr));
}
__device__ __forceinline__ void ldsm4t(uint32_t* r, uint32_t addr){
    asm volatile("ldmatrix.sync.aligned.m8n8.x4.trans.shared.b16 {%0,%1,%2,%3}, [%4];"
        : "=r"(r[0]), "=r"(r[1]), "=r"(r[2]), "=r"(r[3]) : "r"(addr));
}
__device__ __forceinline__ uint32_t packe(float a, float b){
    __half2 h = __floats2half2_rn(a, b);
    return *(uint32_t*)&h;
}
#define CP16(dst, src) asm volatile("cp.async.cg.shared.global [%0], [%1], 16;" :: "r"(dst), "l"(src))
#define CP_COMMIT()    asm volatile("cp.async.commit_group;")
#define CP_WAIT1()     asm volatile("cp.async.wait_group 1;")

// ---------------------------------------------------------------------------
// Merged fp32 -> fp16 convert: x (8M elems) then 4 weights (1M each)
// ---------------------------------------------------------------------------
#define XN_  (M_*C_)        // 8388608
#define WN_  (C_*C_)        // 1048576
__global__ __launch_bounds__(256) void convert_all(const float* __restrict__ x,
                                                   const float* __restrict__ w0,
                                                   const float* __restrict__ w1,
                                                   const float* __restrict__ w2,
                                                   const float* __restrict__ w3,
                                                   __half* __restrict__ xh,
                                                   __half* __restrict__ wh)
{
    long i = ((long)blockIdx.x * 256 + threadIdx.x) * 4;
    const float* src;
    __half* dst;
    if (i < XN_) { src = x + i; dst = xh + i; }
    else {
        long j = i - XN_;
        int z = (int)(j >> 20);
        const float* w = z == 0 ? w0 : (z == 1 ? w1 : (z == 2 ? w2 : w3));
        src = w + (j & (WN_ - 1));
        dst = wh + j;
    }
    float4 v = *(const float4*)src;
    ((__half2*)dst)[0] = __floats2half2_rn(v.x, v.y);
    ((__half2*)dst)[1] = __floats2half2_rn(v.z, v.w);
}

// ---------------------------------------------------------------------------
// Mask pre-scan: flag[b][qb][kb] = 1 iff mask[b, qb*128:+128, kb*64:+64] all != 0
// ---------------------------------------------------------------------------
__global__ __launch_bounds__(256) void mask_flags(const int* __restrict__ mask)
{
    __shared__ int s_zero;
    const int t = threadIdx.x;
    if (t == 0) s_zero = 0;
    __syncthreads();
    const int fid = blockIdx.x;
    const int b  = fid >> 9;
    const int qb = (fid >> 5) & 15;
    const int kb = fid & 31;
    const int* base = mask + ((size_t)b * T_ + qb * 128) * T_ + kb * 64;
    const int r = t >> 1, hh = t & 1;
    const int4* p = (const int4*)(base + (size_t)r * T_ + hh * 32);
    bool ok = true;
#pragma unroll
    for (int i = 0; i < 8; i++) {
        int4 v = p[i];
        ok = ok && (v.x != 0) && (v.y != 0) && (v.z != 0) && (v.w != 0);
    }
    if (!ok) s_zero = 1;
    __syncthreads();
    if (t == 0) g_mflag[fid] = s_zero ? 0 : 1;
}

// ===========================================================================
// GEMM: C[m,n] = sum_k A[m,k]*W[n,k], single-pass fp16 mma.
// CTA 128x128, BK=64, 3-stage cp.async (96KB -> 2 CTAs/SM), 128 threads,
// 4 warps with 64x64 tiles. blockIdx.z selects weight slice + output.
// ===========================================================================
#define TILE16 16384                  // 128 rows x 128 bytes (64 fp16 cols)
#define NSTG   3
#define STAGE_B (2*TILE16)            // A | B
#define G_SMEM (NSTG*STAGE_B)         // 98304

template<bool HALF_OUT>
__global__ __launch_bounds__(128, 2) void gemm_fp16(
    const __half* __restrict__ Ag,
    const __half* __restrict__ Bg,
    void* __restrict__ C0, void* __restrict__ C1, void* __restrict__ C2,
    int M, int N, int K)
{
    extern __shared__ char smem_raw[];
    const uint32_t sb = smem_u32a(smem_raw);

    const int z = blockIdx.z;
    const __half* Bz = Bg + (size_t)z * N * K;
    void* Cout = z == 0 ? C0 : (z == 1 ? C1 : C2);

    const int tid  = threadIdx.x;
    const int w    = tid >> 5;
    const int lane = tid & 31;
    const int wm   = w >> 1;          // 0..1
    const int wn   = w & 1;           // 0..1
    const int m0   = blockIdx.y * 128;
    const int n0   = blockIdx.x * 128;

    auto prefetch = [&](int t, int s){
        uint32_t st = sb + s * STAGE_B;
        int k0 = t * 64;
#pragma unroll
        for (int i = 0; i < 8; i++) {
            int id = i * 128 + tid;          // 0..1023
            int r = id >> 3, c = id & 7;
            uint32_t dsw = (uint32_t)(r * 128 + ((c ^ (r & 7)) << 4));
            CP16(st + dsw,          Ag + (size_t)(m0 + r) * K + k0 + c * 8);
            CP16(st + TILE16 + dsw, Bz + (size_t)(n0 + r) * K + k0 + c * 8);
        }
    };

    prefetch(0, 0); CP_COMMIT();
    prefetch(1, 1); CP_COMMIT();

    float acc[4][8][4];
#pragma unroll
    for (int mi = 0; mi < 4; mi++)
#pragma unroll
        for (int nb = 0; nb < 8; nb++)
#pragma unroll
            for (int j = 0; j < 4; j++) acc[mi][nb][j] = 0.f;

    const int NT = K / 64;            // 16
    for (int t = 0; t < NT; t++) {
        CP_WAIT1();
        __syncthreads();
        if (t + 2 < NT) prefetch(t + 2, (t + 2) % NSTG);
        CP_COMMIT();                  // uniform group accounting

        const uint32_t aB = sb + (t % NSTG) * STAGE_B;
        const uint32_t bB = aB + TILE16;

#pragma unroll
        for (int kp = 0; kp < 2; kp++) {
            uint32_t bhf[8][4];
#pragma unroll
            for (int nb = 0; nb < 8; nb++) {
                int r = wn * 64 + nb * 8 + (lane & 7);
                int c = kp * 4 + (lane >> 3);
                ldsm4(bhf[nb], bB + (uint32_t)(r * 128 + ((c ^ (r & 7)) << 4)));
            }
#pragma unroll
            for (int k2 = 0; k2 < 2; k2++) {
                const int kk = kp * 2 + k2;
                uint32_t ahf[4][4];
#pragma unroll
                for (int mi = 0; mi < 4; mi++) {
                    int r = wm * 64 + mi * 16 + (lane & 15);
                    int c = kk * 2 + (lane >> 4);
                    ldsm4(ahf[mi], aB + (uint32_t)(r * 128 + ((c ^ (r & 7)) << 4)));
                }
#pragma unroll
                for (int mi = 0; mi < 4; mi++)
#pragma unroll
                    for (int nb = 0; nb < 8; nb++)
                        mma16816(acc[mi][nb], ahf[mi], bhf[nb] + k2 * 2);
            }
        }
    }

    // Epilogue: direct register -> global
#pragma unroll
    for (int mi = 0; mi < 4; mi++) {
        int r0 = m0 + wm * 64 + mi * 16 + (lane >> 2);
#pragma unroll
        for (int nb = 0; nb < 8; nb++) {
            int col = n0 + wn * 64 + nb * 8 + (lane & 3) * 2;
            if (HALF_OUT) {
                __half* Ch = (__half*)Cout;
                *(__half2*)(Ch + (size_t)r0 * N + col) =
                    __floats2half2_rn(acc[mi][nb][0], acc[mi][nb][1]);
                *(__half2*)(Ch + (size_t)(r0 + 8) * N + col) =
                    __floats2half2_rn(acc[mi][nb][2], acc[mi][nb][3]);
            } else {
                float* Cf = (float*)Cout;
                *(float2*)(Cf + (size_t)r0 * N + col) =
                    make_float2(acc[mi][nb][0], acc[mi][nb][1]);
                *(float2*)(Cf + (size_t)(r0 + 8) * N + col) =
                    make_float2(acc[mi][nb][2], acc[mi][nb][3]);
            }
        }
    }
}

// ===========================================================================
// Register-resident flash attention (raw mma, fp16), fp16 output.
// CTA = (b,h) x 128 q-rows, 128 threads (4 warps x 32 q-rows = 2 m-blocks),
// 3-stage KV pipeline, single sync per tile, 2 CTAs/SM.
// ===========================================================================
#define AT_ROWB 144                   // 72 halves per row
#define OFF_Q   0
#define Q_BYTES (128*AT_ROWB)         // 18432
#define OFF_KV  Q_BYTES
#define KV_STG  (64*AT_ROWB*2)        // 18432 (K + V)
#define NKV     3
#define ATT_SMEM (OFF_KV + NKV*KV_STG) // 73728

__global__ __launch_bounds__(128, 2) void attn_reg(const __half* __restrict__ Q,
                                                   const __half* __restrict__ K,
                                                   const __half* __restrict__ V,
                                                   const int*    __restrict__ mask,
                                                   __half* __restrict__ Oh)
{
    extern __shared__ char smem_raw[];
    const uint32_t sb = smem_u32a(smem_raw);

    const int tid  = threadIdx.x;
    const int w    = tid >> 5;
    const int lane = tid & 31;
    const int b    = blockIdx.y >> 4;
    const int h    = blockIdx.y & 15;
    const int q0   = blockIdx.x * 128;

    auto prefetch = [&](int kt, int s){
        uint32_t kbase = sb + OFF_KV + s * KV_STG;
        uint32_t vbase = kbase + 64 * AT_ROWB;
        const __half* Kg = K + (size_t)(b * T_ + kt * 64) * C_ + h * D_;
        const __half* Vg = V + (size_t)(b * T_ + kt * 64) * C_ + h * D_;
#pragma unroll
        for (int i = 0; i < 4; i++) {
            int cid = i * 128 + tid;         // 0..511
            int r = cid >> 3, c = cid & 7;
            CP16(kbase + r * AT_ROWB + c * 16, Kg + (size_t)r * C_ + c * 8);
            CP16(vbase + r * AT_ROWB + c * 16, Vg + (size_t)r * C_ + c * 8);
        }
    };

    prefetch(0, 0); CP_COMMIT();
    prefetch(1, 1); CP_COMMIT();

    // Q tile: 128 rows
#pragma unroll
    for (int i = 0; i < 8; i++) {
        int cid = i * 128 + tid;             // 0..1023
        int r = cid >> 3, c = cid & 7;
        *(uint4*)(smem_raw + OFF_Q + r * AT_ROWB + c * 16) =
            *(const uint4*)(Q + (size_t)(b * T_ + q0 + r) * C_ + h * D_ + c * 8);
    }
    __syncthreads();

    uint32_t qf[2][4][4];                    // 2 m-blocks x 4 kd
#pragma unroll
    for (int m = 0; m < 2; m++)
#pragma unroll
        for (int kd = 0; kd < 4; kd++) {
            uint32_t aq = sb + OFF_Q + (w * 32 + m * 16 + (lane & 15)) * AT_ROWB
                        + (kd * 16 + (lane >> 4) * 8) * 2;
            ldsm4(qf[m][kd], aq);
        }

    float oacc[2][8][4];
#pragma unroll
    for (int m = 0; m < 2; m++)
#pragma unroll
        for (int i = 0; i < 8; i++)
#pragma unroll
            for (int j = 0; j < 4; j++) oacc[m][i][j] = 0.f;
    float lsum[2][2] = {{0.f, 0.f}, {0.f, 0.f}};

    const int NT = T_ / 64;  // 32
    for (int kt = 0; kt < NT; kt++) {
        CP_WAIT1();
        __syncthreads();                     // all warps done with stage (kt-1)%3
        if (kt + 2 < NT) prefetch(kt + 2, (kt + 2) % NKV);
        CP_COMMIT();

        const uint32_t kS = sb + OFF_KV + (kt % NKV) * KV_STG;
        const uint32_t vS = kS + 64 * AT_ROWB;
        const int flag = g_mflag[(b * 16 + blockIdx.x) * 32 + kt];

        uint32_t pf[2][4][4];
        // ---- S = Q K^T, softmax, pack P fragments ----
#pragma unroll
        for (int j = 0; j < 8; j++) {
            uint32_t kb0[4], kb1[4];
            uint32_t a0 = kS + (j * 8 + (lane & 7)) * AT_ROWB + (lane >> 3) * 16;
            ldsm4(kb0, a0);
            ldsm4(kb1, a0 + 64);
#pragma unroll
            for (int m = 0; m < 2; m++) {
                float sj[4] = {0.f, 0.f, 0.f, 0.f};
                mma16816(sj, qf[m][0], kb0 + 0);
                mma16816(sj, qf[m][1], kb0 + 2);
                mma16816(sj, qf[m][2], kb1 + 0);
                mma16816(sj, qf[m][3], kb1 + 2);

                float e0 = __expf(sj[0] * 0.125f);
                float e1 = __expf(sj[1] * 0.125f);
                float e2 = __expf(sj[2] * 0.125f);
                float e3 = __expf(sj[3] * 0.125f);
                if (!flag) {
                    const int* mp = mask
                        + ((size_t)b * T_ + q0 + w * 32 + m * 16 + (lane >> 2)) * T_
                        + kt * 64 + j * 8 + 2 * (lane & 3);
                    int2 m0v = *(const int2*)mp;
                    int2 m1v = *(const int2*)(mp + 8 * T_);
                    if (m0v.x == 0) e0 = 0.f;
                    if (m0v.y == 0) e1 = 0.f;
                    if (m1v.x == 0) e2 = 0.f;
                    if (m1v.y == 0) e3 = 0.f;
                }
                lsum[m][0] += e0 + e1;
                lsum[m][1] += e2 + e3;
                pf[m][j >> 1][(j & 1) * 2 + 0] = packe(e0, e1);
                pf[m][j >> 1][(j & 1) * 2 + 1] = packe(e2, e3);
            }
        }

        // ---- O += P V ----
#pragma unroll
        for (int kk = 0; kk < 4; kk++) {
#pragma unroll
            for (int np = 0; np < 4; np++) {
                uint32_t vb[4];
                uint32_t ad = vS + (kk * 16 + ((lane >> 3) & 1) * 8 + (lane & 7)) * AT_ROWB
                            + (np * 16 + (lane >> 4) * 8) * 2;
                ldsm4t(vb, ad);
#pragma unroll
                for (int m = 0; m < 2; m++) {
                    mma16816(oacc[m][np * 2 + 0], pf[m][kk], vb + 0);
                    mma16816(oacc[m][np * 2 + 1], pf[m][kk], vb + 2);
                }
            }
        }
    }

    // ---- normalize and write ----
#pragma unroll
    for (int m = 0; m < 2; m++) {
        float l0 = lsum[m][0], l1 = lsum[m][1];
        l0 += __shfl_xor_sync(0xFFFFFFFFu, l0, 1);
        l0 += __shfl_xor_sync(0xFFFFFFFFu, l0, 2);
        l1 += __shfl_xor_sync(0xFFFFFFFFu, l1, 1);
        l1 += __shfl_xor_sync(0xFFFFFFFFu, l1, 2);
        const float inv0 = 1.f / l0;
        const float inv1 = 1.f / l1;

        size_t o0 = (size_t)(b * T_ + q0 + w * 32 + m * 16 + (lane >> 2)) * C_
                  + h * D_ + 2 * (lane & 3);
        size_t o1 = o0 + 8 * C_;
#pragma unroll
        for (int nd = 0; nd < 8; nd++) {
            *(__half2*)(Oh + o0 + nd * 8) =
                __floats2half2_rn(oacc[m][nd][0] * inv0, oacc[m][nd][1] * inv0);
            *(__half2*)(Oh + o1 + nd * 8) =
                __floats2half2_rn(oacc[m][nd][2] * inv1, oacc[m][nd][3] * inv1);
        }
    }
}

// ===========================================================================
extern "C" void kernel_launch(void* const* d_in, const int* in_sizes, int n_in,
                              void* d_out, int out_size)
{
    const float* x    = (const float*)d_in[0];
    const int*   mask = (const int*)  d_in[1];
    const float* Wq   = (const float*)d_in[2];
    const float* Wk   = (const float*)d_in[3];
    const float* Wv   = (const float*)d_in[4];
    const float* Wo   = (const float*)d_in[5];
    float* out = (float*)d_out;

    __half *Qh, *Kh, *Vh, *xh, *wh, *Oh;
    cudaGetSymbolAddress((void**)&Qh, g_Qh);
    cudaGetSymbolAddress((void**)&Kh, g_Kh);
    cudaGetSymbolAddress((void**)&Vh, g_Vh);
    cudaGetSymbolAddress((void**)&xh, g_xh);
    cudaGetSymbolAddress((void**)&wh, g_wh);
    cudaGetSymbolAddress((void**)&Oh, g_Oh);

    cudaFuncSetAttribute((const void*)gemm_fp16<true>,
                         cudaFuncAttributeMaxDynamicSharedMemorySize, G_SMEM);
    cudaFuncSetAttribute((const void*)gemm_fp16<false>,
                         cudaFuncAttributeMaxDynamicSharedMemorySize, G_SMEM);
    cudaFuncSetAttribute(attn_reg, cudaFuncAttributeMaxDynamicSharedMemorySize, ATT_SMEM);

    convert_all<<<(XN_ + 4 * WN_) / 1024, 256>>>(x, Wq, Wk, Wv, Wo, xh, wh);
    mask_flags<<<B_ * 16 * 32, 256>>>(mask);

    dim3 gq(C_ / 128, M_ / 128, 3);   // fused QKV, single-pass fp16
    gemm_fp16<true><<<gq, 128, G_SMEM>>>(xh, wh, Qh, Kh, Vh, M_, C_, C_);

    dim3 ga(T_ / 128, B_ * H_);       // (16, 64)
    attn_reg<<<ga, 128, ATT_SMEM>>>(Qh, Kh, Vh, mask, Oh);

    dim3 go(C_ / 128, M_ / 128, 1);   // out-proj, single-pass fp16
    gemm_fp16<false><<<go, 128, G_SMEM>>>(Oh, wh + 3 * (size_t)WN_,
                                          out, out, out, M_, C_, C_);
}

// round 10
// speedup vs baseline: 10.2431x; 1.0445x over previous
#include <cuda_runtime.h>
#include <cuda_fp16.h>
#include <cstdint>
#include <math.h>

// Problem constants
#define B_  4
#define T_  2048
#define C_  1024
#define H_  16
#define D_  64
#define M_  (B_*T_)   // 8192

// Scratch (allocation-free rule: __device__ globals)
__device__ __half g_Qh[M_ * C_];
__device__ __half g_Kh[M_ * C_];
__device__ __half g_Vh[M_ * C_];
__device__ __half g_xh[M_ * C_];
__device__ __half g_wh[4 * C_ * C_];
__device__ __half g_Oh[M_ * C_];
__device__ int    g_mflag[B_ * 16 * 32];

// ---------------------------------------------------------------------------
// Common PTX helpers
// ---------------------------------------------------------------------------
__device__ __forceinline__ uint32_t smem_u32a(const void* p){
    uint32_t a;
    asm("{ .reg .u64 t; cvta.to.shared.u64 t, %1; cvt.u32.u64 %0, t; }" : "=r"(a) : "l"(p));
    return a;
}
__device__ __forceinline__ void mma16816(float* d, const uint32_t* a, const uint32_t* b){
    asm volatile("mma.sync.aligned.m16n8k16.row.col.f32.f16.f16.f32 "
        "{%0,%1,%2,%3}, {%4,%5,%6,%7}, {%8,%9}, {%0,%1,%2,%3};"
        : "+f"(d[0]), "+f"(d[1]), "+f"(d[2]), "+f"(d[3])
        : "r"(a[0]), "r"(a[1]), "r"(a[2]), "r"(a[3]), "r"(b[0]), "r"(b[1]));
}
__device__ __forceinline__ void ldsm4(uint32_t* r, uint32_t addr){
    asm volatile("ldmatrix.sync.aligned.m8n8.x4.shared.b16 {%0,%1,%2,%3}, [%4];"
        : "=r"(r[0]), "=r"(r[1]), "=r"(r[2]), "=r"(r[3]) : "r"(addr));
}
__device__ __forceinline__ void ldsm4t(uint32_t* r, uint32_t addr){
    asm volatile("ldmatrix.sync.aligned.m8n8.x4.trans.shared.b16 {%0,%1,%2,%3}, [%4];"
        : "=r"(r[0]), "=r"(r[1]), "=r"(r[2]), "=r"(r[3]) : "r"(addr));
}
__device__ __forceinline__ uint32_t packe(float a, float b){
    __half2 h = __floats2half2_rn(a, b);
    return *(uint32_t*)&h;
}
__device__ __forceinline__ float ex2f(float x){
    float y;
    asm("ex2.approx.f32 %0, %1;" : "=f"(y) : "f"(x));
    return y;
}
#define CP16(dst, src) asm volatile("cp.async.cg.shared.global [%0], [%1], 16;" :: "r"(dst), "l"(src))
#define CP_COMMIT()    asm volatile("cp.async.commit_group;")
#define CP_WAIT1()     asm volatile("cp.async.wait_group 1;")

// ---------------------------------------------------------------------------
// Merged fp32 -> fp16 convert: x (8M elems) then 4 weights (1M each)
// ---------------------------------------------------------------------------
#define XN_  (M_*C_)        // 8388608
#define WN_  (C_*C_)        // 1048576
__global__ __launch_bounds__(256) void convert_all(const float* __restrict__ x,
                                                   const float* __restrict__ w0,
                                                   const float* __restrict__ w1,
                                                   const float* __restrict__ w2,
                                                   const float* __restrict__ w3,
                                                   __half* __restrict__ xh,
                                                   __half* __restrict__ wh)
{
    long i = ((long)blockIdx.x * 256 + threadIdx.x) * 4;
    const float* src;
    __half* dst;
    if (i < XN_) { src = x + i; dst = xh + i; }
    else {
        long j = i - XN_;
        int z = (int)(j >> 20);
        const float* w = z == 0 ? w0 : (z == 1 ? w1 : (z == 2 ? w2 : w3));
        src = w + (j & (WN_ - 1));
        dst = wh + j;
    }
    float4 v = *(const float4*)src;
    ((__half2*)dst)[0] = __floats2half2_rn(v.x, v.y);
    ((__half2*)dst)[1] = __floats2half2_rn(v.z, v.w);
}

// ---------------------------------------------------------------------------
// Mask pre-scan: flag[b][qb][kb] = 1 iff mask[b, qb*128:+128, kb*64:+64] all != 0
// ---------------------------------------------------------------------------
__global__ __launch_bounds__(256) void mask_flags(const int* __restrict__ mask)
{
    __shared__ int s_zero;
    const int t = threadIdx.x;
    if (t == 0) s_zero = 0;
    __syncthreads();
    const int fid = blockIdx.x;
    const int b  = fid >> 9;
    const int qb = (fid >> 5) & 15;
    const int kb = fid & 31;
    const int* base = mask + ((size_t)b * T_ + qb * 128) * T_ + kb * 64;
    const int r = t >> 1, hh = t & 1;
    const int4* p = (const int4*)(base + (size_t)r * T_ + hh * 32);
    bool ok = true;
#pragma unroll
    for (int i = 0; i < 8; i++) {
        int4 v = p[i];
        ok = ok && (v.x != 0) && (v.y != 0) && (v.z != 0) && (v.w != 0);
    }
    if (!ok) s_zero = 1;
    __syncthreads();
    if (t == 0) g_mflag[fid] = s_zero ? 0 : 1;
}

// ===========================================================================
// GEMM: C[m,n] = sum_k A[m,k]*W[n,k], single-pass fp16 mma.
// CTA 128x128, BK=64, 3-stage cp.async (96KB -> 2 CTAs/SM), 128 threads,
// 4 warps with 64x64 tiles. blockIdx.z selects weight slice + output.
// ===========================================================================
#define TILE16 16384                  // 128 rows x 128 bytes (64 fp16 cols)
#define NSTG   3
#define STAGE_B (2*TILE16)            // A | B
#define G_SMEM (NSTG*STAGE_B)         // 98304

template<bool HALF_OUT>
__global__ __launch_bounds__(128, 2) void gemm_fp16(
    const __half* __restrict__ Ag,
    const __half* __restrict__ Bg,
    void* __restrict__ C0, void* __restrict__ C1, void* __restrict__ C2,
    int M, int N, int K)
{
    extern __shared__ char smem_raw[];
    const uint32_t sb = smem_u32a(smem_raw);

    const int z = blockIdx.z;
    const __half* Bz = Bg + (size_t)z * N * K;
    void* Cout = z == 0 ? C0 : (z == 1 ? C1 : C2);

    const int tid  = threadIdx.x;
    const int w    = tid >> 5;
    const int lane = tid & 31;
    const int wm   = w >> 1;          // 0..1
    const int wn   = w & 1;           // 0..1
    const int m0   = blockIdx.y * 128;
    const int n0   = blockIdx.x * 128;

    auto prefetch = [&](int t, int s){
        uint32_t st = sb + s * STAGE_B;
        int k0 = t * 64;
#pragma unroll
        for (int i = 0; i < 8; i++) {
            int id = i * 128 + tid;          // 0..1023
            int r = id >> 3, c = id & 7;
            uint32_t dsw = (uint32_t)(r * 128 + ((c ^ (r & 7)) << 4));
            CP16(st + dsw,          Ag + (size_t)(m0 + r) * K + k0 + c * 8);
            CP16(st + TILE16 + dsw, Bz + (size_t)(n0 + r) * K + k0 + c * 8);
        }
    };

    prefetch(0, 0); CP_COMMIT();
    prefetch(1, 1); CP_COMMIT();

    float acc[4][8][4];
#pragma unroll
    for (int mi = 0; mi < 4; mi++)
#pragma unroll
        for (int nb = 0; nb < 8; nb++)
#pragma unroll
            for (int j = 0; j < 4; j++) acc[mi][nb][j] = 0.f;

    const int NT = K / 64;            // 16
    for (int t = 0; t < NT; t++) {
        CP_WAIT1();
        __syncthreads();
        if (t + 2 < NT) prefetch(t + 2, (t + 2) % NSTG);
        CP_COMMIT();                  // uniform group accounting

        const uint32_t aB = sb + (t % NSTG) * STAGE_B;
        const uint32_t bB = aB + TILE16;

#pragma unroll
        for (int kp = 0; kp < 2; kp++) {
            uint32_t bhf[8][4];
#pragma unroll
            for (int nb = 0; nb < 8; nb++) {
                int r = wn * 64 + nb * 8 + (lane & 7);
                int c = kp * 4 + (lane >> 3);
                ldsm4(bhf[nb], bB + (uint32_t)(r * 128 + ((c ^ (r & 7)) << 4)));
            }
#pragma unroll
            for (int k2 = 0; k2 < 2; k2++) {
                const int kk = kp * 2 + k2;
                uint32_t ahf[4][4];
#pragma unroll
                for (int mi = 0; mi < 4; mi++) {
                    int r = wm * 64 + mi * 16 + (lane & 15);
                    int c = kk * 2 + (lane >> 4);
                    ldsm4(ahf[mi], aB + (uint32_t)(r * 128 + ((c ^ (r & 7)) << 4)));
                }
#pragma unroll
                for (int mi = 0; mi < 4; mi++)
#pragma unroll
                    for (int nb = 0; nb < 8; nb++)
                        mma16816(acc[mi][nb], ahf[mi], bhf[nb] + k2 * 2);
            }
        }
    }

    // Epilogue: direct register -> global
#pragma unroll
    for (int mi = 0; mi < 4; mi++) {
        int r0 = m0 + wm * 64 + mi * 16 + (lane >> 2);
#pragma unroll
        for (int nb = 0; nb < 8; nb++) {
            int col = n0 + wn * 64 + nb * 8 + (lane & 3) * 2;
            if (HALF_OUT) {
                __half* Ch = (__half*)Cout;
                *(__half2*)(Ch + (size_t)r0 * N + col) =
                    __floats2half2_rn(acc[mi][nb][0], acc[mi][nb][1]);
                *(__half2*)(Ch + (size_t)(r0 + 8) * N + col) =
                    __floats2half2_rn(acc[mi][nb][2], acc[mi][nb][3]);
            } else {
                float* Cf = (float*)Cout;
                *(float2*)(Cf + (size_t)r0 * N + col) =
                    make_float2(acc[mi][nb][0], acc[mi][nb][1]);
                *(float2*)(Cf + (size_t)(r0 + 8) * N + col) =
                    make_float2(acc[mi][nb][2], acc[mi][nb][3]);
            }
        }
    }
}

// ===========================================================================
// Register-resident flash attention (raw mma, fp16), fp16 output.
// CTA = (b,h) x 128 q-rows, 128 threads (4 warps x 32 q-rows = 2 m-blocks),
// 3-stage KV pipeline, one sync/tile, 2 CTAs/SM.
// Row sums via ones-MMA (l = P.1); exp via ex2.approx with folded constant.
// ===========================================================================
#define AT_ROWB 144                   // 72 halves per row
#define OFF_Q   0
#define Q_BYTES (128*AT_ROWB)         // 18432
#define OFF_KV  Q_BYTES
#define KV_STG  (64*AT_ROWB*2)        // 18432 (K + V)
#define NKV     3
#define ATT_SMEM (OFF_KV + NKV*KV_STG) // 73728

__global__ __launch_bounds__(128, 2) void attn_reg(const __half* __restrict__ Q,
                                                   const __half* __restrict__ K,
                                                   const __half* __restrict__ V,
                                                   const int*    __restrict__ mask,
                                                   __half* __restrict__ Oh)
{
    extern __shared__ char smem_raw[];
    const uint32_t sb = smem_u32a(smem_raw);

    const int tid  = threadIdx.x;
    const int w    = tid >> 5;
    const int lane = tid & 31;
    const int b    = blockIdx.y >> 4;
    const int h    = blockIdx.y & 15;
    const int q0   = blockIdx.x * 128;

    // ---- per-thread prefetch bases (advance by 64*C_ per tile) ----
    const int pr = tid >> 3;                 // 0..15
    const int pc = tid & 7;                  // 0..7
    const __half* kg = K + ((size_t)(b * T_) + pr) * C_ + h * D_ + pc * 8;
    const __half* vg = V + ((size_t)(b * T_) + pr) * C_ + h * D_ + pc * 8;
    const uint32_t soff = (uint32_t)(pr * AT_ROWB + pc * 16);
    const uint32_t stg[NKV] = { sb + OFF_KV, sb + OFF_KV + KV_STG, sb + OFF_KV + 2 * KV_STG };

    auto prefetch = [&](const __half* kp, const __half* vp, uint32_t sbase){
#pragma unroll
        for (int i = 0; i < 4; i++) {
            CP16(sbase + soff + i * 16 * AT_ROWB,                 kp + (size_t)i * 16 * C_);
            CP16(sbase + 64 * AT_ROWB + soff + i * 16 * AT_ROWB,  vp + (size_t)i * 16 * C_);
        }
    };

    prefetch(kg, vg, stg[0]); CP_COMMIT();
    prefetch(kg + 64 * C_, vg + 64 * C_, stg[1]); CP_COMMIT();
    const __half* kgn = kg + 128 * C_;
    const __half* vgn = vg + 128 * C_;

    // ---- Q tile: 128 rows ----
#pragma unroll
    for (int i = 0; i < 8; i++) {
        int cid = i * 128 + tid;             // 0..1023
        int r = cid >> 3, c = cid & 7;
        *(uint4*)(smem_raw + OFF_Q + r * AT_ROWB + c * 16) =
            *(const uint4*)(Q + (size_t)(b * T_ + q0 + r) * C_ + h * D_ + c * 8);
    }
    __syncthreads();

    uint32_t qf[2][4][4];                    // 2 m-blocks x 4 kd
#pragma unroll
    for (int m = 0; m < 2; m++)
#pragma unroll
        for (int kd = 0; kd < 4; kd++) {
            uint32_t aq = sb + OFF_Q + (w * 32 + m * 16 + (lane & 15)) * AT_ROWB
                        + (kd * 16 + (lane >> 4) * 8) * 2;
            ldsm4(qf[m][kd], aq);
        }

    float oacc[2][8][4];
#pragma unroll
    for (int m = 0; m < 2; m++)
#pragma unroll
        for (int i = 0; i < 8; i++)
#pragma unroll
            for (int j = 0; j < 4; j++) oacc[m][i][j] = 0.f;
    float lacc[2][4];                        // row sums via ones-mma
#pragma unroll
    for (int m = 0; m < 2; m++)
#pragma unroll
        for (int j = 0; j < 4; j++) lacc[m][j] = 0.f;

    const uint32_t bones[2] = { 0x3C003C00u, 0x3C003C00u };   // fp16 1.0 x4
    const float CEXP = 0.125f * 1.44269504f;                  // scale * log2(e)
    const int* mflag_p = g_mflag + (b * 16 + blockIdx.x) * 32;

    int s_cur = 0, s_pf = 2;
    const int NT = T_ / 64;  // 32
    for (int kt = 0; kt < NT; kt++) {
        CP_WAIT1();
        __syncthreads();                     // all warps done with prefetch-target stage
        if (kt + 2 < NT) {
            prefetch(kgn, vgn, stg[s_pf]);
            kgn += 64 * C_; vgn += 64 * C_;
        }
        CP_COMMIT();

        const uint32_t kS = stg[s_cur];
        const uint32_t vS = kS + 64 * AT_ROWB;
        const int flag = mflag_p[kt];
        s_cur = (s_cur == 2) ? 0 : s_cur + 1;
        s_pf  = (s_pf  == 2) ? 0 : s_pf  + 1;

        uint32_t pf[2][4][4];
        // ---- S = Q K^T, exp, pack P fragments ----
#pragma unroll
        for (int j = 0; j < 8; j++) {
            uint32_t kb0[4], kb1[4];
            uint32_t a0 = kS + (j * 8 + (lane & 7)) * AT_ROWB + (lane >> 3) * 16;
            ldsm4(kb0, a0);
            ldsm4(kb1, a0 + 64);
#pragma unroll
            for (int m = 0; m < 2; m++) {
                float sj[4] = {0.f, 0.f, 0.f, 0.f};
                mma16816(sj, qf[m][0], kb0 + 0);
                mma16816(sj, qf[m][1], kb0 + 2);
                mma16816(sj, qf[m][2], kb1 + 0);
                mma16816(sj, qf[m][3], kb1 + 2);

                float e0 = ex2f(sj[0] * CEXP);
                float e1 = ex2f(sj[1] * CEXP);
                float e2 = ex2f(sj[2] * CEXP);
                float e3 = ex2f(sj[3] * CEXP);
                if (!flag) {
                    const int* mp = mask
                        + ((size_t)b * T_ + q0 + w * 32 + m * 16 + (lane >> 2)) * T_
                        + kt * 64 + j * 8 + 2 * (lane & 3);
                    int2 m0v = *(const int2*)mp;
                    int2 m1v = *(const int2*)(mp + 8 * T_);
                    if (m0v.x == 0) e0 = 0.f;
                    if (m0v.y == 0) e1 = 0.f;
                    if (m1v.x == 0) e2 = 0.f;
                    if (m1v.y == 0) e3 = 0.f;
                }
                pf[m][j >> 1][(j & 1) * 2 + 0] = packe(e0, e1);
                pf[m][j >> 1][(j & 1) * 2 + 1] = packe(e2, e3);
            }
        }

        // ---- O += P V ; l += P 1 ----
#pragma unroll
        for (int kk = 0; kk < 4; kk++) {
#pragma unroll
            for (int np = 0; np < 4; np++) {
                uint32_t vb[4];
                uint32_t ad = vS + (kk * 16 + ((lane >> 3) & 1) * 8 + (lane & 7)) * AT_ROWB
                            + (np * 16 + (lane >> 4) * 8) * 2;
                ldsm4t(vb, ad);
#pragma unroll
                for (int m = 0; m < 2; m++) {
                    mma16816(oacc[m][np * 2 + 0], pf[m][kk], vb + 0);
                    mma16816(oacc[m][np * 2 + 1], pf[m][kk], vb + 2);
                }
            }
#pragma unroll
            for (int m = 0; m < 2; m++)
                mma16816(lacc[m], pf[m][kk], bones);
        }
    }

    // ---- normalize and write (row sums replicated across quad lanes) ----
#pragma unroll
    for (int m = 0; m < 2; m++) {
        const float inv0 = 1.f / lacc[m][0];
        const float inv1 = 1.f / lacc[m][2];

        size_t o0 = (size_t)(b * T_ + q0 + w * 32 + m * 16 + (lane >> 2)) * C_
                  + h * D_ + 2 * (lane & 3);
        size_t o1 = o0 + 8 * C_;
#pragma unroll
        for (int nd = 0; nd < 8; nd++) {
            *(__half2*)(Oh + o0 + nd * 8) =
                __floats2half2_rn(oacc[m][nd][0] * inv0, oacc[m][nd][1] * inv0);
            *(__half2*)(Oh + o1 + nd * 8) =
                __floats2half2_rn(oacc[m][nd][2] * inv1, oacc[m][nd][3] * inv1);
        }
    }
}

// ===========================================================================
extern "C" void kernel_launch(void* const* d_in, const int* in_sizes, int n_in,
                              void* d_out, int out_size)
{
    const float* x    = (const float*)d_in[0];
    const int*   mask = (const int*)  d_in[1];
    const float* Wq   = (const float*)d_in[2];
    const float* Wk   = (const float*)d_in[3];
    const float* Wv   = (const float*)d_in[4];
    const float* Wo   = (const float*)d_in[5];
    float* out = (float*)d_out;

    __half *Qh, *Kh, *Vh, *xh, *wh, *Oh;
    cudaGetSymbolAddress((void**)&Qh, g_Qh);
    cudaGetSymbolAddress((void**)&Kh, g_Kh);
    cudaGetSymbolAddress((void**)&Vh, g_Vh);
    cudaGetSymbolAddress((void**)&xh, g_xh);
    cudaGetSymbolAddress((void**)&wh, g_wh);
    cudaGetSymbolAddress((void**)&Oh, g_Oh);

    cudaFuncSetAttribute((const void*)gemm_fp16<true>,
                         cudaFuncAttributeMaxDynamicSharedMemorySize, G_SMEM);
    cudaFuncSetAttribute((const void*)gemm_fp16<false>,
                         cudaFuncAttributeMaxDynamicSharedMemorySize, G_SMEM);
    cudaFuncSetAttribute(attn_reg, cudaFuncAttributeMaxDynamicSharedMemorySize, ATT_SMEM);

    convert_all<<<(XN_ + 4 * WN_) / 1024, 256>>>(x, Wq, Wk, Wv, Wo, xh, wh);
    mask_flags<<<B_ * 16 * 32, 256>>>(mask);

    dim3 gq(C_ / 128, M_ / 128, 3);   // fused QKV, single-pass fp16
    gemm_fp16<true><<<gq, 128, G_SMEM>>>(xh, wh, Qh, Kh, Vh, M_, C_, C_);

    dim3 ga(T_ / 128, B_ * H_);       // (16, 64)
    attn_reg<<<ga, 128, ATT_SMEM>>>(Qh, Kh, Vh, mask, Oh);

    dim3 go(C_ / 128, M_ / 128, 1);   // out-proj, single-pass fp16
    gemm_fp16<false><<<go, 128, G_SMEM>>>(Oh, wh + 3 * (size_t)WN_,
                                          out, out, out, M_, C_, C_);
}

// round 11
// speedup vs baseline: 10.8009x; 1.0545x over previous
#include <cuda_runtime.h>
#include <cuda_fp16.h>
#include <cstdint>
#include <math.h>

// Problem constants
#define B_  4
#define T_  2048
#define C_  1024
#define H_  16
#define D_  64
#define M_  (B_*T_)   // 8192

// Scratch (allocation-free rule: __device__ globals)
__device__ __half g_Qh[M_ * C_];
__device__ __half g_Kh[M_ * C_];
__device__ __half g_Vh[M_ * C_];
__device__ __half g_xh[M_ * C_];
__device__ __half g_wh[4 * C_ * C_];
__device__ __half g_Oh[M_ * C_];
__device__ int    g_mflag[B_ * 16 * 32];

// ---------------------------------------------------------------------------
// Common PTX helpers
// ---------------------------------------------------------------------------
__device__ __forceinline__ uint32_t smem_u32a(const void* p){
    uint32_t a;
    asm("{ .reg .u64 t; cvta.to.shared.u64 t, %1; cvt.u32.u64 %0, t; }" : "=r"(a) : "l"(p));
    return a;
}
__device__ __forceinline__ void mma16816(float* d, const uint32_t* a, const uint32_t* b){
    asm volatile("mma.sync.aligned.m16n8k16.row.col.f32.f16.f16.f32 "
        "{%0,%1,%2,%3}, {%4,%5,%6,%7}, {%8,%9}, {%0,%1,%2,%3};"
        : "+f"(d[0]), "+f"(d[1]), "+f"(d[2]), "+f"(d[3])
        : "r"(a[0]), "r"(a[1]), "r"(a[2]), "r"(a[3]), "r"(b[0]), "r"(b[1]));
}
__device__ __forceinline__ void ldsm4(uint32_t* r, uint32_t addr){
    asm volatile("ldmatrix.sync.aligned.m8n8.x4.shared.b16 {%0,%1,%2,%3}, [%4];"
        : "=r"(r[0]), "=r"(r[1]), "=r"(r[2]), "=r"(r[3]) : "r"(addr));
}
__device__ __forceinline__ void ldsm4t(uint32_t* r, uint32_t addr){
    asm volatile("ldmatrix.sync.aligned.m8n8.x4.trans.shared.b16 {%0,%1,%2,%3}, [%4];"
        : "=r"(r[0]), "=r"(r[1]), "=r"(r[2]), "=r"(r[3]) : "r"(addr));
}
__device__ __forceinline__ uint32_t packe(float a, float b){
    __half2 h = __floats2half2_rn(a, b);
    return *(uint32_t*)&h;
}
__device__ __forceinline__ float ex2f(float x){
    float y;
    asm("ex2.approx.f32 %0, %1;" : "=f"(y) : "f"(x));
    return y;
}
#define CP16(dst, src) asm volatile("cp.async.cg.shared.global [%0], [%1], 16;" :: "r"(dst), "l"(src))
#define CP_COMMIT()    asm volatile("cp.async.commit_group;")
#define CP_WAIT1()     asm volatile("cp.async.wait_group 1;")

// ---------------------------------------------------------------------------
// Merged fp32 -> fp16 convert: x (8M elems) then 4 weights (1M each)
// ---------------------------------------------------------------------------
#define XN_  (M_*C_)        // 8388608
#define WN_  (C_*C_)        // 1048576
__global__ __launch_bounds__(256) void convert_all(const float* __restrict__ x,
                                                   const float* __restrict__ w0,
                                                   const float* __restrict__ w1,
                                                   const float* __restrict__ w2,
                                                   const float* __restrict__ w3,
                                                   __half* __restrict__ xh,
                                                   __half* __restrict__ wh)
{
    long i = ((long)blockIdx.x * 256 + threadIdx.x) * 4;
    const float* src;
    __half* dst;
    if (i < XN_) { src = x + i; dst = xh + i; }
    else {
        long j = i - XN_;
        int z = (int)(j >> 20);
        const float* w = z == 0 ? w0 : (z == 1 ? w1 : (z == 2 ? w2 : w3));
        src = w + (j & (WN_ - 1));
        dst = wh + j;
    }
    float4 v = *(const float4*)src;
    ((__half2*)dst)[0] = __floats2half2_rn(v.x, v.y);
    ((__half2*)dst)[1] = __floats2half2_rn(v.z, v.w);
}

// ---------------------------------------------------------------------------
// Mask pre-scan: flag[b][qb][kb] = 1 iff mask[b, qb*128:+128, kb*64:+64] all != 0
// ---------------------------------------------------------------------------
__global__ __launch_bounds__(256) void mask_flags(const int* __restrict__ mask)
{
    __shared__ int s_zero;
    const int t = threadIdx.x;
    if (t == 0) s_zero = 0;
    __syncthreads();
    const int fid = blockIdx.x;
    const int b  = fid >> 9;
    const int qb = (fid >> 5) & 15;
    const int kb = fid & 31;
    const int* base = mask + ((size_t)b * T_ + qb * 128) * T_ + kb * 64;
    const int r = t >> 1, hh = t & 1;
    const int4* p = (const int4*)(base + (size_t)r * T_ + hh * 32);
    bool ok = true;
#pragma unroll
    for (int i = 0; i < 8; i++) {
        int4 v = p[i];
        ok = ok && (v.x != 0) && (v.y != 0) && (v.z != 0) && (v.w != 0);
    }
    if (!ok) s_zero = 1;
    __syncthreads();
    if (t == 0) g_mflag[fid] = s_zero ? 0 : 1;
}

// ===========================================================================
// GEMM: C[m,n] = sum_k A[m,k]*W[n,k], single-pass fp16 mma.
// CTA 128x128, BK=64, 3-stage cp.async (96KB -> 2 CTAs/SM), 128 threads,
// 4 warps with 64x64 tiles. blockIdx.z selects weight slice + output.
// HALF_OUT path applies a per-slice output scale (softmax scale folded into Q).
// ===========================================================================
#define TILE16 16384                  // 128 rows x 128 bytes (64 fp16 cols)
#define NSTG   3
#define STAGE_B (2*TILE16)            // A | B
#define G_SMEM (NSTG*STAGE_B)         // 98304

#define QSCALE 0.18033688011f         // 0.125 * log2(e)

template<bool HALF_OUT>
__global__ __launch_bounds__(128, 2) void gemm_fp16(
    const __half* __restrict__ Ag,
    const __half* __restrict__ Bg,
    void* __restrict__ C0, void* __restrict__ C1, void* __restrict__ C2,
    int M, int N, int K)
{
    extern __shared__ char smem_raw[];
    const uint32_t sb = smem_u32a(smem_raw);

    const int z = blockIdx.z;
    const __half* Bz = Bg + (size_t)z * N * K;
    void* Cout = z == 0 ? C0 : (z == 1 ? C1 : C2);
    const float oscale = (HALF_OUT && z == 0) ? QSCALE : 1.0f;

    const int tid  = threadIdx.x;
    const int w    = tid >> 5;
    const int lane = tid & 31;
    const int wm   = w >> 1;          // 0..1
    const int wn   = w & 1;           // 0..1
    const int m0   = blockIdx.y * 128;
    const int n0   = blockIdx.x * 128;

    auto prefetch = [&](int t, int s){
        uint32_t st = sb + s * STAGE_B;
        int k0 = t * 64;
#pragma unroll
        for (int i = 0; i < 8; i++) {
            int id = i * 128 + tid;          // 0..1023
            int r = id >> 3, c = id & 7;
            uint32_t dsw = (uint32_t)(r * 128 + ((c ^ (r & 7)) << 4));
            CP16(st + dsw,          Ag + (size_t)(m0 + r) * K + k0 + c * 8);
            CP16(st + TILE16 + dsw, Bz + (size_t)(n0 + r) * K + k0 + c * 8);
        }
    };

    prefetch(0, 0); CP_COMMIT();
    prefetch(1, 1); CP_COMMIT();

    float acc[4][8][4];
#pragma unroll
    for (int mi = 0; mi < 4; mi++)
#pragma unroll
        for (int nb = 0; nb < 8; nb++)
#pragma unroll
            for (int j = 0; j < 4; j++) acc[mi][nb][j] = 0.f;

    const int NT = K / 64;            // 16
    for (int t = 0; t < NT; t++) {
        CP_WAIT1();
        __syncthreads();
        if (t + 2 < NT) prefetch(t + 2, (t + 2) % NSTG);
        CP_COMMIT();                  // uniform group accounting

        const uint32_t aB = sb + (t % NSTG) * STAGE_B;
        const uint32_t bB = aB + TILE16;

#pragma unroll
        for (int kp = 0; kp < 2; kp++) {
            uint32_t bhf[8][4];
#pragma unroll
            for (int nb = 0; nb < 8; nb++) {
                int r = wn * 64 + nb * 8 + (lane & 7);
                int c = kp * 4 + (lane >> 3);
                ldsm4(bhf[nb], bB + (uint32_t)(r * 128 + ((c ^ (r & 7)) << 4)));
            }
#pragma unroll
            for (int k2 = 0; k2 < 2; k2++) {
                const int kk = kp * 2 + k2;
                uint32_t ahf[4][4];
#pragma unroll
                for (int mi = 0; mi < 4; mi++) {
                    int r = wm * 64 + mi * 16 + (lane & 15);
                    int c = kk * 2 + (lane >> 4);
                    ldsm4(ahf[mi], aB + (uint32_t)(r * 128 + ((c ^ (r & 7)) << 4)));
                }
#pragma unroll
                for (int mi = 0; mi < 4; mi++)
#pragma unroll
                    for (int nb = 0; nb < 8; nb++)
                        mma16816(acc[mi][nb], ahf[mi], bhf[nb] + k2 * 2);
            }
        }
    }

    // Epilogue: direct register -> global (with optional output scale)
#pragma unroll
    for (int mi = 0; mi < 4; mi++) {
        int r0 = m0 + wm * 64 + mi * 16 + (lane >> 2);
#pragma unroll
        for (int nb = 0; nb < 8; nb++) {
            int col = n0 + wn * 64 + nb * 8 + (lane & 3) * 2;
            if (HALF_OUT) {
                __half* Ch = (__half*)Cout;
                *(__half2*)(Ch + (size_t)r0 * N + col) =
                    __floats2half2_rn(acc[mi][nb][0] * oscale, acc[mi][nb][1] * oscale);
                *(__half2*)(Ch + (size_t)(r0 + 8) * N + col) =
                    __floats2half2_rn(acc[mi][nb][2] * oscale, acc[mi][nb][3] * oscale);
            } else {
                float* Cf = (float*)Cout;
                *(float2*)(Cf + (size_t)r0 * N + col) =
                    make_float2(acc[mi][nb][0], acc[mi][nb][1]);
                *(float2*)(Cf + (size_t)(r0 + 8) * N + col) =
                    make_float2(acc[mi][nb][2], acc[mi][nb][3]);
            }
        }
    }
}

// ===========================================================================
// Register-resident flash attention (raw mma, fp16), fp16 output.
// CTA = (b,h) x 128 q-rows, 128 threads (4 warps x 32 q-rows = 2 m-blocks),
// 3-stage KV pipeline, one sync/tile, 2 CTAs/SM.
// Softmax scale pre-folded into Q (log2 units) -> exp is a bare ex2.
// Row sums via ones-MMA. Mask branch hoisted to tile level.
// ===========================================================================
#define AT_ROWB 144                   // 72 halves per row
#define OFF_Q   0
#define Q_BYTES (128*AT_ROWB)         // 18432
#define OFF_KV  Q_BYTES
#define KV_STG  (64*AT_ROWB*2)        // 18432 (K + V)
#define NKV     3
#define ATT_SMEM (OFF_KV + NKV*KV_STG) // 73728

__global__ __launch_bounds__(128, 2) void attn_reg(const __half* __restrict__ Q,
                                                   const __half* __restrict__ K,
                                                   const __half* __restrict__ V,
                                                   const int*    __restrict__ mask,
                                                   __half* __restrict__ Oh)
{
    extern __shared__ char smem_raw[];
    const uint32_t sb = smem_u32a(smem_raw);

    const int tid  = threadIdx.x;
    const int w    = tid >> 5;
    const int lane = tid & 31;
    const int b    = blockIdx.y >> 4;
    const int h    = blockIdx.y & 15;
    const int q0   = blockIdx.x * 128;

    // ---- per-thread prefetch bases (advance by 64*C_ per tile) ----
    const int pr = tid >> 3;                 // 0..15
    const int pc = tid & 7;                  // 0..7
    const __half* kg = K + ((size_t)(b * T_) + pr) * C_ + h * D_ + pc * 8;
    const __half* vg = V + ((size_t)(b * T_) + pr) * C_ + h * D_ + pc * 8;
    const uint32_t soff = (uint32_t)(pr * AT_ROWB + pc * 16);
    const uint32_t stg[NKV] = { sb + OFF_KV, sb + OFF_KV + KV_STG, sb + OFF_KV + 2 * KV_STG };

    auto prefetch = [&](const __half* kp, const __half* vp, uint32_t sbase){
#pragma unroll
        for (int i = 0; i < 4; i++) {
            CP16(sbase + soff + i * 16 * AT_ROWB,                 kp + (size_t)i * 16 * C_);
            CP16(sbase + 64 * AT_ROWB + soff + i * 16 * AT_ROWB,  vp + (size_t)i * 16 * C_);
        }
    };

    prefetch(kg, vg, stg[0]); CP_COMMIT();
    prefetch(kg + 64 * C_, vg + 64 * C_, stg[1]); CP_COMMIT();
    const __half* kgn = kg + 128 * C_;
    const __half* vgn = vg + 128 * C_;

    // ---- Q tile: 128 rows (Q already carries 0.125*log2e) ----
#pragma unroll
    for (int i = 0; i < 8; i++) {
        int cid = i * 128 + tid;             // 0..1023
        int r = cid >> 3, c = cid & 7;
        *(uint4*)(smem_raw + OFF_Q + r * AT_ROWB + c * 16) =
            *(const uint4*)(Q + (size_t)(b * T_ + q0 + r) * C_ + h * D_ + c * 8);
    }
    __syncthreads();

    uint32_t qf[2][4][4];                    // 2 m-blocks x 4 kd
#pragma unroll
    for (int m = 0; m < 2; m++)
#pragma unroll
        for (int kd = 0; kd < 4; kd++) {
            uint32_t aq = sb + OFF_Q + (w * 32 + m * 16 + (lane & 15)) * AT_ROWB
                        + (kd * 16 + (lane >> 4) * 8) * 2;
            ldsm4(qf[m][kd], aq);
        }

    float oacc[2][8][4];
#pragma unroll
    for (int m = 0; m < 2; m++)
#pragma unroll
        for (int i = 0; i < 8; i++)
#pragma unroll
            for (int j = 0; j < 4; j++) oacc[m][i][j] = 0.f;
    float lacc[2][4];                        // row sums via ones-mma
#pragma unroll
    for (int m = 0; m < 2; m++)
#pragma unroll
        for (int j = 0; j < 4; j++) lacc[m][j] = 0.f;

    const uint32_t bones[2] = { 0x3C003C00u, 0x3C003C00u };   // fp16 1.0 x4
    const int* mflag_p = g_mflag + (b * 16 + blockIdx.x) * 32;

    int s_cur = 0, s_pf = 2;
    const int NT = T_ / 64;  // 32
    for (int kt = 0; kt < NT; kt++) {
        CP_WAIT1();
        __syncthreads();                     // all warps done with prefetch-target stage
        if (kt + 2 < NT) {
            prefetch(kgn, vgn, stg[s_pf]);
            kgn += 64 * C_; vgn += 64 * C_;
        }
        CP_COMMIT();

        const uint32_t kS = stg[s_cur];
        const uint32_t vS = kS + 64 * AT_ROWB;
        const int flag = mflag_p[kt];
        s_cur = (s_cur == 2) ? 0 : s_cur + 1;
        s_pf  = (s_pf  == 2) ? 0 : s_pf  + 1;

        uint32_t pf[2][4][4];
        // ---- S = Q K^T (log2 units), exp via bare ex2, pack P fragments ----
        if (flag) {
#pragma unroll
            for (int j = 0; j < 8; j++) {
                uint32_t kb0[4], kb1[4];
                uint32_t a0 = kS + (j * 8 + (lane & 7)) * AT_ROWB + (lane >> 3) * 16;
                ldsm4(kb0, a0);
                ldsm4(kb1, a0 + 64);
#pragma unroll
                for (int m = 0; m < 2; m++) {
                    float sj[4] = {0.f, 0.f, 0.f, 0.f};
                    mma16816(sj, qf[m][0], kb0 + 0);
                    mma16816(sj, qf[m][1], kb0 + 2);
                    mma16816(sj, qf[m][2], kb1 + 0);
                    mma16816(sj, qf[m][3], kb1 + 2);
                    pf[m][j >> 1][(j & 1) * 2 + 0] = packe(ex2f(sj[0]), ex2f(sj[1]));
                    pf[m][j >> 1][(j & 1) * 2 + 1] = packe(ex2f(sj[2]), ex2f(sj[3]));
                }
            }
        } else {
#pragma unroll
            for (int j = 0; j < 8; j++) {
                uint32_t kb0[4], kb1[4];
                uint32_t a0 = kS + (j * 8 + (lane & 7)) * AT_ROWB + (lane >> 3) * 16;
                ldsm4(kb0, a0);
                ldsm4(kb1, a0 + 64);
#pragma unroll
                for (int m = 0; m < 2; m++) {
                    float sj[4] = {0.f, 0.f, 0.f, 0.f};
                    mma16816(sj, qf[m][0], kb0 + 0);
                    mma16816(sj, qf[m][1], kb0 + 2);
                    mma16816(sj, qf[m][2], kb1 + 0);
                    mma16816(sj, qf[m][3], kb1 + 2);

                    float e0 = ex2f(sj[0]);
                    float e1 = ex2f(sj[1]);
                    float e2 = ex2f(sj[2]);
                    float e3 = ex2f(sj[3]);
                    const int* mp = mask
                        + ((size_t)b * T_ + q0 + w * 32 + m * 16 + (lane >> 2)) * T_
                        + kt * 64 + j * 8 + 2 * (lane & 3);
                    int2 m0v = *(const int2*)mp;
                    int2 m1v = *(const int2*)(mp + 8 * T_);
                    if (m0v.x == 0) e0 = 0.f;
                    if (m0v.y == 0) e1 = 0.f;
                    if (m1v.x == 0) e2 = 0.f;
                    if (m1v.y == 0) e3 = 0.f;
                    pf[m][j >> 1][(j & 1) * 2 + 0] = packe(e0, e1);
                    pf[m][j >> 1][(j & 1) * 2 + 1] = packe(e2, e3);
                }
            }
        }

        // ---- O += P V ; l += P 1 ----
#pragma unroll
        for (int kk = 0; kk < 4; kk++) {
#pragma unroll
            for (int np = 0; np < 4; np++) {
                uint32_t vb[4];
                uint32_t ad = vS + (kk * 16 + ((lane >> 3) & 1) * 8 + (lane & 7)) * AT_ROWB
                            + (np * 16 + (lane >> 4) * 8) * 2;
                ldsm4t(vb, ad);
#pragma unroll
                for (int m = 0; m < 2; m++) {
                    mma16816(oacc[m][np * 2 + 0], pf[m][kk], vb + 0);
                    mma16816(oacc[m][np * 2 + 1], pf[m][kk], vb + 2);
                }
            }
#pragma unroll
            for (int m = 0; m < 2; m++)
                mma16816(lacc[m], pf[m][kk], bones);
        }
    }

    // ---- normalize and write (row sums replicated across quad lanes) ----
#pragma unroll
    for (int m = 0; m < 2; m++) {
        const float inv0 = 1.f / lacc[m][0];
        const float inv1 = 1.f / lacc[m][2];

        size_t o0 = (size_t)(b * T_ + q0 + w * 32 + m * 16 + (lane >> 2)) * C_
                  + h * D_ + 2 * (lane & 3);
        size_t o1 = o0 + 8 * C_;
#pragma unroll
        for (int nd = 0; nd < 8; nd++) {
            *(__half2*)(Oh + o0 + nd * 8) =
                __floats2half2_rn(oacc[m][nd][0] * inv0, oacc[m][nd][1] * inv0);
            *(__half2*)(Oh + o1 + nd * 8) =
                __floats2half2_rn(oacc[m][nd][2] * inv1, oacc[m][nd][3] * inv1);
        }
    }
}

// ===========================================================================
extern "C" void kernel_launch(void* const* d_in, const int* in_sizes, int n_in,
                              void* d_out, int out_size)
{
    const float* x    = (const float*)d_in[0];
    const int*   mask = (const int*)  d_in[1];
    const float* Wq   = (const float*)d_in[2];
    const float* Wk   = (const float*)d_in[3];
    const float* Wv   = (const float*)d_in[4];
    const float* Wo   = (const float*)d_in[5];
    float* out = (float*)d_out;

    __half *Qh, *Kh, *Vh, *xh, *wh, *Oh;
    cudaGetSymbolAddress((void**)&Qh, g_Qh);
    cudaGetSymbolAddress((void**)&Kh, g_Kh);
    cudaGetSymbolAddress((void**)&Vh, g_Vh);
    cudaGetSymbolAddress((void**)&xh, g_xh);
    cudaGetSymbolAddress((void**)&wh, g_wh);
    cudaGetSymbolAddress((void**)&Oh, g_Oh);

    cudaFuncSetAttribute((const void*)gemm_fp16<true>,
                         cudaFuncAttributeMaxDynamicSharedMemorySize, G_SMEM);
    cudaFuncSetAttribute((const void*)gemm_fp16<false>,
                         cudaFuncAttributeMaxDynamicSharedMemorySize, G_SMEM);
    cudaFuncSetAttribute(attn_reg, cudaFuncAttributeMaxDynamicSharedMemorySize, ATT_SMEM);

    convert_all<<<(XN_ + 4 * WN_) / 1024, 256>>>(x, Wq, Wk, Wv, Wo, xh, wh);
    mask_flags<<<B_ * 16 * 32, 256>>>(mask);

    dim3 gq(C_ / 128, M_ / 128, 3);   // fused QKV, single-pass fp16 (Q scaled)
    gemm_fp16<true><<<gq, 128, G_SMEM>>>(xh, wh, Qh, Kh, Vh, M_, C_, C_);

    dim3 ga(T_ / 128, B_ * H_);       // (16, 64)
    attn_reg<<<ga, 128, ATT_SMEM>>>(Qh, Kh, Vh, mask, Oh);

    dim3 go(C_ / 128, M_ / 128, 1);   // out-proj, single-pass fp16
    gemm_fp16<false><<<go, 128, G_SMEM>>>(Oh, wh + 3 * (size_t)WN_,
                                          out, out, out, M_, C_, C_);
}

// round 12
// speedup vs baseline: 11.2350x; 1.0402x over previous
#include <cuda_runtime.h>
#include <cuda_fp16.h>
#include <cstdint>
#include <math.h>

// Problem constants
#define B_  4
#define T_  2048
#define C_  1024
#define H_  16
#define D_  64
#define M_  (B_*T_)   // 8192

// Scratch (allocation-free rule: __device__ globals)
__device__ __half g_Qh[M_ * C_];
__device__ __half g_Kh[M_ * C_];
__device__ __half g_Vh[M_ * C_];
__device__ __half g_xh[M_ * C_];
__device__ __half g_wh[4 * C_ * C_];
__device__ __half g_Oh[M_ * C_];
__device__ int    g_mflag[B_ * 16 * 32];

// ---------------------------------------------------------------------------
// Common PTX helpers
// ---------------------------------------------------------------------------
__device__ __forceinline__ uint32_t smem_u32a(const void* p){
    uint32_t a;
    asm("{ .reg .u64 t; cvta.to.shared.u64 t, %1; cvt.u32.u64 %0, t; }" : "=r"(a) : "l"(p));
    return a;
}
__device__ __forceinline__ void mma16816(float* d, const uint32_t* a, const uint32_t* b){
    asm volatile("mma.sync.aligned.m16n8k16.row.col.f32.f16.f16.f32 "
        "{%0,%1,%2,%3}, {%4,%5,%6,%7}, {%8,%9}, {%0,%1,%2,%3};"
        : "+f"(d[0]), "+f"(d[1]), "+f"(d[2]), "+f"(d[3])
        : "r"(a[0]), "r"(a[1]), "r"(a[2]), "r"(a[3]), "r"(b[0]), "r"(b[1]));
}
__device__ __forceinline__ void ldsm4(uint32_t* r, uint32_t addr){
    asm volatile("ldmatrix.sync.aligned.m8n8.x4.shared.b16 {%0,%1,%2,%3}, [%4];"
        : "=r"(r[0]), "=r"(r[1]), "=r"(r[2]), "=r"(r[3]) : "r"(addr));
}
__device__ __forceinline__ void ldsm4t(uint32_t* r, uint32_t addr){
    asm volatile("ldmatrix.sync.aligned.m8n8.x4.trans.shared.b16 {%0,%1,%2,%3}, [%4];"
        : "=r"(r[0]), "=r"(r[1]), "=r"(r[2]), "=r"(r[3]) : "r"(addr));
}
__device__ __forceinline__ uint32_t packe(float a, float b){
    __half2 h = __floats2half2_rn(a, b);
    return *(uint32_t*)&h;
}
__device__ __forceinline__ float ex2f(float x){
    float y;
    asm("ex2.approx.f32 %0, %1;" : "=f"(y) : "f"(x));
    return y;
}
#define CP16(dst, src) asm volatile("cp.async.cg.shared.global [%0], [%1], 16;" :: "r"(dst), "l"(src))
#define CP_COMMIT()    asm volatile("cp.async.commit_group;")
#define CP_WAIT1()     asm volatile("cp.async.wait_group 1;")

// ---------------------------------------------------------------------------
// Merged fp32 -> fp16 convert: x (8M elems) then 4 weights (1M each)
// ---------------------------------------------------------------------------
#define XN_  (M_*C_)        // 8388608
#define WN_  (C_*C_)        // 1048576
__global__ __launch_bounds__(256) void convert_all(const float* __restrict__ x,
                                                   const float* __restrict__ w0,
                                                   const float* __restrict__ w1,
                                                   const float* __restrict__ w2,
                                                   const float* __restrict__ w3,
                                                   __half* __restrict__ xh,
                                                   __half* __restrict__ wh)
{
    long i = ((long)blockIdx.x * 256 + threadIdx.x) * 4;
    const float* src;
    __half* dst;
    if (i < XN_) { src = x + i; dst = xh + i; }
    else {
        long j = i - XN_;
        int z = (int)(j >> 20);
        const float* w = z == 0 ? w0 : (z == 1 ? w1 : (z == 2 ? w2 : w3));
        src = w + (j & (WN_ - 1));
        dst = wh + j;
    }
    float4 v = *(const float4*)src;
    ((__half2*)dst)[0] = __floats2half2_rn(v.x, v.y);
    ((__half2*)dst)[1] = __floats2half2_rn(v.z, v.w);
}

// ---------------------------------------------------------------------------
// Mask pre-scan: flag[b][qb][kb] = 1 iff mask[b, qb*128:+128, kb*64:+64] all != 0
// ---------------------------------------------------------------------------
__global__ __launch_bounds__(256) void mask_flags(const int* __restrict__ mask)
{
    __shared__ int s_zero;
    const int t = threadIdx.x;
    if (t == 0) s_zero = 0;
    __syncthreads();
    const int fid = blockIdx.x;
    const int b  = fid >> 9;
    const int qb = (fid >> 5) & 15;
    const int kb = fid & 31;
    const int* base = mask + ((size_t)b * T_ + qb * 128) * T_ + kb * 64;
    const int r = t >> 1, hh = t & 1;
    const int4* p = (const int4*)(base + (size_t)r * T_ + hh * 32);
    bool ok = true;
#pragma unroll
    for (int i = 0; i < 8; i++) {
        int4 v = p[i];
        ok = ok && (v.x != 0) && (v.y != 0) && (v.z != 0) && (v.w != 0);
    }
    if (!ok) s_zero = 1;
    __syncthreads();
    if (t == 0) g_mflag[fid] = s_zero ? 0 : 1;
}

// ===========================================================================
// GEMM: C[m,n] = sum_k A[m,k]*W[n,k], single-pass fp16 mma.
// CTA 128x128, BK=64, 3-stage cp.async (96KB -> 2 CTAs/SM), 128 threads,
// 4 warps with 64x64 tiles. blockIdx.z selects weight slice + output.
// HALF_OUT path applies a per-slice output scale (softmax scale folded into Q).
// ===========================================================================
#define TILE16 16384                  // 128 rows x 128 bytes (64 fp16 cols)
#define NSTG   3
#define STAGE_B (2*TILE16)            // A | B
#define G_SMEM (NSTG*STAGE_B)         // 98304

#define QSCALE 0.18033688011f         // 0.125 * log2(e)

template<bool HALF_OUT>
__global__ __launch_bounds__(128, 2) void gemm_fp16(
    const __half* __restrict__ Ag,
    const __half* __restrict__ Bg,
    void* __restrict__ C0, void* __restrict__ C1, void* __restrict__ C2,
    int M, int N, int K)
{
    extern __shared__ char smem_raw[];
    const uint32_t sb = smem_u32a(smem_raw);

    const int z = blockIdx.z;
    const __half* Bz = Bg + (size_t)z * N * K;
    void* Cout = z == 0 ? C0 : (z == 1 ? C1 : C2);
    const float oscale = (HALF_OUT && z == 0) ? QSCALE : 1.0f;

    const int tid  = threadIdx.x;
    const int w    = tid >> 5;
    const int lane = tid & 31;
    const int wm   = w >> 1;          // 0..1
    const int wn   = w & 1;           // 0..1
    const int m0   = blockIdx.y * 128;
    const int n0   = blockIdx.x * 128;

    auto prefetch = [&](int t, int s){
        uint32_t st = sb + s * STAGE_B;
        int k0 = t * 64;
#pragma unroll
        for (int i = 0; i < 8; i++) {
            int id = i * 128 + tid;          // 0..1023
            int r = id >> 3, c = id & 7;
            uint32_t dsw = (uint32_t)(r * 128 + ((c ^ (r & 7)) << 4));
            CP16(st + dsw,          Ag + (size_t)(m0 + r) * K + k0 + c * 8);
            CP16(st + TILE16 + dsw, Bz + (size_t)(n0 + r) * K + k0 + c * 8);
        }
    };

    prefetch(0, 0); CP_COMMIT();
    prefetch(1, 1); CP_COMMIT();

    float acc[4][8][4];
#pragma unroll
    for (int mi = 0; mi < 4; mi++)
#pragma unroll
        for (int nb = 0; nb < 8; nb++)
#pragma unroll
            for (int j = 0; j < 4; j++) acc[mi][nb][j] = 0.f;

    const int NT = K / 64;            // 16
    for (int t = 0; t < NT; t++) {
        CP_WAIT1();
        __syncthreads();
        if (t + 2 < NT) prefetch(t + 2, (t + 2) % NSTG);
        CP_COMMIT();                  // uniform group accounting

        const uint32_t aB = sb + (t % NSTG) * STAGE_B;
        const uint32_t bB = aB + TILE16;

#pragma unroll
        for (int kp = 0; kp < 2; kp++) {
            uint32_t bhf[8][4];
#pragma unroll
            for (int nb = 0; nb < 8; nb++) {
                int r = wn * 64 + nb * 8 + (lane & 7);
                int c = kp * 4 + (lane >> 3);
                ldsm4(bhf[nb], bB + (uint32_t)(r * 128 + ((c ^ (r & 7)) << 4)));
            }
#pragma unroll
            for (int k2 = 0; k2 < 2; k2++) {
                const int kk = kp * 2 + k2;
                uint32_t ahf[4][4];
#pragma unroll
                for (int mi = 0; mi < 4; mi++) {
                    int r = wm * 64 + mi * 16 + (lane & 15);
                    int c = kk * 2 + (lane >> 4);
                    ldsm4(ahf[mi], aB + (uint32_t)(r * 128 + ((c ^ (r & 7)) << 4)));
                }
#pragma unroll
                for (int mi = 0; mi < 4; mi++)
#pragma unroll
                    for (int nb = 0; nb < 8; nb++)
                        mma16816(acc[mi][nb], ahf[mi], bhf[nb] + k2 * 2);
            }
        }
    }

    // Epilogue: direct register -> global (with optional output scale)
#pragma unroll
    for (int mi = 0; mi < 4; mi++) {
        int r0 = m0 + wm * 64 + mi * 16 + (lane >> 2);
#pragma unroll
        for (int nb = 0; nb < 8; nb++) {
            int col = n0 + wn * 64 + nb * 8 + (lane & 3) * 2;
            if (HALF_OUT) {
                __half* Ch = (__half*)Cout;
                *(__half2*)(Ch + (size_t)r0 * N + col) =
                    __floats2half2_rn(acc[mi][nb][0] * oscale, acc[mi][nb][1] * oscale);
                *(__half2*)(Ch + (size_t)(r0 + 8) * N + col) =
                    __floats2half2_rn(acc[mi][nb][2] * oscale, acc[mi][nb][3] * oscale);
            } else {
                float* Cf = (float*)Cout;
                *(float2*)(Cf + (size_t)r0 * N + col) =
                    make_float2(acc[mi][nb][0], acc[mi][nb][1]);
                *(float2*)(Cf + (size_t)(r0 + 8) * N + col) =
                    make_float2(acc[mi][nb][2], acc[mi][nb][3]);
            }
        }
    }
}

// ===========================================================================
// Register-resident flash attention (raw mma, fp16), fp16 output.
// CTA = (b,h) x 128 q-rows, 128 threads (4 warps x 32 q-rows = 2 m-blocks),
// 3-stage KV pipeline, one sync/tile, 2 CTAs/SM.
// Softmax scale pre-folded into Q (log2 units) -> exp is a bare ex2.
// Row sums via ones-MMA. S and PV phases software-pipelined at kk granularity
// so exp/pack bursts interleave with independent PV mma in program order.
// ===========================================================================
#define AT_ROWB 144                   // 72 halves per row
#define OFF_Q   0
#define Q_BYTES (128*AT_ROWB)         // 18432
#define OFF_KV  Q_BYTES
#define KV_STG  (64*AT_ROWB*2)        // 18432 (K + V)
#define NKV     3
#define ATT_SMEM (OFF_KV + NKV*KV_STG) // 73728

__global__ __launch_bounds__(128, 2) void attn_reg(const __half* __restrict__ Q,
                                                   const __half* __restrict__ K,
                                                   const __half* __restrict__ V,
                                                   const int*    __restrict__ mask,
                                                   __half* __restrict__ Oh)
{
    extern __shared__ char smem_raw[];
    const uint32_t sb = smem_u32a(smem_raw);

    const int tid  = threadIdx.x;
    const int w    = tid >> 5;
    const int lane = tid & 31;
    const int b    = blockIdx.y >> 4;
    const int h    = blockIdx.y & 15;
    const int q0   = blockIdx.x * 128;

    // ---- per-thread prefetch bases (advance by 64*C_ per tile) ----
    const int pr = tid >> 3;                 // 0..15
    const int pc = tid & 7;                  // 0..7
    const __half* kg = K + ((size_t)(b * T_) + pr) * C_ + h * D_ + pc * 8;
    const __half* vg = V + ((size_t)(b * T_) + pr) * C_ + h * D_ + pc * 8;
    const uint32_t soff = (uint32_t)(pr * AT_ROWB + pc * 16);
    const uint32_t stg[NKV] = { sb + OFF_KV, sb + OFF_KV + KV_STG, sb + OFF_KV + 2 * KV_STG };

    auto prefetch = [&](const __half* kp, const __half* vp, uint32_t sbase){
#pragma unroll
        for (int i = 0; i < 4; i++) {
            CP16(sbase + soff + i * 16 * AT_ROWB,                 kp + (size_t)i * 16 * C_);
            CP16(sbase + 64 * AT_ROWB + soff + i * 16 * AT_ROWB,  vp + (size_t)i * 16 * C_);
        }
    };

    prefetch(kg, vg, stg[0]); CP_COMMIT();
    prefetch(kg + 64 * C_, vg + 64 * C_, stg[1]); CP_COMMIT();
    const __half* kgn = kg + 128 * C_;
    const __half* vgn = vg + 128 * C_;

    // ---- Q tile: 128 rows (Q already carries 0.125*log2e) ----
#pragma unroll
    for (int i = 0; i < 8; i++) {
        int cid = i * 128 + tid;             // 0..1023
        int r = cid >> 3, c = cid & 7;
        *(uint4*)(smem_raw + OFF_Q + r * AT_ROWB + c * 16) =
            *(const uint4*)(Q + (size_t)(b * T_ + q0 + r) * C_ + h * D_ + c * 8);
    }
    __syncthreads();

    uint32_t qf[2][4][4];                    // 2 m-blocks x 4 kd
#pragma unroll
    for (int m = 0; m < 2; m++)
#pragma unroll
        for (int kd = 0; kd < 4; kd++) {
            uint32_t aq = sb + OFF_Q + (w * 32 + m * 16 + (lane & 15)) * AT_ROWB
                        + (kd * 16 + (lane >> 4) * 8) * 2;
            ldsm4(qf[m][kd], aq);
        }

    float oacc[2][8][4];
#pragma unroll
    for (int m = 0; m < 2; m++)
#pragma unroll
        for (int i = 0; i < 8; i++)
#pragma unroll
            for (int j = 0; j < 4; j++) oacc[m][i][j] = 0.f;
    float lacc[2][4];                        // row sums via ones-mma
#pragma unroll
    for (int m = 0; m < 2; m++)
#pragma unroll
        for (int j = 0; j < 4; j++) lacc[m][j] = 0.f;

    const uint32_t bones[2] = { 0x3C003C00u, 0x3C003C00u };   // fp16 1.0 x4
    const int* mflag_p = g_mflag + (b * 16 + blockIdx.x) * 32;

    int s_cur = 0, s_pf = 2;
    const int NT = T_ / 64;  // 32
    for (int kt = 0; kt < NT; kt++) {
        CP_WAIT1();
        __syncthreads();                     // all warps done with prefetch-target stage
        if (kt + 2 < NT) {
            prefetch(kgn, vgn, stg[s_pf]);
            kgn += 64 * C_; vgn += 64 * C_;
        }
        CP_COMMIT();

        const uint32_t kS = stg[s_cur];
        const uint32_t vS = kS + 64 * AT_ROWB;
        const int flag = mflag_p[kt];
        s_cur = (s_cur == 2) ? 0 : s_cur + 1;
        s_pf  = (s_pf  == 2) ? 0 : s_pf  + 1;

        uint32_t pf[2][4][4];

        // S-phase for one j-column (8 keys): S = Q K^T (log2 units), ex2, pack.
        // `masked` is a call-site constant -> branch folds at compile time.
        auto s_phase = [&](int j, int masked){
            uint32_t kb0[4], kb1[4];
            uint32_t a0 = kS + (j * 8 + (lane & 7)) * AT_ROWB + (lane >> 3) * 16;
            ldsm4(kb0, a0);
            ldsm4(kb1, a0 + 64);
#pragma unroll
            for (int m = 0; m < 2; m++) {
                float sj[4] = {0.f, 0.f, 0.f, 0.f};
                mma16816(sj, qf[m][0], kb0 + 0);
                mma16816(sj, qf[m][1], kb0 + 2);
                mma16816(sj, qf[m][2], kb1 + 0);
                mma16816(sj, qf[m][3], kb1 + 2);

                float e0 = ex2f(sj[0]);
                float e1 = ex2f(sj[1]);
                float e2 = ex2f(sj[2]);
                float e3 = ex2f(sj[3]);
                if (masked) {
                    const int* mp = mask
                        + ((size_t)b * T_ + q0 + w * 32 + m * 16 + (lane >> 2)) * T_
                        + kt * 64 + j * 8 + 2 * (lane & 3);
                    int2 m0v = *(const int2*)mp;
                    int2 m1v = *(const int2*)(mp + 8 * T_);
                    if (m0v.x == 0) e0 = 0.f;
                    if (m0v.y == 0) e1 = 0.f;
                    if (m1v.x == 0) e2 = 0.f;
                    if (m1v.y == 0) e3 = 0.f;
                }
                pf[m][j >> 1][(j & 1) * 2 + 0] = packe(e0, e1);
                pf[m][j >> 1][(j & 1) * 2 + 1] = packe(e2, e3);
            }
        };

        // PV-phase for one kk chunk (16 keys): O += P V ; l += P 1.
        auto pv_phase = [&](int kk){
#pragma unroll
            for (int np = 0; np < 4; np++) {
                uint32_t vb[4];
                uint32_t ad = vS + (kk * 16 + ((lane >> 3) & 1) * 8 + (lane & 7)) * AT_ROWB
                            + (np * 16 + (lane >> 4) * 8) * 2;
                ldsm4t(vb, ad);
#pragma unroll
                for (int m = 0; m < 2; m++) {
                    mma16816(oacc[m][np * 2 + 0], pf[m][kk], vb + 0);
                    mma16816(oacc[m][np * 2 + 1], pf[m][kk], vb + 2);
                }
            }
#pragma unroll
            for (int m = 0; m < 2; m++)
                mma16816(lacc[m], pf[m][kk], bones);
        };

        // Software-pipelined: produce pf[kk+1] while PV consumes pf[kk].
        if (flag) {
            s_phase(0, 0); s_phase(1, 0);
#pragma unroll
            for (int kk = 0; kk < 4; kk++) {
                if (kk < 3) { s_phase(2 * kk + 2, 0); s_phase(2 * kk + 3, 0); }
                pv_phase(kk);
            }
        } else {
            s_phase(0, 1); s_phase(1, 1);
#pragma unroll
            for (int kk = 0; kk < 4; kk++) {
                if (kk < 3) { s_phase(2 * kk + 2, 1); s_phase(2 * kk + 3, 1); }
                pv_phase(kk);
            }
        }
    }

    // ---- normalize and write (row sums replicated across quad lanes) ----
#pragma unroll
    for (int m = 0; m < 2; m++) {
        const float inv0 = 1.f / lacc[m][0];
        const float inv1 = 1.f / lacc[m][2];

        size_t o0 = (size_t)(b * T_ + q0 + w * 32 + m * 16 + (lane >> 2)) * C_
                  + h * D_ + 2 * (lane & 3);
        size_t o1 = o0 + 8 * C_;
#pragma unroll
        for (int nd = 0; nd < 8; nd++) {
            *(__half2*)(Oh + o0 + nd * 8) =
                __floats2half2_rn(oacc[m][nd][0] * inv0, oacc[m][nd][1] * inv0);
            *(__half2*)(Oh + o1 + nd * 8) =
                __floats2half2_rn(oacc[m][nd][2] * inv1, oacc[m][nd][3] * inv1);
        }
    }
}

// ===========================================================================
extern "C" void kernel_launch(void* const* d_in, const int* in_sizes, int n_in,
                              void* d_out, int out_size)
{
    const float* x    = (const float*)d_in[0];
    const int*   mask = (const int*)  d_in[1];
    const float* Wq   = (const float*)d_in[2];
    const float* Wk   = (const float*)d_in[3];
    const float* Wv   = (const float*)d_in[4];
    const float* Wo   = (const float*)d_in[5];
    float* out = (float*)d_out;

    __half *Qh, *Kh, *Vh, *xh, *wh, *Oh;
    cudaGetSymbolAddress((void**)&Qh, g_Qh);
    cudaGetSymbolAddress((void**)&Kh, g_Kh);
    cudaGetSymbolAddress((void**)&Vh, g_Vh);
    cudaGetSymbolAddress((void**)&xh, g_xh);
    cudaGetSymbolAddress((void**)&wh, g_wh);
    cudaGetSymbolAddress((void**)&Oh, g_Oh);

    cudaFuncSetAttribute((const void*)gemm_fp16<true>,
                         cudaFuncAttributeMaxDynamicSharedMemorySize, G_SMEM);
    cudaFuncSetAttribute((const void*)gemm_fp16<false>,
                         cudaFuncAttributeMaxDynamicSharedMemorySize, G_SMEM);
    cudaFuncSetAttribute(attn_reg, cudaFuncAttributeMaxDynamicSharedMemorySize, ATT_SMEM);

    convert_all<<<(XN_ + 4 * WN_) / 1024, 256>>>(x, Wq, Wk, Wv, Wo, xh, wh);
    mask_flags<<<B_ * 16 * 32, 256>>>(mask);

    dim3 gq(C_ / 128, M_ / 128, 3);   // fused QKV, single-pass fp16 (Q scaled)
    gemm_fp16<true><<<gq, 128, G_SMEM>>>(xh, wh, Qh, Kh, Vh, M_, C_, C_);

    dim3 ga(T_ / 128, B_ * H_);       // (16, 64)
    attn_reg<<<ga, 128, ATT_SMEM>>>(Qh, Kh, Vh, mask, Oh);

    dim3 go(C_ / 128, M_ / 128, 1);   // out-proj, single-pass fp16
    gemm_fp16<false><<<go, 128, G_SMEM>>>(Oh, wh + 3 * (size_t)WN_,
                                          out, out, out, M_, C_, C_);
}

// round 13
// speedup vs baseline: 11.2924x; 1.0051x over previous
#include <cuda_runtime.h>
#include <cuda_fp16.h>
#include <cstdint>
#include <math.h>

// Problem constants
#define B_  4
#define T_  2048
#define C_  1024
#define H_  16
#define D_  64
#define M_  (B_*T_)   // 8192

// Scratch (allocation-free rule: __device__ globals)
__device__ __half g_Qh[M_ * C_];
__device__ __half g_Kh[M_ * C_];
__device__ __half g_Vh[M_ * C_];
__device__ __half g_xh[M_ * C_];
__device__ __half g_wh[4 * C_ * C_];
__device__ __half g_Oh[M_ * C_];
__device__ int    g_mflag[B_ * 16 * 32];

// ---------------------------------------------------------------------------
// Common PTX helpers
// ---------------------------------------------------------------------------
__device__ __forceinline__ uint32_t smem_u32a(const void* p){
    uint32_t a;
    asm("{ .reg .u64 t; cvta.to.shared.u64 t, %1; cvt.u32.u64 %0, t; }" : "=r"(a) : "l"(p));
    return a;
}
__device__ __forceinline__ void mma16816(float* d, const uint32_t* a, const uint32_t* b){
    asm volatile("mma.sync.aligned.m16n8k16.row.col.f32.f16.f16.f32 "
        "{%0,%1,%2,%3}, {%4,%5,%6,%7}, {%8,%9}, {%0,%1,%2,%3};"
        : "+f"(d[0]), "+f"(d[1]), "+f"(d[2]), "+f"(d[3])
        : "r"(a[0]), "r"(a[1]), "r"(a[2]), "r"(a[3]), "r"(b[0]), "r"(b[1]));
}
__device__ __forceinline__ void ldsm4(uint32_t* r, uint32_t addr){
    asm volatile("ldmatrix.sync.aligned.m8n8.x4.shared.b16 {%0,%1,%2,%3}, [%4];"
        : "=r"(r[0]), "=r"(r[1]), "=r"(r[2]), "=r"(r[3]) : "r"(addr));
}
__device__ __forceinline__ void ldsm4t(uint32_t* r, uint32_t addr){
    asm volatile("ldmatrix.sync.aligned.m8n8.x4.trans.shared.b16 {%0,%1,%2,%3}, [%4];"
        : "=r"(r[0]), "=r"(r[1]), "=r"(r[2]), "=r"(r[3]) : "r"(addr));
}
__device__ __forceinline__ uint32_t packe(float a, float b){
    __half2 h = __floats2half2_rn(a, b);
    return *(uint32_t*)&h;
}
__device__ __forceinline__ float ex2f(float x){
    float y;
    asm("ex2.approx.f32 %0, %1;" : "=f"(y) : "f"(x));
    return y;
}
#define CP16(dst, src) asm volatile("cp.async.cg.shared.global [%0], [%1], 16;" :: "r"(dst), "l"(src))
#define CP_COMMIT()    asm volatile("cp.async.commit_group;")
#define CP_WAIT1()     asm volatile("cp.async.wait_group 1;")

// ---------------------------------------------------------------------------
// Merged fp32 -> fp16 convert: x (8M elems) then 4 weights (1M each)
// ---------------------------------------------------------------------------
#define XN_  (M_*C_)        // 8388608
#define WN_  (C_*C_)        // 1048576
__global__ __launch_bounds__(256) void convert_all(const float* __restrict__ x,
                                                   const float* __restrict__ w0,
                                                   const float* __restrict__ w1,
                                                   const float* __restrict__ w2,
                                                   const float* __restrict__ w3,
                                                   __half* __restrict__ xh,
                                                   __half* __restrict__ wh)
{
    long i = ((long)blockIdx.x * 256 + threadIdx.x) * 4;
    const float* src;
    __half* dst;
    if (i < XN_) { src = x + i; dst = xh + i; }
    else {
        long j = i - XN_;
        int z = (int)(j >> 20);
        const float* w = z == 0 ? w0 : (z == 1 ? w1 : (z == 2 ? w2 : w3));
        src = w + (j & (WN_ - 1));
        dst = wh + j;
    }
    float4 v = *(const float4*)src;
    ((__half2*)dst)[0] = __floats2half2_rn(v.x, v.y);
    ((__half2*)dst)[1] = __floats2half2_rn(v.z, v.w);
}

// ---------------------------------------------------------------------------
// Mask pre-scan: flag[b][qb][kb] = 1 iff mask[b, qb*128:+128, kb*64:+64] all != 0
// ---------------------------------------------------------------------------
__global__ __launch_bounds__(256) void mask_flags(const int* __restrict__ mask)
{
    __shared__ int s_zero;
    const int t = threadIdx.x;
    if (t == 0) s_zero = 0;
    __syncthreads();
    const int fid = blockIdx.x;
    const int b  = fid >> 9;
    const int qb = (fid >> 5) & 15;
    const int kb = fid & 31;
    const int* base = mask + ((size_t)b * T_ + qb * 128) * T_ + kb * 64;
    const int r = t >> 1, hh = t & 1;
    const int4* p = (const int4*)(base + (size_t)r * T_ + hh * 32);
    bool ok = true;
#pragma unroll
    for (int i = 0; i < 8; i++) {
        int4 v = p[i];
        ok = ok && (v.x != 0) && (v.y != 0) && (v.z != 0) && (v.w != 0);
    }
    if (!ok) s_zero = 1;
    __syncthreads();
    if (t == 0) g_mflag[fid] = s_zero ? 0 : 1;
}

// ===========================================================================
// GEMM: C[m,n] = sum_k A[m,k]*W[n,k], single-pass fp16 mma.
// CTA 128x128, BK=64, 3-stage cp.async (96KB -> 2 CTAs/SM), 128 threads,
// 4 warps with 64x64 tiles. Register-level fragment double-buffering:
// each kk's ldsm issues under the previous kk's 32-mma shadow.
// blockIdx.z selects weight slice + output (fused QKV).
// ===========================================================================
#define TILE16 16384                  // 128 rows x 128 bytes (64 fp16 cols)
#define NSTG   3
#define STAGE_B (2*TILE16)            // A | B
#define G_SMEM (NSTG*STAGE_B)         // 98304

#define QSCALE 0.18033688011f         // 0.125 * log2(e)

template<bool HALF_OUT>
__global__ __launch_bounds__(128, 2) void gemm_fp16(
    const __half* __restrict__ Ag,
    const __half* __restrict__ Bg,
    void* __restrict__ C0, void* __restrict__ C1, void* __restrict__ C2,
    int M, int N, int K)
{
    extern __shared__ char smem_raw[];
    const uint32_t sb = smem_u32a(smem_raw);

    const int z = blockIdx.z;
    const __half* Bz = Bg + (size_t)z * N * K;
    void* Cout = z == 0 ? C0 : (z == 1 ? C1 : C2);
    const float oscale = (HALF_OUT && z == 0) ? QSCALE : 1.0f;

    const int tid  = threadIdx.x;
    const int w    = tid >> 5;
    const int lane = tid & 31;
    const int wm   = w >> 1;          // 0..1
    const int wn   = w & 1;           // 0..1
    const int m0   = blockIdx.y * 128;
    const int n0   = blockIdx.x * 128;

    auto prefetch = [&](int t, int s){
        uint32_t st = sb + s * STAGE_B;
        int k0 = t * 64;
#pragma unroll
        for (int i = 0; i < 8; i++) {
            int id = i * 128 + tid;          // 0..1023
            int r = id >> 3, c = id & 7;
            uint32_t dsw = (uint32_t)(r * 128 + ((c ^ (r & 7)) << 4));
            CP16(st + dsw,          Ag + (size_t)(m0 + r) * K + k0 + c * 8);
            CP16(st + TILE16 + dsw, Bz + (size_t)(n0 + r) * K + k0 + c * 8);
        }
    };

    prefetch(0, 0); CP_COMMIT();
    prefetch(1, 1); CP_COMMIT();

    float acc[4][8][4];
#pragma unroll
    for (int mi = 0; mi < 4; mi++)
#pragma unroll
        for (int nb = 0; nb < 8; nb++)
#pragma unroll
            for (int j = 0; j < 4; j++) acc[mi][nb][j] = 0.f;

    uint32_t bhf[2][8][4];            // per kp (2 kk each)
    uint32_t ahf[2][4][4];            // double-buffered per kk

    const int NT = K / 64;            // 16
    for (int t = 0; t < NT; t++) {
        CP_WAIT1();
        __syncthreads();
        if (t + 2 < NT) prefetch(t + 2, (t + 2) % NSTG);
        CP_COMMIT();                  // uniform group accounting

        const uint32_t aB = sb + (t % NSTG) * STAGE_B;
        const uint32_t bB = aB + TILE16;

        auto ldsmB = [&](int kp, uint32_t (*dst)[4]){
#pragma unroll
            for (int nb = 0; nb < 8; nb++) {
                int r = wn * 64 + nb * 8 + (lane & 7);
                int c = kp * 4 + (lane >> 3);
                ldsm4(dst[nb], bB + (uint32_t)(r * 128 + ((c ^ (r & 7)) << 4)));
            }
        };
        auto ldsmA = [&](int kk, uint32_t (*dst)[4]){
#pragma unroll
            for (int mi = 0; mi < 4; mi++) {
                int r = wm * 64 + mi * 16 + (lane & 15);
                int c = kk * 2 + (lane >> 4);
                ldsm4(dst[mi], aB + (uint32_t)(r * 128 + ((c ^ (r & 7)) << 4)));
            }
        };
        auto mma_kk = [&](uint32_t (*af)[4], uint32_t (*bf)[4], int k2){
#pragma unroll
            for (int mi = 0; mi < 4; mi++)
#pragma unroll
                for (int nb = 0; nb < 8; nb++)
                    mma16816(acc[mi][nb], af[mi], bf[nb] + k2 * 2);
        };

        // Pipelined: ldsm for kk+1 issues before the mma burst for kk.
        ldsmB(0, bhf[0]);
        ldsmA(0, ahf[0]);

        ldsmA(1, ahf[1]); ldsmB(1, bhf[1]);
        mma_kk(ahf[0], bhf[0], 0);            // kk0

        ldsmA(2, ahf[0]);
        mma_kk(ahf[1], bhf[0], 1);            // kk1

        ldsmA(3, ahf[1]);
        mma_kk(ahf[0], bhf[1], 0);            // kk2

        mma_kk(ahf[1], bhf[1], 1);            // kk3
    }

    // Epilogue: direct register -> global (with optional output scale)
#pragma unroll
    for (int mi = 0; mi < 4; mi++) {
        int r0 = m0 + wm * 64 + mi * 16 + (lane >> 2);
#pragma unroll
        for (int nb = 0; nb < 8; nb++) {
            int col = n0 + wn * 64 + nb * 8 + (lane & 3) * 2;
            if (HALF_OUT) {
                __half* Ch = (__half*)Cout;
                *(__half2*)(Ch + (size_t)r0 * N + col) =
                    __floats2half2_rn(acc[mi][nb][0] * oscale, acc[mi][nb][1] * oscale);
                *(__half2*)(Ch + (size_t)(r0 + 8) * N + col) =
                    __floats2half2_rn(acc[mi][nb][2] * oscale, acc[mi][nb][3] * oscale);
            } else {
                float* Cf = (float*)Cout;
                *(float2*)(Cf + (size_t)r0 * N + col) =
                    make_float2(acc[mi][nb][0], acc[mi][nb][1]);
                *(float2*)(Cf + (size_t)(r0 + 8) * N + col) =
                    make_float2(acc[mi][nb][2], acc[mi][nb][3]);
            }
        }
    }
}

// ===========================================================================
// Register-resident flash attention (raw mma, fp16), fp16 output.
// CTA = (b,h) x 128 q-rows, 128 threads (4 warps x 32 q-rows = 2 m-blocks),
// 3-stage KV pipeline, one sync/tile, 2 CTAs/SM.
// Softmax scale pre-folded into Q (log2 units) -> exp is a bare ex2.
// Row sums via ones-MMA. S and PV phases software-pipelined at kk granularity.
// ===========================================================================
#define AT_ROWB 144                   // 72 halves per row
#define OFF_Q   0
#define Q_BYTES (128*AT_ROWB)         // 18432
#define OFF_KV  Q_BYTES
#define KV_STG  (64*AT_ROWB*2)        // 18432 (K + V)
#define NKV     3
#define ATT_SMEM (OFF_KV + NKV*KV_STG) // 73728

__global__ __launch_bounds__(128, 2) void attn_reg(const __half* __restrict__ Q,
                                                   const __half* __restrict__ K,
                                                   const __half* __restrict__ V,
                                                   const int*    __restrict__ mask,
                                                   __half* __restrict__ Oh)
{
    extern __shared__ char smem_raw[];
    const uint32_t sb = smem_u32a(smem_raw);

    const int tid  = threadIdx.x;
    const int w    = tid >> 5;
    const int lane = tid & 31;
    const int b    = blockIdx.y >> 4;
    const int h    = blockIdx.y & 15;
    const int q0   = blockIdx.x * 128;

    // ---- per-thread prefetch bases (advance by 64*C_ per tile) ----
    const int pr = tid >> 3;                 // 0..15
    const int pc = tid & 7;                  // 0..7
    const __half* kg = K + ((size_t)(b * T_) + pr) * C_ + h * D_ + pc * 8;
    const __half* vg = V + ((size_t)(b * T_) + pr) * C_ + h * D_ + pc * 8;
    const uint32_t soff = (uint32_t)(pr * AT_ROWB + pc * 16);
    const uint32_t stg[NKV] = { sb + OFF_KV, sb + OFF_KV + KV_STG, sb + OFF_KV + 2 * KV_STG };

    auto prefetch = [&](const __half* kp, const __half* vp, uint32_t sbase){
#pragma unroll
        for (int i = 0; i < 4; i++) {
            CP16(sbase + soff + i * 16 * AT_ROWB,                 kp + (size_t)i * 16 * C_);
            CP16(sbase + 64 * AT_ROWB + soff + i * 16 * AT_ROWB,  vp + (size_t)i * 16 * C_);
        }
    };

    prefetch(kg, vg, stg[0]); CP_COMMIT();
    prefetch(kg + 64 * C_, vg + 64 * C_, stg[1]); CP_COMMIT();
    const __half* kgn = kg + 128 * C_;
    const __half* vgn = vg + 128 * C_;

    // ---- Q tile: 128 rows (Q already carries 0.125*log2e) ----
#pragma unroll
    for (int i = 0; i < 8; i++) {
        int cid = i * 128 + tid;             // 0..1023
        int r = cid >> 3, c = cid & 7;
        *(uint4*)(smem_raw + OFF_Q + r * AT_ROWB + c * 16) =
            *(const uint4*)(Q + (size_t)(b * T_ + q0 + r) * C_ + h * D_ + c * 8);
    }
    __syncthreads();

    uint32_t qf[2][4][4];                    // 2 m-blocks x 4 kd
#pragma unroll
    for (int m = 0; m < 2; m++)
#pragma unroll
        for (int kd = 0; kd < 4; kd++) {
            uint32_t aq = sb + OFF_Q + (w * 32 + m * 16 + (lane & 15)) * AT_ROWB
                        + (kd * 16 + (lane >> 4) * 8) * 2;
            ldsm4(qf[m][kd], aq);
        }

    float oacc[2][8][4];
#pragma unroll
    for (int m = 0; m < 2; m++)
#pragma unroll
        for (int i = 0; i < 8; i++)
#pragma unroll
            for (int j = 0; j < 4; j++) oacc[m][i][j] = 0.f;
    float lacc[2][4];                        // row sums via ones-mma
#pragma unroll
    for (int m = 0; m < 2; m++)
#pragma unroll
        for (int j = 0; j < 4; j++) lacc[m][j] = 0.f;

    const uint32_t bones[2] = { 0x3C003C00u, 0x3C003C00u };   // fp16 1.0 x4
    const int* mflag_p = g_mflag + (b * 16 + blockIdx.x) * 32;

    int s_cur = 0, s_pf = 2;
    const int NT = T_ / 64;  // 32
    for (int kt = 0; kt < NT; kt++) {
        CP_WAIT1();
        __syncthreads();                     // all warps done with prefetch-target stage
        if (kt + 2 < NT) {
            prefetch(kgn, vgn, stg[s_pf]);
            kgn += 64 * C_; vgn += 64 * C_;
        }
        CP_COMMIT();

        const uint32_t kS = stg[s_cur];
        const uint32_t vS = kS + 64 * AT_ROWB;
        const int flag = mflag_p[kt];
        s_cur = (s_cur == 2) ? 0 : s_cur + 1;
        s_pf  = (s_pf  == 2) ? 0 : s_pf  + 1;

        uint32_t pf[2][4][4];

        // S-phase for one j-column (8 keys): S = Q K^T (log2 units), ex2, pack.
        auto s_phase = [&](int j, int masked){
            uint32_t kb0[4], kb1[4];
            uint32_t a0 = kS + (j * 8 + (lane & 7)) * AT_ROWB + (lane >> 3) * 16;
            ldsm4(kb0, a0);
            ldsm4(kb1, a0 + 64);
#pragma unroll
            for (int m = 0; m < 2; m++) {
                float sj[4] = {0.f, 0.f, 0.f, 0.f};
                mma16816(sj, qf[m][0], kb0 + 0);
                mma16816(sj, qf[m][1], kb0 + 2);
                mma16816(sj, qf[m][2], kb1 + 0);
                mma16816(sj, qf[m][3], kb1 + 2);

                float e0 = ex2f(sj[0]);
                float e1 = ex2f(sj[1]);
                float e2 = ex2f(sj[2]);
                float e3 = ex2f(sj[3]);
                if (masked) {
                    const int* mp = mask
                        + ((size_t)b * T_ + q0 + w * 32 + m * 16 + (lane >> 2)) * T_
                        + kt * 64 + j * 8 + 2 * (lane & 3);
                    int2 m0v = *(const int2*)mp;
                    int2 m1v = *(const int2*)(mp + 8 * T_);
                    if (m0v.x == 0) e0 = 0.f;
                    if (m0v.y == 0) e1 = 0.f;
                    if (m1v.x == 0) e2 = 0.f;
                    if (m1v.y == 0) e3 = 0.f;
                }
                pf[m][j >> 1][(j & 1) * 2 + 0] = packe(e0, e1);
                pf[m][j >> 1][(j & 1) * 2 + 1] = packe(e2, e3);
            }
        };

        // PV-phase for one kk chunk (16 keys): O += P V ; l += P 1.
        auto pv_phase = [&](int kk){
#pragma unroll
            for (int np = 0; np < 4; np++) {
                uint32_t vb[4];
                uint32_t ad = vS + (kk * 16 + ((lane >> 3) & 1) * 8 + (lane & 7)) * AT_ROWB
                            + (np * 16 + (lane >> 4) * 8) * 2;
                ldsm4t(vb, ad);
#pragma unroll
                for (int m = 0; m < 2; m++) {
                    mma16816(oacc[m][np * 2 + 0], pf[m][kk], vb + 0);
                    mma16816(oacc[m][np * 2 + 1], pf[m][kk], vb + 2);
                }
            }
#pragma unroll
            for (int m = 0; m < 2; m++)
                mma16816(lacc[m], pf[m][kk], bones);
        };

        // Software-pipelined: produce pf[kk+1] while PV consumes pf[kk].
        if (flag) {
            s_phase(0, 0); s_phase(1, 0);
#pragma unroll
            for (int kk = 0; kk < 4; kk++) {
                if (kk < 3) { s_phase(2 * kk + 2, 0); s_phase(2 * kk + 3, 0); }
                pv_phase(kk);
            }
        } else {
            s_phase(0, 1); s_phase(1, 1);
#pragma unroll
            for (int kk = 0; kk < 4; kk++) {
                if (kk < 3) { s_phase(2 * kk + 2, 1); s_phase(2 * kk + 3, 1); }
                pv_phase(kk);
            }
        }
    }

    // ---- normalize and write (row sums replicated across quad lanes) ----
#pragma unroll
    for (int m = 0; m < 2; m++) {
        const float inv0 = 1.f / lacc[m][0];
        const float inv1 = 1.f / lacc[m][2];

        size_t o0 = (size_t)(b * T_ + q0 + w * 32 + m * 16 + (lane >> 2)) * C_
                  + h * D_ + 2 * (lane & 3);
        size_t o1 = o0 + 8 * C_;
#pragma unroll
        for (int nd = 0; nd < 8; nd++) {
            *(__half2*)(Oh + o0 + nd * 8) =
                __floats2half2_rn(oacc[m][nd][0] * inv0, oacc[m][nd][1] * inv0);
            *(__half2*)(Oh + o1 + nd * 8) =
                __floats2half2_rn(oacc[m][nd][2] * inv1, oacc[m][nd][3] * inv1);
        }
    }
}

// ===========================================================================
extern "C" void kernel_launch(void* const* d_in, const int* in_sizes, int n_in,
                              void* d_out, int out_size)
{
    const float* x    = (const float*)d_in[0];
    const int*   mask = (const int*)  d_in[1];
    const float* Wq   = (const float*)d_in[2];
    const float* Wk   = (const float*)d_in[3];
    const float* Wv   = (const float*)d_in[4];
    const float* Wo   = (const float*)d_in[5];
    float* out = (float*)d_out;

    __half *Qh, *Kh, *Vh, *xh, *wh, *Oh;
    cudaGetSymbolAddress((void**)&Qh, g_Qh);
    cudaGetSymbolAddress((void**)&Kh, g_Kh);
    cudaGetSymbolAddress((void**)&Vh, g_Vh);
    cudaGetSymbolAddress((void**)&xh, g_xh);
    cudaGetSymbolAddress((void**)&wh, g_wh);
    cudaGetSymbolAddress((void**)&Oh, g_Oh);

    cudaFuncSetAttribute((const void*)gemm_fp16<true>,
                         cudaFuncAttributeMaxDynamicSharedMemorySize, G_SMEM);
    cudaFuncSetAttribute((const void*)gemm_fp16<false>,
                         cudaFuncAttributeMaxDynamicSharedMemorySize, G_SMEM);
    cudaFuncSetAttribute(attn_reg, cudaFuncAttributeMaxDynamicSharedMemorySize, ATT_SMEM);

    convert_all<<<(XN_ + 4 * WN_) / 1024, 256>>>(x, Wq, Wk, Wv, Wo, xh, wh);
    mask_flags<<<B_ * 16 * 32, 256>>>(mask);

    dim3 gq(C_ / 128, M_ / 128, 3);   // fused QKV, single-pass fp16 (Q scaled)
    gemm_fp16<true><<<gq, 128, G_SMEM>>>(xh, wh, Qh, Kh, Vh, M_, C_, C_);

    dim3 ga(T_ / 128, B_ * H_);       // (16, 64)
    attn_reg<<<ga, 128, ATT_SMEM>>>(Qh, Kh, Vh, mask, Oh);

    dim3 go(C_ / 128, M_ / 128, 1);   // out-proj, single-pass fp16
    gemm_fp16<false><<<go, 128, G_SMEM>>>(Oh, wh + 3 * (size_t)WN_,
                                          out, out, out, M_, C_, C_);
}

// round 14
// speedup vs baseline: 11.3512x; 1.0052x over previous
#include <cuda_runtime.h>
#include <cuda_fp16.h>
#include <cstdint>
#include <math.h>

// Problem constants
#define B_  4
#define T_  2048
#define C_  1024
#define H_  16
#define D_  64
#define M_  (B_*T_)   // 8192

// Scratch (allocation-free rule: __device__ globals)
__device__ __half g_Qh[M_ * C_];
__device__ __half g_Kh[M_ * C_];
__device__ __half g_Vh[M_ * C_];
__device__ __half g_xh[M_ * C_];
__device__ __half g_wh[4 * C_ * C_];
__device__ __half g_Oh[M_ * C_];
__device__ int    g_mflag[B_ * 16 * 32];

// ---------------------------------------------------------------------------
// Common PTX helpers
// ---------------------------------------------------------------------------
__device__ __forceinline__ uint32_t smem_u32a(const void* p){
    uint32_t a;
    asm("{ .reg .u64 t; cvta.to.shared.u64 t, %1; cvt.u32.u64 %0, t; }" : "=r"(a) : "l"(p));
    return a;
}
__device__ __forceinline__ void mma16816(float* d, const uint32_t* a, const uint32_t* b){
    asm volatile("mma.sync.aligned.m16n8k16.row.col.f32.f16.f16.f32 "
        "{%0,%1,%2,%3}, {%4,%5,%6,%7}, {%8,%9}, {%0,%1,%2,%3};"
        : "+f"(d[0]), "+f"(d[1]), "+f"(d[2]), "+f"(d[3])
        : "r"(a[0]), "r"(a[1]), "r"(a[2]), "r"(a[3]), "r"(b[0]), "r"(b[1]));
}
__device__ __forceinline__ void ldsm4(uint32_t* r, uint32_t addr){
    asm volatile("ldmatrix.sync.aligned.m8n8.x4.shared.b16 {%0,%1,%2,%3}, [%4];"
        : "=r"(r[0]), "=r"(r[1]), "=r"(r[2]), "=r"(r[3]) : "r"(addr));
}
__device__ __forceinline__ void ldsm4t(uint32_t* r, uint32_t addr){
    asm volatile("ldmatrix.sync.aligned.m8n8.x4.trans.shared.b16 {%0,%1,%2,%3}, [%4];"
        : "=r"(r[0]), "=r"(r[1]), "=r"(r[2]), "=r"(r[3]) : "r"(addr));
}
__device__ __forceinline__ uint32_t packe(float a, float b){
    __half2 h = __floats2half2_rn(a, b);
    return *(uint32_t*)&h;
}
__device__ __forceinline__ float ex2f(float x){
    float y;
    asm("ex2.approx.f32 %0, %1;" : "=f"(y) : "f"(x));
    return y;
}
#define CP16(dst, src) asm volatile("cp.async.cg.shared.global [%0], [%1], 16;" :: "r"(dst), "l"(src))
#define CP_COMMIT()    asm volatile("cp.async.commit_group;")
#define CP_WAIT1()     asm volatile("cp.async.wait_group 1;")

// ---------------------------------------------------------------------------
// Merged fp32 -> fp16 convert: x (8M elems) then 4 weights (1M each)
// ---------------------------------------------------------------------------
#define XN_  (M_*C_)        // 8388608
#define WN_  (C_*C_)        // 1048576
__global__ __launch_bounds__(256) void convert_all(const float* __restrict__ x,
                                                   const float* __restrict__ w0,
                                                   const float* __restrict__ w1,
                                                   const float* __restrict__ w2,
                                                   const float* __restrict__ w3,
                                                   __half* __restrict__ xh,
                                                   __half* __restrict__ wh)
{
    long i = ((long)blockIdx.x * 256 + threadIdx.x) * 4;
    const float* src;
    __half* dst;
    if (i < XN_) { src = x + i; dst = xh + i; }
    else {
        long j = i - XN_;
        int z = (int)(j >> 20);
        const float* w = z == 0 ? w0 : (z == 1 ? w1 : (z == 2 ? w2 : w3));
        src = w + (j & (WN_ - 1));
        dst = wh + j;
    }
    float4 v = *(const float4*)src;
    ((__half2*)dst)[0] = __floats2half2_rn(v.x, v.y);
    ((__half2*)dst)[1] = __floats2half2_rn(v.z, v.w);
}

// ---------------------------------------------------------------------------
// Mask pre-scan: flag[b][qb][kb] = 1 iff mask[b, qb*128:+128, kb*64:+64] all != 0
// ---------------------------------------------------------------------------
__global__ __launch_bounds__(256) void mask_flags(const int* __restrict__ mask)
{
    __shared__ int s_zero;
    const int t = threadIdx.x;
    if (t == 0) s_zero = 0;
    __syncthreads();
    const int fid = blockIdx.x;
    const int b  = fid >> 9;
    const int qb = (fid >> 5) & 15;
    const int kb = fid & 31;
    const int* base = mask + ((size_t)b * T_ + qb * 128) * T_ + kb * 64;
    const int r = t >> 1, hh = t & 1;
    const int4* p = (const int4*)(base + (size_t)r * T_ + hh * 32);
    bool ok = true;
#pragma unroll
    for (int i = 0; i < 8; i++) {
        int4 v = p[i];
        ok = ok && (v.x != 0) && (v.y != 0) && (v.z != 0) && (v.w != 0);
    }
    if (!ok) s_zero = 1;
    __syncthreads();
    if (t == 0) g_mflag[fid] = s_zero ? 0 : 1;
}

// ===========================================================================
// GEMM: C[m,n] = sum_k A[m,k]*W[n,k], single-pass fp16 mma.
// CTA 128x128, BK=64, 3-stage cp.async (96KB -> 2 CTAs/SM), 128 threads,
// 4 warps with 64x64 tiles. A fragments double-buffered, B single-buffered
// (live regs ~215 < 256 cap -> no accumulator spills).
// blockIdx.z selects weight slice + output (fused QKV).
// ===========================================================================
#define TILE16 16384                  // 128 rows x 128 bytes (64 fp16 cols)
#define NSTG   3
#define STAGE_B (2*TILE16)            // A | B
#define G_SMEM (NSTG*STAGE_B)         // 98304

#define QSCALE 0.18033688011f         // 0.125 * log2(e)

template<bool HALF_OUT>
__global__ __launch_bounds__(128, 2) void gemm_fp16(
    const __half* __restrict__ Ag,
    const __half* __restrict__ Bg,
    void* __restrict__ C0, void* __restrict__ C1, void* __restrict__ C2,
    int M, int N, int K)
{
    extern __shared__ char smem_raw[];
    const uint32_t sb = smem_u32a(smem_raw);

    const int z = blockIdx.z;
    const __half* Bz = Bg + (size_t)z * N * K;
    void* Cout = z == 0 ? C0 : (z == 1 ? C1 : C2);
    const float oscale = (HALF_OUT && z == 0) ? QSCALE : 1.0f;

    const int tid  = threadIdx.x;
    const int w    = tid >> 5;
    const int lane = tid & 31;
    const int wm   = w >> 1;          // 0..1
    const int wn   = w & 1;           // 0..1
    const int m0   = blockIdx.y * 128;
    const int n0   = blockIdx.x * 128;

    auto prefetch = [&](int t, int s){
        uint32_t st = sb + s * STAGE_B;
        int k0 = t * 64;
#pragma unroll
        for (int i = 0; i < 8; i++) {
            int id = i * 128 + tid;          // 0..1023
            int r = id >> 3, c = id & 7;
            uint32_t dsw = (uint32_t)(r * 128 + ((c ^ (r & 7)) << 4));
            CP16(st + dsw,          Ag + (size_t)(m0 + r) * K + k0 + c * 8);
            CP16(st + TILE16 + dsw, Bz + (size_t)(n0 + r) * K + k0 + c * 8);
        }
    };

    prefetch(0, 0); CP_COMMIT();
    prefetch(1, 1); CP_COMMIT();

    float acc[4][8][4];
#pragma unroll
    for (int mi = 0; mi < 4; mi++)
#pragma unroll
        for (int nb = 0; nb < 8; nb++)
#pragma unroll
            for (int j = 0; j < 4; j++) acc[mi][nb][j] = 0.f;

    uint32_t bhf[8][4];               // single-buffered per kp
    uint32_t ahf[2][4][4];            // double-buffered per kk

    const int NT = K / 64;            // 16
    for (int t = 0; t < NT; t++) {
        CP_WAIT1();
        __syncthreads();
        if (t + 2 < NT) prefetch(t + 2, (t + 2) % NSTG);
        CP_COMMIT();                  // uniform group accounting

        const uint32_t aB = sb + (t % NSTG) * STAGE_B;
        const uint32_t bB = aB + TILE16;

        auto ldsmB = [&](int kp){
#pragma unroll
            for (int nb = 0; nb < 8; nb++) {
                int r = wn * 64 + nb * 8 + (lane & 7);
                int c = kp * 4 + (lane >> 3);
                ldsm4(bhf[nb], bB + (uint32_t)(r * 128 + ((c ^ (r & 7)) << 4)));
            }
        };
        auto ldsmA = [&](int kk, uint32_t (*dst)[4]){
#pragma unroll
            for (int mi = 0; mi < 4; mi++) {
                int r = wm * 64 + mi * 16 + (lane & 15);
                int c = kk * 2 + (lane >> 4);
                ldsm4(dst[mi], aB + (uint32_t)(r * 128 + ((c ^ (r & 7)) << 4)));
            }
        };
        auto mma_kk = [&](uint32_t (*af)[4], int k2){
#pragma unroll
            for (int mi = 0; mi < 4; mi++)
#pragma unroll
                for (int nb = 0; nb < 8; nb++)
                    mma16816(acc[mi][nb], af[mi], bhf[nb] + k2 * 2);
        };

        // A double-buffered; B reloaded per kp (WAR handled by in-order issue).
        ldsmB(0);
        ldsmA(0, ahf[0]);
        ldsmA(1, ahf[1]);
        mma_kk(ahf[0], 0);            // kk0 (kp0)
        ldsmA(2, ahf[0]);
        mma_kk(ahf[1], 1);            // kk1 (kp0)
        ldsmB(1);
        ldsmA(3, ahf[1]);
        mma_kk(ahf[0], 0);            // kk2 (kp1)
        mma_kk(ahf[1], 1);            // kk3 (kp1)
    }

    // Epilogue: direct register -> global (with optional output scale)
#pragma unroll
    for (int mi = 0; mi < 4; mi++) {
        int r0 = m0 + wm * 64 + mi * 16 + (lane >> 2);
#pragma unroll
        for (int nb = 0; nb < 8; nb++) {
            int col = n0 + wn * 64 + nb * 8 + (lane & 3) * 2;
            if (HALF_OUT) {
                __half* Ch = (__half*)Cout;
                *(__half2*)(Ch + (size_t)r0 * N + col) =
                    __floats2half2_rn(acc[mi][nb][0] * oscale, acc[mi][nb][1] * oscale);
                *(__half2*)(Ch + (size_t)(r0 + 8) * N + col) =
                    __floats2half2_rn(acc[mi][nb][2] * oscale, acc[mi][nb][3] * oscale);
            } else {
                float* Cf = (float*)Cout;
                *(float2*)(Cf + (size_t)r0 * N + col) =
                    make_float2(acc[mi][nb][0], acc[mi][nb][1]);
                *(float2*)(Cf + (size_t)(r0 + 8) * N + col) =
                    make_float2(acc[mi][nb][2], acc[mi][nb][3]);
            }
        }
    }
}

// ===========================================================================
// Register-resident flash attention (raw mma, fp16), fp16 output.
// CTA = (b,h) x 128 q-rows, 128 threads (4 warps x 32 q-rows = 2 m-blocks),
// 3-stage KV pipeline, one sync/tile, 2 CTAs/SM.
// Softmax scale pre-folded into Q (log2 units) -> exp is a bare ex2.
// Row sums via ones-MMA. S and PV phases software-pipelined at kk granularity.
// ===========================================================================
#define AT_ROWB 144                   // 72 halves per row
#define OFF_Q   0
#define Q_BYTES (128*AT_ROWB)         // 18432
#define OFF_KV  Q_BYTES
#define KV_STG  (64*AT_ROWB*2)        // 18432 (K + V)
#define NKV     3
#define ATT_SMEM (OFF_KV + NKV*KV_STG) // 73728

__global__ __launch_bounds__(128, 2) void attn_reg(const __half* __restrict__ Q,
                                                   const __half* __restrict__ K,
                                                   const __half* __restrict__ V,
                                                   const int*    __restrict__ mask,
                                                   __half* __restrict__ Oh)
{
    extern __shared__ char smem_raw[];
    const uint32_t sb = smem_u32a(smem_raw);

    const int tid  = threadIdx.x;
    const int w    = tid >> 5;
    const int lane = tid & 31;
    const int b    = blockIdx.y >> 4;
    const int h    = blockIdx.y & 15;
    const int q0   = blockIdx.x * 128;

    // ---- per-thread prefetch bases (advance by 64*C_ per tile) ----
    const int pr = tid >> 3;                 // 0..15
    const int pc = tid & 7;                  // 0..7
    const __half* kg = K + ((size_t)(b * T_) + pr) * C_ + h * D_ + pc * 8;
    const __half* vg = V + ((size_t)(b * T_) + pr) * C_ + h * D_ + pc * 8;
    const uint32_t soff = (uint32_t)(pr * AT_ROWB + pc * 16);
    const uint32_t stg[NKV] = { sb + OFF_KV, sb + OFF_KV + KV_STG, sb + OFF_KV + 2 * KV_STG };

    auto prefetch = [&](const __half* kp, const __half* vp, uint32_t sbase){
#pragma unroll
        for (int i = 0; i < 4; i++) {
            CP16(sbase + soff + i * 16 * AT_ROWB,                 kp + (size_t)i * 16 * C_);
            CP16(sbase + 64 * AT_ROWB + soff + i * 16 * AT_ROWB,  vp + (size_t)i * 16 * C_);
        }
    };

    prefetch(kg, vg, stg[0]); CP_COMMIT();
    prefetch(kg + 64 * C_, vg + 64 * C_, stg[1]); CP_COMMIT();
    const __half* kgn = kg + 128 * C_;
    const __half* vgn = vg + 128 * C_;

    // ---- Q tile: 128 rows (Q already carries 0.125*log2e) ----
#pragma unroll
    for (int i = 0; i < 8; i++) {
        int cid = i * 128 + tid;             // 0..1023
        int r = cid >> 3, c = cid & 7;
        *(uint4*)(smem_raw + OFF_Q + r * AT_ROWB + c * 16) =
            *(const uint4*)(Q + (size_t)(b * T_ + q0 + r) * C_ + h * D_ + c * 8);
    }
    __syncthreads();

    uint32_t qf[2][4][4];                    // 2 m-blocks x 4 kd
#pragma unroll
    for (int m = 0; m < 2; m++)
#pragma unroll
        for (int kd = 0; kd < 4; kd++) {
            uint32_t aq = sb + OFF_Q + (w * 32 + m * 16 + (lane & 15)) * AT_ROWB
                        + (kd * 16 + (lane >> 4) * 8) * 2;
            ldsm4(qf[m][kd], aq);
        }

    float oacc[2][8][4];
#pragma unroll
    for (int m = 0; m < 2; m++)
#pragma unroll
        for (int i = 0; i < 8; i++)
#pragma unroll
            for (int j = 0; j < 4; j++) oacc[m][i][j] = 0.f;
    float lacc[2][4];                        // row sums via ones-mma
#pragma unroll
    for (int m = 0; m < 2; m++)
#pragma unroll
        for (int j = 0; j < 4; j++) lacc[m][j] = 0.f;

    const uint32_t bones[2] = { 0x3C003C00u, 0x3C003C00u };   // fp16 1.0 x4
    const int* mflag_p = g_mflag + (b * 16 + blockIdx.x) * 32;

    int s_cur = 0, s_pf = 2;
    const int NT = T_ / 64;  // 32
    for (int kt = 0; kt < NT; kt++) {
        CP_WAIT1();
        __syncthreads();                     // all warps done with prefetch-target stage
        if (kt + 2 < NT) {
            prefetch(kgn, vgn, stg[s_pf]);
            kgn += 64 * C_; vgn += 64 * C_;
        }
        CP_COMMIT();

        const uint32_t kS = stg[s_cur];
        const uint32_t vS = kS + 64 * AT_ROWB;
        const int flag = mflag_p[kt];
        s_cur = (s_cur == 2) ? 0 : s_cur + 1;
        s_pf  = (s_pf  == 2) ? 0 : s_pf  + 1;

        uint32_t pf[2][4][4];

        // S-phase for one j-column (8 keys): S = Q K^T (log2 units), ex2, pack.
        auto s_phase = [&](int j, int masked){
            uint32_t kb0[4], kb1[4];
            uint32_t a0 = kS + (j * 8 + (lane & 7)) * AT_ROWB + (lane >> 3) * 16;
            ldsm4(kb0, a0);
            ldsm4(kb1, a0 + 64);
#pragma unroll
            for (int m = 0; m < 2; m++) {
                float sj[4] = {0.f, 0.f, 0.f, 0.f};
                mma16816(sj, qf[m][0], kb0 + 0);
                mma16816(sj, qf[m][1], kb0 + 2);
                mma16816(sj, qf[m][2], kb1 + 0);
                mma16816(sj, qf[m][3], kb1 + 2);

                float e0 = ex2f(sj[0]);
                float e1 = ex2f(sj[1]);
                float e2 = ex2f(sj[2]);
                float e3 = ex2f(sj[3]);
                if (masked) {
                    const int* mp = mask
                        + ((size_t)b * T_ + q0 + w * 32 + m * 16 + (lane >> 2)) * T_
                        + kt * 64 + j * 8 + 2 * (lane & 3);
                    int2 m0v = *(const int2*)mp;
                    int2 m1v = *(const int2*)(mp + 8 * T_);
                    if (m0v.x == 0) e0 = 0.f;
                    if (m0v.y == 0) e1 = 0.f;
                    if (m1v.x == 0) e2 = 0.f;
                    if (m1v.y == 0) e3 = 0.f;
                }
                pf[m][j >> 1][(j & 1) * 2 + 0] = packe(e0, e1);
                pf[m][j >> 1][(j & 1) * 2 + 1] = packe(e2, e3);
            }
        };

        // PV-phase for one kk chunk (16 keys): O += P V ; l += P 1.
        auto pv_phase = [&](int kk){
#pragma unroll
            for (int np = 0; np < 4; np++) {
                uint32_t vb[4];
                uint32_t ad = vS + (kk * 16 + ((lane >> 3) & 1) * 8 + (lane & 7)) * AT_ROWB
                            + (np * 16 + (lane >> 4) * 8) * 2;
                ldsm4t(vb, ad);
#pragma unroll
                for (int m = 0; m < 2; m++) {
                    mma16816(oacc[m][np * 2 + 0], pf[m][kk], vb + 0);
                    mma16816(oacc[m][np * 2 + 1], pf[m][kk], vb + 2);
                }
            }
#pragma unroll
            for (int m = 0; m < 2; m++)
                mma16816(lacc[m], pf[m][kk], bones);
        };

        // Software-pipelined: produce pf[kk+1] while PV consumes pf[kk].
        if (flag) {
            s_phase(0, 0); s_phase(1, 0);
#pragma unroll
            for (int kk = 0; kk < 4; kk++) {
                if (kk < 3) { s_phase(2 * kk + 2, 0); s_phase(2 * kk + 3, 0); }
                pv_phase(kk);
            }
        } else {
            s_phase(0, 1); s_phase(1, 1);
#pragma unroll
            for (int kk = 0; kk < 4; kk++) {
                if (kk < 3) { s_phase(2 * kk + 2, 1); s_phase(2 * kk + 3, 1); }
                pv_phase(kk);
            }
        }
    }

    // ---- normalize and write (row sums replicated across quad lanes) ----
#pragma unroll
    for (int m = 0; m < 2; m++) {
        const float inv0 = 1.f / lacc[m][0];
        const float inv1 = 1.f / lacc[m][2];

        size_t o0 = (size_t)(b * T_ + q0 + w * 32 + m * 16 + (lane >> 2)) * C_
                  + h * D_ + 2 * (lane & 3);
        size_t o1 = o0 + 8 * C_;
#pragma unroll
        for (int nd = 0; nd < 8; nd++) {
            *(__half2*)(Oh + o0 + nd * 8) =
                __floats2half2_rn(oacc[m][nd][0] * inv0, oacc[m][nd][1] * inv0);
            *(__half2*)(Oh + o1 + nd * 8) =
                __floats2half2_rn(oacc[m][nd][2] * inv1, oacc[m][nd][3] * inv1);
        }
    }
}

// ===========================================================================
extern "C" void kernel_launch(void* const* d_in, const int* in_sizes, int n_in,
                              void* d_out, int out_size)
{
    const float* x    = (const float*)d_in[0];
    const int*   mask = (const int*)  d_in[1];
    const float* Wq   = (const float*)d_in[2];
    const float* Wk   = (const float*)d_in[3];
    const float* Wv   = (const float*)d_in[4];
    const float* Wo   = (const float*)d_in[5];
    float* out = (float*)d_out;

    __half *Qh, *Kh, *Vh, *xh, *wh, *Oh;
    cudaGetSymbolAddress((void**)&Qh, g_Qh);
    cudaGetSymbolAddress((void**)&Kh, g_Kh);
    cudaGetSymbolAddress((void**)&Vh, g_Vh);
    cudaGetSymbolAddress((void**)&xh, g_xh);
    cudaGetSymbolAddress((void**)&wh, g_wh);
    cudaGetSymbolAddress((void**)&Oh, g_Oh);

    cudaFuncSetAttribute((const void*)gemm_fp16<true>,
                         cudaFuncAttributeMaxDynamicSharedMemorySize, G_SMEM);
    cudaFuncSetAttribute((const void*)gemm_fp16<false>,
                         cudaFuncAttributeMaxDynamicSharedMemorySize, G_SMEM);
    cudaFuncSetAttribute(attn_reg, cudaFuncAttributeMaxDynamicSharedMemorySize, ATT_SMEM);

    convert_all<<<(XN_ + 4 * WN_) / 1024, 256>>>(x, Wq, Wk, Wv, Wo, xh, wh);
    mask_flags<<<B_ * 16 * 32, 256>>>(mask);

    dim3 gq(C_ / 128, M_ / 128, 3);   // fused QKV, single-pass fp16 (Q scaled)
    gemm_fp16<true><<<gq, 128, G_SMEM>>>(xh, wh, Qh, Kh, Vh, M_, C_, C_);

    dim3 ga(T_ / 128, B_ * H_);       // (16, 64)
    attn_reg<<<ga, 128, ATT_SMEM>>>(Qh, Kh, Vh, mask, Oh);

    dim3 go(C_ / 128, M_ / 128, 1);   // out-proj, single-pass fp16
    gemm_fp16<false><<<go, 128, G_SMEM>>>(Oh, wh + 3 * (size_t)WN_,
                                          out, out, out, M_, C_, C_);
}